// round 6
// baseline (speedup 1.0000x reference)
#include <cuda_runtime.h>
#include <math.h>
#include <stdint.h>

#define BATCH 65536
#define DIN   512
#define DOUT  512
#define HIDN  1024

// ---------------- scratch (static device globals; no allocation) -------------
__device__ float g_buf [(size_t)BATCH * DIN];
__device__ float g_h   [(size_t)BATCH * HIDN];
__device__ float g_slow[(size_t)BATCH * DOUT];
__device__ float g_fast[(size_t)BATCH * DOUT];
__device__ float g_gates[(size_t)BATCH * 3];
__device__ float g_hebb[DOUT * DIN];
__device__ float g_m2  [DOUT];
__device__ float g_stats[4];
__device__ float g_xr  [(size_t)BATCH * DIN];   // tf32-rounded copy of x

// tf32-rounded weight copies
__device__ float g_w1r[3 * HIDN * DIN];
__device__ float g_w2r[3 * DIN * HIDN];
__device__ float g_gwr[3 * HIDN * DIN];
__device__ float g_sfr[2 * DOUT * DIN];

__device__ __forceinline__ float sigf(float x) { return 1.0f / (1.0f + expf(-x)); }

__device__ __forceinline__ uint32_t f2tf32(float x) {
    uint32_t r;
    asm("cvt.rna.tf32.f32 %0, %1;" : "=r"(r) : "f"(x));
    return r;
}
__device__ __forceinline__ float roundtf(float x) { return __uint_as_float(f2tf32(x)); }

__device__ __forceinline__ void mma_tf32(float* c, const uint32_t* a, const uint32_t* b) {
    asm volatile(
        "mma.sync.aligned.m16n8k8.row.col.f32.tf32.tf32.f32 "
        "{%0,%1,%2,%3}, {%4,%5,%6,%7}, {%8,%9}, {%0,%1,%2,%3};\n"
        : "+f"(c[0]), "+f"(c[1]), "+f"(c[2]), "+f"(c[3])
        : "r"(a[0]), "r"(a[1]), "r"(a[2]), "r"(a[3]), "r"(b[0]), "r"(b[1]));
}

__device__ __forceinline__ void cp16(void* smem, const void* g) {
    uint32_t s = (uint32_t)__cvta_generic_to_shared(smem);
    asm volatile("cp.async.cg.shared.global [%0], [%1], 16;\n" :: "r"(s), "l"(g));
}
__device__ __forceinline__ void cp_commit() { asm volatile("cp.async.commit_group;\n"); }
template <int N>
__device__ __forceinline__ void cp_wait() { asm volatile("cp.async.wait_group %0;\n" :: "n"(N)); }

// ---------------- prepass ----------------------------------------------------
#define NW1 (3 * HIDN * DIN)
#define NW2 (3 * DIN * HIDN)
#define NGW (HIDN * DIN)
#define NSF (DOUT * DIN)
#define NX  ((size_t)BATCH * DIN)

__global__ void prep_kernel(const float* __restrict__ x,
                            const float* __restrict__ w1, const float* __restrict__ w2,
                            const float* __restrict__ gm, const float* __restrict__ gs,
                            const float* __restrict__ gg, const float* __restrict__ ws,
                            const float* __restrict__ wf)
{
    const size_t idx = blockIdx.x * blockDim.x + threadIdx.x;
    const size_t stride = (size_t)gridDim.x * blockDim.x;
    for (size_t i = idx; i < NX; i += stride) g_xr[i] = roundtf(x[i]);
    for (size_t i = idx; i < NW1; i += stride) g_w1r[i] = roundtf(w1[i]);
    for (size_t i = idx; i < NW2; i += stride) g_w2r[i] = roundtf(w2[i]);
    for (size_t i = idx; i < NGW; i += stride) {
        g_gwr[i]           = roundtf(gm[i]);
        g_gwr[i + NGW]     = roundtf(gs[i]);
        g_gwr[i + 2 * NGW] = roundtf(gg[i]);
    }
    for (size_t i = idx; i < NSF; i += stride) {
        g_sfr[i]       = roundtf(ws[i]);
        g_sfr[i + NSF] = roundtf(wf[i]);
    }
    for (size_t i = idx; i < DOUT * DIN; i += stride) g_hebb[i] = 0.0f;
    if (idx < DOUT) g_m2[idx] = 0.0f;
    if (idx < 4)    g_stats[idx] = 0.0f;
}

// ---------------- tf32 tensor-core GEMM, reg double-buffered pipeline --------
enum { EPI_RELU = 0, EPI_RESID = 1, EPI_SIGW = 2, EPI_SIGA = 3, EPI_NONE = 4 };

#define SPITCH 20
#define STAGES 4
#define GEMM_SMEM (STAGES * 2 * 128 * SPITCH * 4)   // 81920 bytes

__device__ __forceinline__ void load_frag(
    const float (*As)[128][SPITCH], const float (*Bs)[128][SPITCH],
    int st, int ks, int lane, int wm, int wn,
    uint32_t af[4][4], uint32_t bf[4][2])
{
    const int kk = ks * 8 + (lane & 3);
#pragma unroll
    for (int mt = 0; mt < 4; ++mt) {
        const int mr = wm * 64 + mt * 16 + (lane >> 2);
        af[mt][0] = __float_as_uint(As[st][mr][kk]);
        af[mt][1] = __float_as_uint(As[st][mr + 8][kk]);
        af[mt][2] = __float_as_uint(As[st][mr][kk + 4]);
        af[mt][3] = __float_as_uint(As[st][mr + 8][kk + 4]);
    }
#pragma unroll
    for (int nt = 0; nt < 4; ++nt) {
        const int nc = wn * 32 + nt * 8 + (lane >> 2);
        bf[nt][0] = __float_as_uint(Bs[st][nc][kk]);
        bf[nt][1] = __float_as_uint(Bs[st][nc][kk + 4]);
    }
}

__device__ __forceinline__ void mma_all(float acc[4][4][4],
                                        const uint32_t af[4][4],
                                        const uint32_t bf[4][2])
{
#pragma unroll
    for (int mt = 0; mt < 4; ++mt)
#pragma unroll
        for (int nt = 0; nt < 4; ++nt)
            mma_tf32(acc[mt][nt], af[mt], bf[nt]);
}

// block tile 128x128x16; 8 warps as 2(M) x 4(N); warp tile 64x32.
template <int EPI, bool ROUND_OUT>
__global__ __launch_bounds__(256)
void mma_gemm(const float* __restrict__ A, const float* __restrict__ W,
              const float* __restrict__ bias, const float* __restrict__ R,
              float* __restrict__ C, int N, int K,
              const int* __restrict__ step, int freq)
{
    if (freq > 1) { if ((step[0] % freq) != 0) return; }

    extern __shared__ float dynsmem[];
    float (*As)[128][SPITCH] = (float(*)[128][SPITCH])dynsmem;
    float (*Bs)[128][SPITCH] = (float(*)[128][SPITCH])(dynsmem + STAGES * 128 * SPITCH);

    const int tid  = threadIdx.x;
    const int lane = tid & 31;
    const int warp = tid >> 5;
    const int wm   = warp >> 2;
    const int wn   = warp & 3;
    const int m0   = blockIdx.y * 128;
    const int n0   = blockIdx.x * 128;

    float acc[4][4][4];
#pragma unroll
    for (int mt = 0; mt < 4; ++mt)
#pragma unroll
        for (int nt = 0; nt < 4; ++nt)
#pragma unroll
            for (int i = 0; i < 4; ++i) acc[mt][nt][i] = 0.0f;

    const int lr = tid >> 2;
    const int lc = tid & 3;

    const float* Ag = A + (size_t)(m0 + lr) * K + lc * 4;
    const float* Wg = W + (size_t)(n0 + lr) * K + lc * 4;

    const int KT = K >> 4;

    // prologue: stages 0..2
#pragma unroll
    for (int s = 0; s < STAGES - 1; ++s) {
        const size_t ko = (size_t)s * 16;
        cp16(&As[s][lr][lc * 4],      Ag + ko);
        cp16(&As[s][lr + 64][lc * 4], Ag + (size_t)64 * K + ko);
        cp16(&Bs[s][lr][lc * 4],      Wg + ko);
        cp16(&Bs[s][lr + 64][lc * 4], Wg + (size_t)64 * K + ko);
        cp_commit();
    }
    cp_wait<1>();          // stages 0,1 landed (this thread)
    __syncthreads();       // ... for every thread

    uint32_t afA[4][4], bfA[4][2], afB[4][4], bfB[4][2];
    load_frag(As, Bs, 0, 0, lane, wm, wn, afA, bfA);

    for (int kt = 0; kt < KT; ++kt) {
        const int st = kt & (STAGES - 1);

        __syncthreads();   // all warps done reading slot (kt-1)&3; safe to refill
        if (kt + STAGES - 1 < KT) {
            const int sn = (kt + STAGES - 1) & (STAGES - 1);
            const size_t ko = (size_t)(kt + STAGES - 1) * 16;
            cp16(&As[sn][lr][lc * 4],      Ag + ko);
            cp16(&As[sn][lr + 64][lc * 4], Ag + (size_t)64 * K + ko);
            cp16(&Bs[sn][lr][lc * 4],      Wg + ko);
            cp16(&Bs[sn][lr + 64][lc * 4], Wg + (size_t)64 * K + ko);
        }
        cp_commit();
        cp_wait<1>();      // completes group kt+2: keeps 2 stages ahead landed

        // ks=0: prefetch (st, ks1) into B while computing A
        load_frag(As, Bs, st, 1, lane, wm, wn, afB, bfB);
        mma_all(acc, afA, bfA);

        // ks=1: read-ahead (stage kt+1, ks0) into A while computing B
        if (kt + 1 < KT)
            load_frag(As, Bs, (kt + 1) & (STAGES - 1), 0, lane, wm, wn, afA, bfA);
        mma_all(acc, afB, bfB);
    }

    // epilogue
#pragma unroll
    for (int mt = 0; mt < 4; ++mt) {
#pragma unroll
        for (int nt = 0; nt < 4; ++nt) {
            const int col = n0 + wn * 32 + nt * 8 + (lane & 3) * 2;
            float bv0 = 0.f, bv1 = 0.f;
            if (EPI != EPI_NONE) { bv0 = bias[col]; bv1 = bias[col + 1]; }
#pragma unroll
            for (int h = 0; h < 2; ++h) {
                const int row = m0 + wm * 64 + mt * 16 + (lane >> 2) + h * 8;
                const size_t idx = (size_t)row * N + col;
                float v0 = acc[mt][nt][h * 2 + 0] + bv0;
                float v1 = acc[mt][nt][h * 2 + 1] + bv1;
                if (EPI == EPI_RELU) {
                    v0 = v0 > 0.f ? v0 : 0.f;
                    v1 = v1 > 0.f ? v1 : 0.f;
                } else if (EPI == EPI_RESID) {
                    v0 += R[idx]; v1 += R[idx + 1];
                } else if (EPI == EPI_SIGW) {
                    v0 = sigf(v0); v1 = sigf(v1);
                } else if (EPI == EPI_SIGA) {
                    v0 = C[idx] + sigf(v0); v1 = C[idx + 1] + sigf(v1);
                }
                if (ROUND_OUT) { v0 = roundtf(v0); v1 = roundtf(v1); }
                *(float2*)&C[idx] = make_float2(v0, v1);
            }
        }
    }
}

// ---------------- hebb: split-K tf32 GEMM, 4-stage pipeline ------------------
#define HPITCH 136
#define HEBB_SMEM (STAGES * 2 * 16 * HPITCH * 4)    // 69632 bytes

__global__ __launch_bounds__(256, 2)
void hebb_mma_kernel()
{
    extern __shared__ float dynsmem[];
    float (*Fs)[16][HPITCH] = (float(*)[16][HPITCH])dynsmem;
    float (*Xs)[16][HPITCH] = (float(*)[16][HPITCH])(dynsmem + STAGES * 16 * HPITCH);

    const int tid  = threadIdx.x;
    const int lane = tid & 31;
    const int warp = tid >> 5;
    const int wm   = warp >> 2;
    const int wn   = warp & 3;
    const int o0   = blockIdx.x * 128;
    const int d0   = blockIdx.y * 128;
    const int b0   = blockIdx.z * 2048;

    float acc[4][4][4];
#pragma unroll
    for (int mt = 0; mt < 4; ++mt)
#pragma unroll
        for (int nt = 0; nt < 4; ++nt)
#pragma unroll
            for (int i = 0; i < 4; ++i) acc[mt][nt][i] = 0.0f;

    const int r0 = tid >> 5,         c0 = tid & 31;
    const int r1 = (tid + 256) >> 5, c1 = tid & 31;

    const int KT = 2048 / 16;

#pragma unroll
    for (int s = 0; s < STAGES - 1; ++s) {
        const int bb = b0 + s * 16;
        cp16(&Fs[s][r0][c0 * 4], &g_fast[(size_t)(bb + r0) * DOUT + o0 + c0 * 4]);
        cp16(&Fs[s][r1][c1 * 4], &g_fast[(size_t)(bb + r1) * DOUT + o0 + c1 * 4]);
        cp16(&Xs[s][r0][c0 * 4], &g_buf [(size_t)(bb + r0) * DIN  + d0 + c0 * 4]);
        cp16(&Xs[s][r1][c1 * 4], &g_buf [(size_t)(bb + r1) * DIN  + d0 + c1 * 4]);
        cp_commit();
    }

    for (int kt = 0; kt < KT; ++kt) {
        cp_wait<STAGES - 2>();
        __syncthreads();

        if (kt + STAGES - 1 < KT) {
            const int st = (kt + STAGES - 1) & (STAGES - 1);
            const int bb = b0 + (kt + STAGES - 1) * 16;
            cp16(&Fs[st][r0][c0 * 4], &g_fast[(size_t)(bb + r0) * DOUT + o0 + c0 * 4]);
            cp16(&Fs[st][r1][c1 * 4], &g_fast[(size_t)(bb + r1) * DOUT + o0 + c1 * 4]);
            cp16(&Xs[st][r0][c0 * 4], &g_buf [(size_t)(bb + r0) * DIN  + d0 + c0 * 4]);
            cp16(&Xs[st][r1][c1 * 4], &g_buf [(size_t)(bb + r1) * DIN  + d0 + c1 * 4]);
        }
        cp_commit();

        const int cur = kt & (STAGES - 1);
#pragma unroll
        for (int ks = 0; ks < 2; ++ks) {
            const int kk = ks * 8 + (lane & 3);
            uint32_t af[4][4];
#pragma unroll
            for (int mt = 0; mt < 4; ++mt) {
                const int mr = wm * 64 + mt * 16 + (lane >> 2);
                af[mt][0] = f2tf32(Fs[cur][kk][mr]);
                af[mt][1] = f2tf32(Fs[cur][kk][mr + 8]);
                af[mt][2] = f2tf32(Fs[cur][kk + 4][mr]);
                af[mt][3] = f2tf32(Fs[cur][kk + 4][mr + 8]);
            }
            uint32_t bf[4][2];
#pragma unroll
            for (int nt = 0; nt < 4; ++nt) {
                const int nc = wn * 32 + nt * 8 + (lane >> 2);
                bf[nt][0] = __float_as_uint(Xs[cur][kk][nc]);
                bf[nt][1] = __float_as_uint(Xs[cur][kk + 4][nc]);
            }
#pragma unroll
            for (int mt = 0; mt < 4; ++mt)
#pragma unroll
                for (int nt = 0; nt < 4; ++nt)
                    mma_tf32(acc[mt][nt], af[mt], bf[nt]);
        }
    }

#pragma unroll
    for (int mt = 0; mt < 4; ++mt)
#pragma unroll
        for (int nt = 0; nt < 4; ++nt) {
            const int col = d0 + wn * 32 + nt * 8 + (lane & 3) * 2;
#pragma unroll
            for (int h = 0; h < 2; ++h) {
                const int row = o0 + wm * 64 + mt * 16 + (lane >> 2) + h * 8;
                atomicAdd(&g_hebb[row * DIN + col],     acc[mt][nt][h * 2 + 0]);
                atomicAdd(&g_hebb[row * DIN + col + 1], acc[mt][nt][h * 2 + 1]);
            }
        }
}

// ---------------- gates head --------------------------------------------------
__global__ __launch_bounds__(256)
void gateout_kernel(const float* __restrict__ gsum,
                    const float* __restrict__ w,
                    const float* __restrict__ b3)
{
    __shared__ float sw[3 * HIDN];
    __shared__ float sacc[3];
    const int tid = threadIdx.x;
    for (int i = tid; i < 3 * HIDN; i += 256) sw[i] = w[i];
    if (tid < 3) sacc[tid] = 0.0f;
    __syncthreads();

    const int lane = tid & 31, warp = tid >> 5;
    const int b = blockIdx.x * 8 + warp;
    const float* row = gsum + (size_t)b * HIDN;
    float a0 = 0.f, a1 = 0.f, a2 = 0.f;
    for (int h = lane; h < HIDN; h += 32) {
        float v = row[h];
        a0 = fmaf(v, sw[h],            a0);
        a1 = fmaf(v, sw[HIDN + h],     a1);
        a2 = fmaf(v, sw[2 * HIDN + h], a2);
    }
#pragma unroll
    for (int o = 16; o > 0; o >>= 1) {
        a0 += __shfl_down_sync(0xffffffffu, a0, o);
        a1 += __shfl_down_sync(0xffffffffu, a1, o);
        a2 += __shfl_down_sync(0xffffffffu, a2, o);
    }
    if (lane == 0) {
        float s0 = sigf(a0 + b3[0]);
        float s1 = sigf(a1 + b3[1]);
        float s2 = sigf(a2 + b3[2]);
        g_gates[(size_t)b * 3 + 0] = s0;
        g_gates[(size_t)b * 3 + 1] = s1;
        g_gates[(size_t)b * 3 + 2] = s2;
        atomicAdd(&sacc[0], s0);
        atomicAdd(&sacc[1], s1);
        atomicAdd(&sacc[2], s2);
    }
    __syncthreads();
    if (tid < 3) atomicAdd(&g_stats[tid], sacc[tid]);
}

// ---------------- m2 -----------------------------------------------------------
__global__ __launch_bounds__(256)
void m2_kernel()
{
    const int c = threadIdx.x;
    const int r0 = blockIdx.x * 256;
    float s0 = 0.f, s1 = 0.f;
    for (int r = r0; r < r0 + 256; ++r) {
        float f0 = g_fast[(size_t)r * DOUT + c];
        float f1 = g_fast[(size_t)r * DOUT + c + 256];
        s0 = fmaf(f0, f0, s0);
        s1 = fmaf(f1, f1, s1);
    }
    atomicAdd(&g_m2[c], s0);
    atomicAdd(&g_m2[c + 256], s1);
}

// ---------------- combine + swish-beta + layernorm ---------------------------
__global__ __launch_bounds__(128)
void finalize_kernel(const float* __restrict__ gamma,
                     const float* __restrict__ lbeta,
                     float* __restrict__ outp)
{
    const int b = blockIdx.x;
    const int tid = threadIdx.x;
    const float sens = g_gates[(size_t)b * 3 + 1];
    const float gate = g_gates[(size_t)b * 3 + 2];
    const float be = 0.5f + 2.0f * sens;

    float a[4];
    float s = 0.f, sq = 0.f;
#pragma unroll
    for (int i = 0; i < 4; ++i) {
        const int c = tid + i * 128;
        float cmb = g_slow[(size_t)b * DOUT + c] + g_fast[(size_t)b * DOUT + c] * gate;
        float act = cmb * sigf(be * cmb);
        a[i] = act;
        s += act;
        sq = fmaf(act, act, sq);
    }

    __shared__ float sh[8];
#pragma unroll
    for (int o = 16; o > 0; o >>= 1) {
        s  += __shfl_down_sync(0xffffffffu, s,  o);
        sq += __shfl_down_sync(0xffffffffu, sq, o);
    }
    const int lane = tid & 31, warp = tid >> 5;
    if (lane == 0) { sh[warp] = s; sh[4 + warp] = sq; }
    __syncthreads();
    if (tid == 0) {
        sh[0] = sh[0] + sh[1] + sh[2] + sh[3];
        sh[4] = sh[4] + sh[5] + sh[6] + sh[7];
    }
    __syncthreads();
    const float mu  = sh[0] * (1.0f / DOUT);
    const float var = sh[4] * (1.0f / DOUT) - mu * mu;
    const float inv = rsqrtf(var + 1e-5f);
#pragma unroll
    for (int i = 0; i < 4; ++i) {
        const int c = tid + i * 128;
        outp[(size_t)b * DOUT + c] = (a[i] - mu) * inv * gamma[c] + lbeta[c];
    }
}

// ---------------- W_fast update + stats output -------------------------------
__global__ void wfast_kernel(const float* __restrict__ Wf,
                             float* __restrict__ out_wf,
                             float* __restrict__ out_st)
{
    const int o = blockIdx.x;
    const float rate = g_stats[0] * (0.1f / (float)BATCH);
    const float m2 = g_m2[o] * (1.0f / (float)BATCH);
    for (int d = threadIdx.x; d < DIN; d += blockDim.x) {
        const float wf = Wf[o * DIN + d];
        const float hebb = g_hebb[o * DIN + d] * (1.0f / (float)BATCH);
        out_wf[o * DIN + d] = wf + tanhf(hebb - m2 * wf) * rate;
    }
    if (o == 0 && threadIdx.x < 3)
        out_st[threadIdx.x] = g_stats[threadIdx.x] * (1.0f / (float)BATCH);
}

// ---------------- launch -----------------------------------------------------
extern "C" void kernel_launch(void* const* d_in, const int* in_sizes, int n_in,
                              void* d_out, int out_size)
{
    (void)in_sizes; (void)n_in; (void)out_size;

    const float* x      = (const float*)d_in[0];
    const int*   step   = (const int*)  d_in[1];
    const float* cms_w1 = (const float*)d_in[2];
    const float* cms_b1 = (const float*)d_in[3];
    const float* cms_w2 = (const float*)d_in[4];
    const float* cms_b2 = (const float*)d_in[5];
    const float* gmw    = (const float*)d_in[6];
    const float* gmb    = (const float*)d_in[7];
    const float* gsw    = (const float*)d_in[8];
    const float* gsb    = (const float*)d_in[9];
    const float* ggw    = (const float*)d_in[10];
    const float* ggb    = (const float*)d_in[11];
    const float* gow    = (const float*)d_in[12];
    const float* gob    = (const float*)d_in[13];
    const float* Wslow  = (const float*)d_in[14];
    const float* Wfast  = (const float*)d_in[15];
    const float* gamma  = (const float*)d_in[16];
    const float* lbeta  = (const float*)d_in[17];

    float* out    = (float*)d_out;
    float* out_ln = out;
    float* out_wf = out + (size_t)BATCH * DOUT;
    float* out_st = out_wf + DOUT * DIN;

    void* p;
    cudaGetSymbolAddress(&p, g_buf);  float* buf   = (float*)p;
    cudaGetSymbolAddress(&p, g_h);    float* hbuf  = (float*)p;
    cudaGetSymbolAddress(&p, g_slow); float* slow  = (float*)p;
    cudaGetSymbolAddress(&p, g_fast); float* fastb = (float*)p;
    cudaGetSymbolAddress(&p, g_xr);   float* xr    = (float*)p;
    cudaGetSymbolAddress(&p, g_w1r);  float* w1r   = (float*)p;
    cudaGetSymbolAddress(&p, g_w2r);  float* w2r   = (float*)p;
    cudaGetSymbolAddress(&p, g_gwr);  float* gwr   = (float*)p;
    cudaGetSymbolAddress(&p, g_sfr);  float* sfr   = (float*)p;

    static bool attr_done = false;
    if (!attr_done) {
        cudaFuncSetAttribute(mma_gemm<EPI_RELU , true >, cudaFuncAttributeMaxDynamicSharedMemorySize, GEMM_SMEM);
        cudaFuncSetAttribute(mma_gemm<EPI_RESID, true >, cudaFuncAttributeMaxDynamicSharedMemorySize, GEMM_SMEM);
        cudaFuncSetAttribute(mma_gemm<EPI_SIGW , false>, cudaFuncAttributeMaxDynamicSharedMemorySize, GEMM_SMEM);
        cudaFuncSetAttribute(mma_gemm<EPI_SIGA , false>, cudaFuncAttributeMaxDynamicSharedMemorySize, GEMM_SMEM);
        cudaFuncSetAttribute(mma_gemm<EPI_NONE , false>, cudaFuncAttributeMaxDynamicSharedMemorySize, GEMM_SMEM);
        cudaFuncSetAttribute(hebb_mma_kernel,            cudaFuncAttributeMaxDynamicSharedMemorySize, HEBB_SMEM);
        attr_done = true;
    }

    const dim3 blk(256);
    const dim3 gh(HIDN / 128, BATCH / 128);
    const dim3 gd(DIN  / 128, BATCH / 128);

    prep_kernel<<<2048, 256>>>(x, cms_w1, cms_w2, gmw, gsw, ggw, Wslow, Wfast);

    // CMS level 0 (freq 1); A = pre-rounded x; residual R = original x.
    mma_gemm<EPI_RELU , true ><<<gh, blk, GEMM_SMEM>>>(xr,   w1r, cms_b1, nullptr, hbuf, HIDN, DIN,  step, 1);
    mma_gemm<EPI_RESID, true ><<<gd, blk, GEMM_SMEM>>>(hbuf, w2r, cms_b2, x,       buf,  DIN,  HIDN, step, 1);
    // CMS level 1 (freq 4)
    mma_gemm<EPI_RELU , true ><<<gh, blk, GEMM_SMEM>>>(buf,  w1r + NGW,     cms_b1 + HIDN,     nullptr, hbuf, HIDN, DIN,  step, 4);
    mma_gemm<EPI_RESID, true ><<<gd, blk, GEMM_SMEM>>>(hbuf, w2r + NGW,     cms_b2 + DIN,      buf,     buf,  DIN,  HIDN, step, 4);
    // CMS level 2 (freq 16)
    mma_gemm<EPI_RELU , true ><<<gh, blk, GEMM_SMEM>>>(buf,  w1r + 2 * NGW, cms_b1 + 2 * HIDN, nullptr, hbuf, HIDN, DIN,  step, 16);
    mma_gemm<EPI_RESID, true ><<<gd, blk, GEMM_SMEM>>>(hbuf, w2r + 2 * NGW, cms_b2 + 2 * DIN,  buf,     buf,  DIN,  HIDN, step, 16);

    // gate hidden sums
    mma_gemm<EPI_SIGW, false><<<gh, blk, GEMM_SMEM>>>(buf, gwr,           gmb, nullptr, hbuf, HIDN, DIN, step, 1);
    mma_gemm<EPI_SIGA, false><<<gh, blk, GEMM_SMEM>>>(buf, gwr + NGW,     gsb, nullptr, hbuf, HIDN, DIN, step, 1);
    mma_gemm<EPI_SIGA, false><<<gh, blk, GEMM_SMEM>>>(buf, gwr + 2 * NGW, ggb, nullptr, hbuf, HIDN, DIN, step, 1);

    gateout_kernel<<<BATCH / 8, 256>>>(hbuf, gow, gob);

    // slow / fast projections
    mma_gemm<EPI_NONE, false><<<gd, blk, GEMM_SMEM>>>(buf, sfr,       nullptr, nullptr, slow,  DOUT, DIN, step, 1);
    mma_gemm<EPI_NONE, false><<<gd, blk, GEMM_SMEM>>>(buf, sfr + NSF, nullptr, nullptr, fastb, DOUT, DIN, step, 1);

    hebb_mma_kernel<<<dim3(4, 4, 32), blk, HEBB_SMEM>>>();
    m2_kernel<<<BATCH / 256, 256>>>();

    finalize_kernel<<<BATCH, 128>>>(gamma, lbeta, out_ln);
    wfast_kernel<<<DOUT, 256>>>(Wfast, out_wf, out_st);
}

// round 9
// speedup vs baseline: 1.0378x; 1.0378x over previous
#include <cuda_runtime.h>
#include <math.h>
#include <stdint.h>

#define BATCH 65536
#define DIN   512
#define DOUT  512
#define HIDN  1024

// ---------------- scratch (static device globals; no allocation) -------------
__device__ float g_buf [(size_t)BATCH * DIN];
__device__ float g_h   [(size_t)BATCH * HIDN];
__device__ float g_slow[(size_t)BATCH * DOUT];
__device__ float g_fast[(size_t)BATCH * DOUT];
__device__ float g_gates[(size_t)BATCH * 3];
__device__ float g_hebb[DOUT * DIN];
__device__ float g_m2  [DOUT];
__device__ float g_stats[4];
__device__ float g_xr  [(size_t)BATCH * DIN];   // tf32-rounded copy of x

// tf32-rounded weight copies
__device__ float g_w1r[3 * HIDN * DIN];
__device__ float g_w2r[3 * DIN * HIDN];
__device__ float g_gwr[3 * HIDN * DIN];
__device__ float g_sfr[2 * DOUT * DIN];

__device__ __forceinline__ float sigf(float x) { return 1.0f / (1.0f + expf(-x)); }

__device__ __forceinline__ uint32_t f2tf32(float x) {
    uint32_t r;
    asm("cvt.rna.tf32.f32 %0, %1;" : "=r"(r) : "f"(x));
    return r;
}
__device__ __forceinline__ float roundtf(float x) { return __uint_as_float(f2tf32(x)); }

__device__ __forceinline__ void mma_tf32(float* c, const uint32_t* a, const uint32_t* b) {
    asm volatile(
        "mma.sync.aligned.m16n8k8.row.col.f32.tf32.tf32.f32 "
        "{%0,%1,%2,%3}, {%4,%5,%6,%7}, {%8,%9}, {%0,%1,%2,%3};\n"
        : "+f"(c[0]), "+f"(c[1]), "+f"(c[2]), "+f"(c[3])
        : "r"(a[0]), "r"(a[1]), "r"(a[2]), "r"(a[3]), "r"(b[0]), "r"(b[1]));
}

__device__ __forceinline__ void cp16(void* smem, const void* g) {
    uint32_t s = (uint32_t)__cvta_generic_to_shared(smem);
    asm volatile("cp.async.cg.shared.global [%0], [%1], 16;\n" :: "r"(s), "l"(g));
}
__device__ __forceinline__ void cp_commit() { asm volatile("cp.async.commit_group;\n"); }
template <int N>
__device__ __forceinline__ void cp_wait() { asm volatile("cp.async.wait_group %0;\n" :: "n"(N)); }

// ---------------- prepass ----------------------------------------------------
#define NW1 (3 * HIDN * DIN)
#define NW2 (3 * DIN * HIDN)
#define NGW (HIDN * DIN)
#define NSF (DOUT * DIN)
#define NX  ((size_t)BATCH * DIN)

__global__ void prep_kernel(const float* __restrict__ x,
                            const float* __restrict__ w1, const float* __restrict__ w2,
                            const float* __restrict__ gm, const float* __restrict__ gs,
                            const float* __restrict__ gg, const float* __restrict__ ws,
                            const float* __restrict__ wf)
{
    const size_t idx = blockIdx.x * blockDim.x + threadIdx.x;
    const size_t stride = (size_t)gridDim.x * blockDim.x;
    for (size_t i = idx; i < NX; i += stride) g_xr[i] = roundtf(x[i]);
    for (size_t i = idx; i < NW1; i += stride) g_w1r[i] = roundtf(w1[i]);
    for (size_t i = idx; i < NW2; i += stride) g_w2r[i] = roundtf(w2[i]);
    for (size_t i = idx; i < NGW; i += stride) {
        g_gwr[i]           = roundtf(gm[i]);
        g_gwr[i + NGW]     = roundtf(gs[i]);
        g_gwr[i + 2 * NGW] = roundtf(gg[i]);
    }
    for (size_t i = idx; i < NSF; i += stride) {
        g_sfr[i]       = roundtf(ws[i]);
        g_sfr[i + NSF] = roundtf(wf[i]);
    }
    for (size_t i = idx; i < DOUT * DIN; i += stride) g_hebb[i] = 0.0f;
    if (idx < DOUT) g_m2[idx] = 0.0f;
    if (idx < 4)    g_stats[idx] = 0.0f;
}

// ---------------- tf32 mma GEMM: 128x128 tile, 4 warps, warp tile 64x64 ------
enum { EPI_RELU = 0, EPI_RESID = 1, EPI_SIGW = 2, EPI_SIGA = 3, EPI_NONE = 4 };

#define SPITCH 20
#define GSTAGES 3
#define GEMM_SMEM (GSTAGES * 2 * 128 * SPITCH * 4)   // 61440 bytes

template <int EPI, bool ROUND_OUT>
__global__ __launch_bounds__(128, 2)
void mma_gemm(const float* __restrict__ A, const float* __restrict__ W,
              const float* __restrict__ bias, const float* __restrict__ R,
              float* __restrict__ C, int N, int K,
              const int* __restrict__ step, int freq)
{
    if (freq > 1) { if ((step[0] % freq) != 0) return; }

    extern __shared__ float dynsmem[];
    float (*As)[128][SPITCH] = (float(*)[128][SPITCH])dynsmem;
    float (*Bs)[128][SPITCH] = (float(*)[128][SPITCH])(dynsmem + GSTAGES * 128 * SPITCH);

    const int tid  = threadIdx.x;
    const int lane = tid & 31;
    const int warp = tid >> 5;     // 0..3
    const int wm   = warp >> 1;    // 0..1 -> 64 rows
    const int wn   = warp & 1;     // 0..1 -> 64 cols
    const int m0   = blockIdx.y * 128;
    const int n0   = blockIdx.x * 128;

    float acc[4][8][4];
#pragma unroll
    for (int mt = 0; mt < 4; ++mt)
#pragma unroll
        for (int nt = 0; nt < 8; ++nt)
#pragma unroll
            for (int i = 0; i < 4; ++i) acc[mt][nt][i] = 0.0f;

    const int lr = tid >> 2;   // 0..31
    const int lc = tid & 3;    // float4 chunk within 16-float k-tile

    const float* Ag = A + (size_t)(m0 + lr) * K + lc * 4;
    const float* Wg = W + (size_t)(n0 + lr) * K + lc * 4;

    const int KT = K >> 4;

    // prologue: stages 0,1
#pragma unroll
    for (int s = 0; s < GSTAGES - 1; ++s) {
        const size_t ko = (size_t)s * 16;
#pragma unroll
        for (int rr = 0; rr < 4; ++rr) {
            cp16(&As[s][lr + rr * 32][lc * 4], Ag + (size_t)rr * 32 * K + ko);
            cp16(&Bs[s][lr + rr * 32][lc * 4], Wg + (size_t)rr * 32 * K + ko);
        }
        cp_commit();
    }

    int cur = 0, nxt = GSTAGES - 1;
    for (int kt = 0; kt < KT; ++kt) {
        cp_wait<GSTAGES - 2>();
        __syncthreads();          // stage `cur` ready; slot `nxt` free (read at kt-1)

        if (kt + GSTAGES - 1 < KT) {
            const size_t ko = (size_t)(kt + GSTAGES - 1) * 16;
#pragma unroll
            for (int rr = 0; rr < 4; ++rr) {
                cp16(&As[nxt][lr + rr * 32][lc * 4], Ag + (size_t)rr * 32 * K + ko);
                cp16(&Bs[nxt][lr + rr * 32][lc * 4], Wg + (size_t)rr * 32 * K + ko);
            }
        }
        cp_commit();

#pragma unroll
        for (int ks = 0; ks < 2; ++ks) {
            const int kk = ks * 8 + (lane & 3);
            uint32_t af[4][4];
#pragma unroll
            for (int mt = 0; mt < 4; ++mt) {
                const int mr = wm * 64 + mt * 16 + (lane >> 2);
                af[mt][0] = __float_as_uint(As[cur][mr][kk]);
                af[mt][1] = __float_as_uint(As[cur][mr + 8][kk]);
                af[mt][2] = __float_as_uint(As[cur][mr][kk + 4]);
                af[mt][3] = __float_as_uint(As[cur][mr + 8][kk + 4]);
            }
            uint32_t bf[8][2];
#pragma unroll
            for (int nt = 0; nt < 8; ++nt) {
                const int nc = wn * 64 + nt * 8 + (lane >> 2);
                bf[nt][0] = __float_as_uint(Bs[cur][nc][kk]);
                bf[nt][1] = __float_as_uint(Bs[cur][nc][kk + 4]);
            }
#pragma unroll
            for (int mt = 0; mt < 4; ++mt)
#pragma unroll
                for (int nt = 0; nt < 8; ++nt)
                    mma_tf32(acc[mt][nt], af[mt], bf[nt]);
        }

        cur = (cur + 1 == GSTAGES) ? 0 : cur + 1;
        nxt = (nxt + 1 == GSTAGES) ? 0 : nxt + 1;
    }

    // epilogue
#pragma unroll
    for (int mt = 0; mt < 4; ++mt) {
#pragma unroll
        for (int nt = 0; nt < 8; ++nt) {
            const int col = n0 + wn * 64 + nt * 8 + (lane & 3) * 2;
            float bv0 = 0.f, bv1 = 0.f;
            if (EPI != EPI_NONE) { bv0 = bias[col]; bv1 = bias[col + 1]; }
#pragma unroll
            for (int h = 0; h < 2; ++h) {
                const int row = m0 + wm * 64 + mt * 16 + (lane >> 2) + h * 8;
                const size_t idx = (size_t)row * N + col;
                float v0 = acc[mt][nt][h * 2 + 0] + bv0;
                float v1 = acc[mt][nt][h * 2 + 1] + bv1;
                if (EPI == EPI_RELU) {
                    v0 = v0 > 0.f ? v0 : 0.f;
                    v1 = v1 > 0.f ? v1 : 0.f;
                } else if (EPI == EPI_RESID) {
                    v0 += R[idx]; v1 += R[idx + 1];
                } else if (EPI == EPI_SIGW) {
                    v0 = sigf(v0); v1 = sigf(v1);
                } else if (EPI == EPI_SIGA) {
                    v0 = C[idx] + sigf(v0); v1 = C[idx + 1] + sigf(v1);
                }
                if (ROUND_OUT) { v0 = roundtf(v0); v1 = roundtf(v1); }
                *(float2*)&C[idx] = make_float2(v0, v1);
            }
        }
    }
}

// ---------------- hebb: split-K tf32 GEMM, 4-stage pipeline (round-5) --------
#define HPITCH 136
#define HSTAGES 4
#define HEBB_SMEM (HSTAGES * 2 * 16 * HPITCH * 4)

__global__ __launch_bounds__(256, 2)
void hebb_mma_kernel()
{
    extern __shared__ float dynsmem[];
    float (*Fs)[16][HPITCH] = (float(*)[16][HPITCH])dynsmem;
    float (*Xs)[16][HPITCH] = (float(*)[16][HPITCH])(dynsmem + HSTAGES * 16 * HPITCH);

    const int tid  = threadIdx.x;
    const int lane = tid & 31;
    const int warp = tid >> 5;
    const int wm   = warp >> 2;
    const int wn   = warp & 3;
    const int o0   = blockIdx.x * 128;
    const int d0   = blockIdx.y * 128;
    const int b0   = blockIdx.z * 2048;

    float acc[4][4][4];
#pragma unroll
    for (int mt = 0; mt < 4; ++mt)
#pragma unroll
        for (int nt = 0; nt < 4; ++nt)
#pragma unroll
            for (int i = 0; i < 4; ++i) acc[mt][nt][i] = 0.0f;

    const int r0 = tid >> 5,         c0 = tid & 31;
    const int r1 = (tid + 256) >> 5, c1 = tid & 31;

    const int KT = 2048 / 16;

#pragma unroll
    for (int s = 0; s < HSTAGES - 1; ++s) {
        const int bb = b0 + s * 16;
        cp16(&Fs[s][r0][c0 * 4], &g_fast[(size_t)(bb + r0) * DOUT + o0 + c0 * 4]);
        cp16(&Fs[s][r1][c1 * 4], &g_fast[(size_t)(bb + r1) * DOUT + o0 + c1 * 4]);
        cp16(&Xs[s][r0][c0 * 4], &g_buf [(size_t)(bb + r0) * DIN  + d0 + c0 * 4]);
        cp16(&Xs[s][r1][c1 * 4], &g_buf [(size_t)(bb + r1) * DIN  + d0 + c1 * 4]);
        cp_commit();
    }

    for (int kt = 0; kt < KT; ++kt) {
        cp_wait<HSTAGES - 2>();
        __syncthreads();

        if (kt + HSTAGES - 1 < KT) {
            const int st = (kt + HSTAGES - 1) & (HSTAGES - 1);
            const int bb = b0 + (kt + HSTAGES - 1) * 16;
            cp16(&Fs[st][r0][c0 * 4], &g_fast[(size_t)(bb + r0) * DOUT + o0 + c0 * 4]);
            cp16(&Fs[st][r1][c1 * 4], &g_fast[(size_t)(bb + r1) * DOUT + o0 + c1 * 4]);
            cp16(&Xs[st][r0][c0 * 4], &g_buf [(size_t)(bb + r0) * DIN  + d0 + c0 * 4]);
            cp16(&Xs[st][r1][c1 * 4], &g_buf [(size_t)(bb + r1) * DIN  + d0 + c1 * 4]);
        }
        cp_commit();

        const int cur = kt & (HSTAGES - 1);
#pragma unroll
        for (int ks = 0; ks < 2; ++ks) {
            const int kk = ks * 8 + (lane & 3);
            uint32_t af[4][4];
#pragma unroll
            for (int mt = 0; mt < 4; ++mt) {
                const int mr = wm * 64 + mt * 16 + (lane >> 2);
                af[mt][0] = f2tf32(Fs[cur][kk][mr]);
                af[mt][1] = f2tf32(Fs[cur][kk][mr + 8]);
                af[mt][2] = f2tf32(Fs[cur][kk + 4][mr]);
                af[mt][3] = f2tf32(Fs[cur][kk + 4][mr + 8]);
            }
            uint32_t bf[4][2];
#pragma unroll
            for (int nt = 0; nt < 4; ++nt) {
                const int nc = wn * 32 + nt * 8 + (lane >> 2);
                bf[nt][0] = __float_as_uint(Xs[cur][kk][nc]);
                bf[nt][1] = __float_as_uint(Xs[cur][kk + 4][nc]);
            }
#pragma unroll
            for (int mt = 0; mt < 4; ++mt)
#pragma unroll
                for (int nt = 0; nt < 4; ++nt)
                    mma_tf32(acc[mt][nt], af[mt], bf[nt]);
        }
    }

#pragma unroll
    for (int mt = 0; mt < 4; ++mt)
#pragma unroll
        for (int nt = 0; nt < 4; ++nt) {
            const int col = d0 + wn * 32 + nt * 8 + (lane & 3) * 2;
#pragma unroll
            for (int h = 0; h < 2; ++h) {
                const int row = o0 + wm * 64 + mt * 16 + (lane >> 2) + h * 8;
                atomicAdd(&g_hebb[row * DIN + col],     acc[mt][nt][h * 2 + 0]);
                atomicAdd(&g_hebb[row * DIN + col + 1], acc[mt][nt][h * 2 + 1]);
            }
        }
}

// ---------------- gates head --------------------------------------------------
__global__ __launch_bounds__(256)
void gateout_kernel(const float* __restrict__ gsum,
                    const float* __restrict__ w,
                    const float* __restrict__ b3)
{
    __shared__ float sw[3 * HIDN];
    __shared__ float sacc[3];
    const int tid = threadIdx.x;
    for (int i = tid; i < 3 * HIDN; i += 256) sw[i] = w[i];
    if (tid < 3) sacc[tid] = 0.0f;
    __syncthreads();

    const int lane = tid & 31, warp = tid >> 5;
    const int b = blockIdx.x * 8 + warp;
    const float* row = gsum + (size_t)b * HIDN;
    float a0 = 0.f, a1 = 0.f, a2 = 0.f;
    for (int h = lane; h < HIDN; h += 32) {
        float v = row[h];
        a0 = fmaf(v, sw[h],            a0);
        a1 = fmaf(v, sw[HIDN + h],     a1);
        a2 = fmaf(v, sw[2 * HIDN + h], a2);
    }
#pragma unroll
    for (int o = 16; o > 0; o >>= 1) {
        a0 += __shfl_down_sync(0xffffffffu, a0, o);
        a1 += __shfl_down_sync(0xffffffffu, a1, o);
        a2 += __shfl_down_sync(0xffffffffu, a2, o);
    }
    if (lane == 0) {
        float s0 = sigf(a0 + b3[0]);
        float s1 = sigf(a1 + b3[1]);
        float s2 = sigf(a2 + b3[2]);
        g_gates[(size_t)b * 3 + 0] = s0;
        g_gates[(size_t)b * 3 + 1] = s1;
        g_gates[(size_t)b * 3 + 2] = s2;
        atomicAdd(&sacc[0], s0);
        atomicAdd(&sacc[1], s1);
        atomicAdd(&sacc[2], s2);
    }
    __syncthreads();
    if (tid < 3) atomicAdd(&g_stats[tid], sacc[tid]);
}

// ---------------- m2 -----------------------------------------------------------
__global__ __launch_bounds__(256)
void m2_kernel()
{
    const int c = threadIdx.x;
    const int r0 = blockIdx.x * 256;
    float s0 = 0.f, s1 = 0.f;
    for (int r = r0; r < r0 + 256; ++r) {
        float f0 = g_fast[(size_t)r * DOUT + c];
        float f1 = g_fast[(size_t)r * DOUT + c + 256];
        s0 = fmaf(f0, f0, s0);
        s1 = fmaf(f1, f1, s1);
    }
    atomicAdd(&g_m2[c], s0);
    atomicAdd(&g_m2[c + 256], s1);
}

// ---------------- combine + swish-beta + layernorm ---------------------------
__global__ __launch_bounds__(128)
void finalize_kernel(const float* __restrict__ gamma,
                     const float* __restrict__ lbeta,
                     float* __restrict__ outp)
{
    const int b = blockIdx.x;
    const int tid = threadIdx.x;
    const float sens = g_gates[(size_t)b * 3 + 1];
    const float gate = g_gates[(size_t)b * 3 + 2];
    const float be = 0.5f + 2.0f * sens;

    float a[4];
    float s = 0.f, sq = 0.f;
#pragma unroll
    for (int i = 0; i < 4; ++i) {
        const int c = tid + i * 128;
        float cmb = g_slow[(size_t)b * DOUT + c] + g_fast[(size_t)b * DOUT + c] * gate;
        float act = cmb * sigf(be * cmb);
        a[i] = act;
        s += act;
        sq = fmaf(act, act, sq);
    }

    __shared__ float sh[8];
#pragma unroll
    for (int o = 16; o > 0; o >>= 1) {
        s  += __shfl_down_sync(0xffffffffu, s,  o);
        sq += __shfl_down_sync(0xffffffffu, sq, o);
    }
    const int lane = tid & 31, warp = tid >> 5;
    if (lane == 0) { sh[warp] = s; sh[4 + warp] = sq; }
    __syncthreads();
    if (tid == 0) {
        sh[0] = sh[0] + sh[1] + sh[2] + sh[3];
        sh[4] = sh[4] + sh[5] + sh[6] + sh[7];
    }
    __syncthreads();
    const float mu  = sh[0] * (1.0f / DOUT);
    const float var = sh[4] * (1.0f / DOUT) - mu * mu;
    const float inv = rsqrtf(var + 1e-5f);
#pragma unroll
    for (int i = 0; i < 4; ++i) {
        const int c = tid + i * 128;
        outp[(size_t)b * DOUT + c] = (a[i] - mu) * inv * gamma[c] + lbeta[c];
    }
}

// ---------------- W_fast update + stats output -------------------------------
__global__ void wfast_kernel(const float* __restrict__ Wf,
                             float* __restrict__ out_wf,
                             float* __restrict__ out_st)
{
    const int o = blockIdx.x;
    const float rate = g_stats[0] * (0.1f / (float)BATCH);
    const float m2 = g_m2[o] * (1.0f / (float)BATCH);
    for (int d = threadIdx.x; d < DIN; d += blockDim.x) {
        const float wf = Wf[o * DIN + d];
        const float hebb = g_hebb[o * DIN + d] * (1.0f / (float)BATCH);
        out_wf[o * DIN + d] = wf + tanhf(hebb - m2 * wf) * rate;
    }
    if (o == 0 && threadIdx.x < 3)
        out_st[threadIdx.x] = g_stats[threadIdx.x] * (1.0f / (float)BATCH);
}

// ---------------- launch -----------------------------------------------------
extern "C" void kernel_launch(void* const* d_in, const int* in_sizes, int n_in,
                              void* d_out, int out_size)
{
    (void)in_sizes; (void)n_in; (void)out_size;

    const float* x      = (const float*)d_in[0];
    const int*   step   = (const int*)  d_in[1];
    const float* cms_w1 = (const float*)d_in[2];
    const float* cms_b1 = (const float*)d_in[3];
    const float* cms_w2 = (const float*)d_in[4];
    const float* cms_b2 = (const float*)d_in[5];
    const float* gmw    = (const float*)d_in[6];
    const float* gmb    = (const float*)d_in[7];
    const float* gsw    = (const float*)d_in[8];
    const float* gsb    = (const float*)d_in[9];
    const float* ggw    = (const float*)d_in[10];
    const float* ggb    = (const float*)d_in[11];
    const float* gow    = (const float*)d_in[12];
    const float* gob    = (const float*)d_in[13];
    const float* Wslow  = (const float*)d_in[14];
    const float* Wfast  = (const float*)d_in[15];
    const float* gamma  = (const float*)d_in[16];
    const float* lbeta  = (const float*)d_in[17];

    float* out    = (float*)d_out;
    float* out_ln = out;
    float* out_wf = out + (size_t)BATCH * DOUT;
    float* out_st = out_wf + DOUT * DIN;

    void* p;
    cudaGetSymbolAddress(&p, g_buf);  float* buf   = (float*)p;
    cudaGetSymbolAddress(&p, g_h);    float* hbuf  = (float*)p;
    cudaGetSymbolAddress(&p, g_slow); float* slow  = (float*)p;
    cudaGetSymbolAddress(&p, g_fast); float* fastb = (float*)p;
    cudaGetSymbolAddress(&p, g_xr);   float* xr    = (float*)p;
    cudaGetSymbolAddress(&p, g_w1r);  float* w1r   = (float*)p;
    cudaGetSymbolAddress(&p, g_w2r);  float* w2r   = (float*)p;
    cudaGetSymbolAddress(&p, g_gwr);  float* gwr   = (float*)p;
    cudaGetSymbolAddress(&p, g_sfr);  float* sfr   = (float*)p;

    static bool attr_done = false;
    if (!attr_done) {
        cudaFuncSetAttribute(mma_gemm<EPI_RELU , true >, cudaFuncAttributeMaxDynamicSharedMemorySize, GEMM_SMEM);
        cudaFuncSetAttribute(mma_gemm<EPI_RESID, true >, cudaFuncAttributeMaxDynamicSharedMemorySize, GEMM_SMEM);
        cudaFuncSetAttribute(mma_gemm<EPI_SIGW , false>, cudaFuncAttributeMaxDynamicSharedMemorySize, GEMM_SMEM);
        cudaFuncSetAttribute(mma_gemm<EPI_SIGA , false>, cudaFuncAttributeMaxDynamicSharedMemorySize, GEMM_SMEM);
        cudaFuncSetAttribute(mma_gemm<EPI_NONE , false>, cudaFuncAttributeMaxDynamicSharedMemorySize, GEMM_SMEM);
        cudaFuncSetAttribute(hebb_mma_kernel,            cudaFuncAttributeMaxDynamicSharedMemorySize, HEBB_SMEM);
        attr_done = true;
    }

    const dim3 blk(128);
    const dim3 gh(HIDN / 128, BATCH / 128);
    const dim3 gd(DIN  / 128, BATCH / 128);

    prep_kernel<<<2048, 256>>>(x, cms_w1, cms_w2, gmw, gsw, ggw, Wslow, Wfast);

    // CMS level 0 (freq 1); A = pre-rounded x; residual R = original x.
    mma_gemm<EPI_RELU , true ><<<gh, blk, GEMM_SMEM>>>(xr,   w1r, cms_b1, nullptr, hbuf, HIDN, DIN,  step, 1);
    mma_gemm<EPI_RESID, true ><<<gd, blk, GEMM_SMEM>>>(hbuf, w2r, cms_b2, x,       buf,  DIN,  HIDN, step, 1);
    // CMS level 1 (freq 4)
    mma_gemm<EPI_RELU , true ><<<gh, blk, GEMM_SMEM>>>(buf,  w1r + NGW,     cms_b1 + HIDN,     nullptr, hbuf, HIDN, DIN,  step, 4);
    mma_gemm<EPI_RESID, true ><<<gd, blk, GEMM_SMEM>>>(hbuf, w2r + NGW,     cms_b2 + DIN,      buf,     buf,  DIN,  HIDN, step, 4);
    // CMS level 2 (freq 16)
    mma_gemm<EPI_RELU , true ><<<gh, blk, GEMM_SMEM>>>(buf,  w1r + 2 * NGW, cms_b1 + 2 * HIDN, nullptr, hbuf, HIDN, DIN,  step, 16);
    mma_gemm<EPI_RESID, true ><<<gd, blk, GEMM_SMEM>>>(hbuf, w2r + 2 * NGW, cms_b2 + 2 * DIN,  buf,     buf,  DIN,  HIDN, step, 16);

    // gate hidden sums
    mma_gemm<EPI_SIGW, false><<<gh, blk, GEMM_SMEM>>>(buf, gwr,           gmb, nullptr, hbuf, HIDN, DIN, step, 1);
    mma_gemm<EPI_SIGA, false><<<gh, blk, GEMM_SMEM>>>(buf, gwr + NGW,     gsb, nullptr, hbuf, HIDN, DIN, step, 1);
    mma_gemm<EPI_SIGA, false><<<gh, blk, GEMM_SMEM>>>(buf, gwr + 2 * NGW, ggb, nullptr, hbuf, HIDN, DIN, step, 1);

    gateout_kernel<<<BATCH / 8, 256>>>(hbuf, gow, gob);

    // slow / fast projections
    mma_gemm<EPI_NONE, false><<<gd, blk, GEMM_SMEM>>>(buf, sfr,       nullptr, nullptr, slow,  DOUT, DIN, step, 1);
    mma_gemm<EPI_NONE, false><<<gd, blk, GEMM_SMEM>>>(buf, sfr + NSF, nullptr, nullptr, fastb, DOUT, DIN, step, 1);

    hebb_mma_kernel<<<dim3(4, 4, 32), dim3(256), HEBB_SMEM>>>();
    m2_kernel<<<BATCH / 256, 256>>>();

    finalize_kernel<<<BATCH, 128>>>(gamma, lbeta, out_ln);
    wfast_kernel<<<DOUT, 256>>>(Wfast, out_wf, out_st);
}

// round 10
// speedup vs baseline: 1.1952x; 1.1516x over previous
#include <cuda_runtime.h>
#include <math.h>
#include <stdint.h>

#define BATCH 65536
#define DIN   512
#define DOUT  512
#define HIDN  1024

// ---------------- scratch (static device globals; no allocation) -------------
__device__ float g_buf [(size_t)BATCH * DIN];
__device__ float g_h   [(size_t)BATCH * HIDN];   // cms hidden
__device__ float g_h3  [(size_t)BATCH * 3 * HIDN]; // 3 gate sigmoids (segments)
__device__ float g_sf  [(size_t)BATCH * 1024];   // [slow | fast] per row
__device__ float g_gates[(size_t)BATCH * 3];
__device__ float g_hebb[DOUT * DIN];
__device__ float g_m2  [DOUT];
__device__ float g_stats[4];
__device__ float g_xr  [(size_t)BATCH * DIN];
__device__ float g_gb3 [3 * HIDN];               // concat gate biases

// tf32-rounded weight copies
__device__ float g_w1r[3 * HIDN * DIN];
__device__ float g_w2r[3 * DIN * HIDN];
__device__ float g_gwr[3 * HIDN * DIN];
__device__ float g_sfr[2 * DOUT * DIN];

__device__ __forceinline__ float sigf(float x) { return 1.0f / (1.0f + expf(-x)); }

__device__ __forceinline__ uint32_t f2tf32(float x) {
    uint32_t r;
    asm("cvt.rna.tf32.f32 %0, %1;" : "=r"(r) : "f"(x));
    return r;
}
__device__ __forceinline__ float roundtf(float x) { return __uint_as_float(f2tf32(x)); }

__device__ __forceinline__ void mma_tf32(float* c, const uint32_t* a, const uint32_t* b) {
    asm volatile(
        "mma.sync.aligned.m16n8k8.row.col.f32.tf32.tf32.f32 "
        "{%0,%1,%2,%3}, {%4,%5,%6,%7}, {%8,%9}, {%0,%1,%2,%3};\n"
        : "+f"(c[0]), "+f"(c[1]), "+f"(c[2]), "+f"(c[3])
        : "r"(a[0]), "r"(a[1]), "r"(a[2]), "r"(a[3]), "r"(b[0]), "r"(b[1]));
}

__device__ __forceinline__ void cp16(void* smem, const void* g) {
    uint32_t s = (uint32_t)__cvta_generic_to_shared(smem);
    asm volatile("cp.async.cg.shared.global [%0], [%1], 16;\n" :: "r"(s), "l"(g));
}
__device__ __forceinline__ void cp_commit() { asm volatile("cp.async.commit_group;\n"); }
template <int N>
__device__ __forceinline__ void cp_wait() { asm volatile("cp.async.wait_group %0;\n" :: "n"(N)); }

// ---------------- prepass ----------------------------------------------------
#define NW1 (3 * HIDN * DIN)
#define NW2 (3 * DIN * HIDN)
#define NGW (HIDN * DIN)
#define NSF (DOUT * DIN)
#define NX  ((size_t)BATCH * DIN)

__global__ void prep_kernel(const float* __restrict__ x,
                            const float* __restrict__ w1, const float* __restrict__ w2,
                            const float* __restrict__ gm, const float* __restrict__ gs,
                            const float* __restrict__ gg, const float* __restrict__ ws,
                            const float* __restrict__ wf,
                            const float* __restrict__ gmb, const float* __restrict__ gsb,
                            const float* __restrict__ ggb)
{
    const size_t idx = blockIdx.x * blockDim.x + threadIdx.x;
    const size_t stride = (size_t)gridDim.x * blockDim.x;
    for (size_t i = idx; i < NX; i += stride) g_xr[i] = roundtf(x[i]);
    for (size_t i = idx; i < NW1; i += stride) g_w1r[i] = roundtf(w1[i]);
    for (size_t i = idx; i < NW2; i += stride) g_w2r[i] = roundtf(w2[i]);
    for (size_t i = idx; i < NGW; i += stride) {
        g_gwr[i]           = roundtf(gm[i]);
        g_gwr[i + NGW]     = roundtf(gs[i]);
        g_gwr[i + 2 * NGW] = roundtf(gg[i]);
    }
    for (size_t i = idx; i < NSF; i += stride) {
        g_sfr[i]       = roundtf(ws[i]);
        g_sfr[i + NSF] = roundtf(wf[i]);
    }
    for (size_t i = idx; i < HIDN; i += stride) {
        g_gb3[i]            = gmb[i];
        g_gb3[i + HIDN]     = gsb[i];
        g_gb3[i + 2 * HIDN] = ggb[i];
    }
    for (size_t i = idx; i < DOUT * DIN; i += stride) g_hebb[i] = 0.0f;
    if (idx < DOUT) g_m2[idx] = 0.0f;
    if (idx < 4)    g_stats[idx] = 0.0f;
}

// ---------------- tf32 mma GEMM: 128x128 tile, 8 warps 64x32, k-tile 32 ------
enum { EPI_RELU = 0, EPI_RESID = 1, EPI_SIGW = 2, EPI_NONE = 4 };

#define SPITCH 36       // 32 k-floats + 4 pad (36 mod 32 = 4 -> conflict-free)
#define GSTAGES 2
#define GEMM_SMEM (GSTAGES * 2 * 128 * SPITCH * 4)   // 73728 bytes

template <int EPI, bool ROUND_OUT>
__global__ __launch_bounds__(256, 2)
void mma_gemm(const float* __restrict__ A, const float* __restrict__ W,
              const float* __restrict__ bias, const float* __restrict__ R,
              float* __restrict__ C, int N, int K,
              const int* __restrict__ step, int freq)
{
    if (freq > 1) { if ((step[0] % freq) != 0) return; }

    extern __shared__ float dynsmem[];
    float (*As)[128][SPITCH] = (float(*)[128][SPITCH])dynsmem;
    float (*Bs)[128][SPITCH] = (float(*)[128][SPITCH])(dynsmem + GSTAGES * 128 * SPITCH);

    const int tid  = threadIdx.x;
    const int lane = tid & 31;
    const int warp = tid >> 5;
    const int wm   = warp >> 2;   // 0..1 -> 64 rows
    const int wn   = warp & 3;    // 0..3 -> 32 cols
    const int m0   = blockIdx.y * 128;
    const int n0   = blockIdx.x * 128;

    float acc[4][4][4];
#pragma unroll
    for (int mt = 0; mt < 4; ++mt)
#pragma unroll
        for (int nt = 0; nt < 4; ++nt)
#pragma unroll
            for (int i = 0; i < 4; ++i) acc[mt][nt][i] = 0.0f;

    // loader: 128 rows x 8 float4-chunks per operand; 4 rows per thread
    const int lr = tid >> 3;   // 0..31
    const int lc = tid & 7;    // chunk 0..7 (32 k-floats)

    const float* Ag = A + (size_t)(m0 + lr) * K + lc * 4;
    const float* Wg = W + (size_t)(n0 + lr) * K + lc * 4;

    const int KT = K >> 5;     // 32-deep k-tiles

    // prologue: tile 0 -> stage 0
#pragma unroll
    for (int rr = 0; rr < 4; ++rr) {
        cp16(&As[0][lr + rr * 32][lc * 4], Ag + (size_t)rr * 32 * K);
        cp16(&Bs[0][lr + rr * 32][lc * 4], Wg + (size_t)rr * 32 * K);
    }
    cp_commit();

    int cur = 0;
    for (int kt = 0; kt < KT; ++kt) {
        cp_wait<0>();
        __syncthreads();       // stage cur ready; other slot free (read at kt-1)

        if (kt + 1 < KT) {
            const int nxt = cur ^ 1;
            const size_t ko = (size_t)(kt + 1) * 32;
#pragma unroll
            for (int rr = 0; rr < 4; ++rr) {
                cp16(&As[nxt][lr + rr * 32][lc * 4], Ag + (size_t)rr * 32 * K + ko);
                cp16(&Bs[nxt][lr + rr * 32][lc * 4], Wg + (size_t)rr * 32 * K + ko);
            }
        }
        cp_commit();

#pragma unroll
        for (int ks = 0; ks < 4; ++ks) {
            const int kk = ks * 8 + (lane & 3);
            uint32_t af[4][4];
#pragma unroll
            for (int mt = 0; mt < 4; ++mt) {
                const int mr = wm * 64 + mt * 16 + (lane >> 2);
                af[mt][0] = __float_as_uint(As[cur][mr][kk]);
                af[mt][1] = __float_as_uint(As[cur][mr + 8][kk]);
                af[mt][2] = __float_as_uint(As[cur][mr][kk + 4]);
                af[mt][3] = __float_as_uint(As[cur][mr + 8][kk + 4]);
            }
            uint32_t bf[4][2];
#pragma unroll
            for (int nt = 0; nt < 4; ++nt) {
                const int nc = wn * 32 + nt * 8 + (lane >> 2);
                bf[nt][0] = __float_as_uint(Bs[cur][nc][kk]);
                bf[nt][1] = __float_as_uint(Bs[cur][nc][kk + 4]);
            }
#pragma unroll
            for (int mt = 0; mt < 4; ++mt)
#pragma unroll
                for (int nt = 0; nt < 4; ++nt)
                    mma_tf32(acc[mt][nt], af[mt], bf[nt]);
        }

        cur ^= 1;
    }

    // epilogue
#pragma unroll
    for (int mt = 0; mt < 4; ++mt) {
#pragma unroll
        for (int nt = 0; nt < 4; ++nt) {
            const int col = n0 + wn * 32 + nt * 8 + (lane & 3) * 2;
            float bv0 = 0.f, bv1 = 0.f;
            if (EPI != EPI_NONE) { bv0 = bias[col]; bv1 = bias[col + 1]; }
#pragma unroll
            for (int h = 0; h < 2; ++h) {
                const int row = m0 + wm * 64 + mt * 16 + (lane >> 2) + h * 8;
                const size_t idx = (size_t)row * N + col;
                float v0 = acc[mt][nt][h * 2 + 0] + bv0;
                float v1 = acc[mt][nt][h * 2 + 1] + bv1;
                if (EPI == EPI_RELU) {
                    v0 = v0 > 0.f ? v0 : 0.f;
                    v1 = v1 > 0.f ? v1 : 0.f;
                } else if (EPI == EPI_RESID) {
                    v0 += R[idx]; v1 += R[idx + 1];
                } else if (EPI == EPI_SIGW) {
                    v0 = sigf(v0); v1 = sigf(v1);
                }
                if (ROUND_OUT) { v0 = roundtf(v0); v1 = roundtf(v1); }
                *(float2*)&C[idx] = make_float2(v0, v1);
            }
        }
    }
}

// ---------------- hebb: split-K tf32 GEMM, 4-stage pipeline ------------------
#define HPITCH 136
#define HSTAGES 4
#define HEBB_SMEM (HSTAGES * 2 * 16 * HPITCH * 4)

__global__ __launch_bounds__(256, 2)
void hebb_mma_kernel()
{
    extern __shared__ float dynsmem[];
    float (*Fs)[16][HPITCH] = (float(*)[16][HPITCH])dynsmem;
    float (*Xs)[16][HPITCH] = (float(*)[16][HPITCH])(dynsmem + HSTAGES * 16 * HPITCH);

    const int tid  = threadIdx.x;
    const int lane = tid & 31;
    const int warp = tid >> 5;
    const int wm   = warp >> 2;
    const int wn   = warp & 3;
    const int o0   = blockIdx.x * 128;
    const int d0   = blockIdx.y * 128;
    const int b0   = blockIdx.z * 2048;

    float acc[4][4][4];
#pragma unroll
    for (int mt = 0; mt < 4; ++mt)
#pragma unroll
        for (int nt = 0; nt < 4; ++nt)
#pragma unroll
            for (int i = 0; i < 4; ++i) acc[mt][nt][i] = 0.0f;

    const int r0 = tid >> 5,         c0 = tid & 31;
    const int r1 = (tid + 256) >> 5, c1 = tid & 31;

    const int KT = 2048 / 16;

#pragma unroll
    for (int s = 0; s < HSTAGES - 1; ++s) {
        const int bb = b0 + s * 16;
        cp16(&Fs[s][r0][c0 * 4], &g_sf[(size_t)(bb + r0) * 1024 + 512 + o0 + c0 * 4]);
        cp16(&Fs[s][r1][c1 * 4], &g_sf[(size_t)(bb + r1) * 1024 + 512 + o0 + c1 * 4]);
        cp16(&Xs[s][r0][c0 * 4], &g_buf[(size_t)(bb + r0) * DIN + d0 + c0 * 4]);
        cp16(&Xs[s][r1][c1 * 4], &g_buf[(size_t)(bb + r1) * DIN + d0 + c1 * 4]);
        cp_commit();
    }

    for (int kt = 0; kt < KT; ++kt) {
        cp_wait<HSTAGES - 2>();
        __syncthreads();

        if (kt + HSTAGES - 1 < KT) {
            const int st = (kt + HSTAGES - 1) & (HSTAGES - 1);
            const int bb = b0 + (kt + HSTAGES - 1) * 16;
            cp16(&Fs[st][r0][c0 * 4], &g_sf[(size_t)(bb + r0) * 1024 + 512 + o0 + c0 * 4]);
            cp16(&Fs[st][r1][c1 * 4], &g_sf[(size_t)(bb + r1) * 1024 + 512 + o0 + c1 * 4]);
            cp16(&Xs[st][r0][c0 * 4], &g_buf[(size_t)(bb + r0) * DIN + d0 + c0 * 4]);
            cp16(&Xs[st][r1][c1 * 4], &g_buf[(size_t)(bb + r1) * DIN + d0 + c1 * 4]);
        }
        cp_commit();

        const int cur = kt & (HSTAGES - 1);
#pragma unroll
        for (int ks = 0; ks < 2; ++ks) {
            const int kk = ks * 8 + (lane & 3);
            uint32_t af[4][4];
#pragma unroll
            for (int mt = 0; mt < 4; ++mt) {
                const int mr = wm * 64 + mt * 16 + (lane >> 2);
                af[mt][0] = f2tf32(Fs[cur][kk][mr]);
                af[mt][1] = f2tf32(Fs[cur][kk][mr + 8]);
                af[mt][2] = f2tf32(Fs[cur][kk + 4][mr]);
                af[mt][3] = f2tf32(Fs[cur][kk + 4][mr + 8]);
            }
            uint32_t bf[4][2];
#pragma unroll
            for (int nt = 0; nt < 4; ++nt) {
                const int nc = wn * 32 + nt * 8 + (lane >> 2);
                bf[nt][0] = __float_as_uint(Xs[cur][kk][nc]);
                bf[nt][1] = __float_as_uint(Xs[cur][kk + 4][nc]);
            }
#pragma unroll
            for (int mt = 0; mt < 4; ++mt)
#pragma unroll
                for (int nt = 0; nt < 4; ++nt)
                    mma_tf32(acc[mt][nt], af[mt], bf[nt]);
        }
    }

#pragma unroll
    for (int mt = 0; mt < 4; ++mt)
#pragma unroll
        for (int nt = 0; nt < 4; ++nt) {
            const int col = d0 + wn * 32 + nt * 8 + (lane & 3) * 2;
#pragma unroll
            for (int h = 0; h < 2; ++h) {
                const int row = o0 + wm * 64 + mt * 16 + (lane >> 2) + h * 8;
                atomicAdd(&g_hebb[row * DIN + col],     acc[mt][nt][h * 2 + 0]);
                atomicAdd(&g_hebb[row * DIN + col + 1], acc[mt][nt][h * 2 + 1]);
            }
        }
}

// ---------------- gates head: sum 3 sigmoid segments, project to 3 -----------
__global__ __launch_bounds__(256)
void gateout_kernel(const float* __restrict__ h3,
                    const float* __restrict__ w,
                    const float* __restrict__ b3)
{
    __shared__ float sw[3 * HIDN];
    __shared__ float sacc[3];
    const int tid = threadIdx.x;
    for (int i = tid; i < 3 * HIDN; i += 256) sw[i] = w[i];
    if (tid < 3) sacc[tid] = 0.0f;
    __syncthreads();

    const int lane = tid & 31, warp = tid >> 5;
    const int b = blockIdx.x * 8 + warp;
    const float* row = h3 + (size_t)b * (3 * HIDN);
    float a0 = 0.f, a1 = 0.f, a2 = 0.f;
    for (int h = lane; h < HIDN; h += 32) {
        float v = (row[h] + row[HIDN + h]) + row[2 * HIDN + h];
        a0 = fmaf(v, sw[h],            a0);
        a1 = fmaf(v, sw[HIDN + h],     a1);
        a2 = fmaf(v, sw[2 * HIDN + h], a2);
    }
#pragma unroll
    for (int o = 16; o > 0; o >>= 1) {
        a0 += __shfl_down_sync(0xffffffffu, a0, o);
        a1 += __shfl_down_sync(0xffffffffu, a1, o);
        a2 += __shfl_down_sync(0xffffffffu, a2, o);
    }
    if (lane == 0) {
        float s0 = sigf(a0 + b3[0]);
        float s1 = sigf(a1 + b3[1]);
        float s2 = sigf(a2 + b3[2]);
        g_gates[(size_t)b * 3 + 0] = s0;
        g_gates[(size_t)b * 3 + 1] = s1;
        g_gates[(size_t)b * 3 + 2] = s2;
        atomicAdd(&sacc[0], s0);
        atomicAdd(&sacc[1], s1);
        atomicAdd(&sacc[2], s2);
    }
    __syncthreads();
    if (tid < 3) atomicAdd(&g_stats[tid], sacc[tid]);
}

// ---------------- m2 -----------------------------------------------------------
__global__ __launch_bounds__(256)
void m2_kernel()
{
    const int c = threadIdx.x;
    const int r0 = blockIdx.x * 256;
    float s0 = 0.f, s1 = 0.f;
    for (int r = r0; r < r0 + 256; ++r) {
        float f0 = g_sf[(size_t)r * 1024 + 512 + c];
        float f1 = g_sf[(size_t)r * 1024 + 512 + c + 256];
        s0 = fmaf(f0, f0, s0);
        s1 = fmaf(f1, f1, s1);
    }
    atomicAdd(&g_m2[c], s0);
    atomicAdd(&g_m2[c + 256], s1);
}

// ---------------- combine + swish-beta + layernorm ---------------------------
__global__ __launch_bounds__(128)
void finalize_kernel(const float* __restrict__ gamma,
                     const float* __restrict__ lbeta,
                     float* __restrict__ outp)
{
    const int b = blockIdx.x;
    const int tid = threadIdx.x;
    const float sens = g_gates[(size_t)b * 3 + 1];
    const float gate = g_gates[(size_t)b * 3 + 2];
    const float be = 0.5f + 2.0f * sens;

    const float* row = &g_sf[(size_t)b * 1024];

    float a[4];
    float s = 0.f, sq = 0.f;
#pragma unroll
    for (int i = 0; i < 4; ++i) {
        const int c = tid + i * 128;
        float cmb = row[c] + row[512 + c] * gate;
        float act = cmb * sigf(be * cmb);
        a[i] = act;
        s += act;
        sq = fmaf(act, act, sq);
    }

    __shared__ float sh[8];
#pragma unroll
    for (int o = 16; o > 0; o >>= 1) {
        s  += __shfl_down_sync(0xffffffffu, s,  o);
        sq += __shfl_down_sync(0xffffffffu, sq, o);
    }
    const int lane = tid & 31, warp = tid >> 5;
    if (lane == 0) { sh[warp] = s; sh[4 + warp] = sq; }
    __syncthreads();
    if (tid == 0) {
        sh[0] = sh[0] + sh[1] + sh[2] + sh[3];
        sh[4] = sh[4] + sh[5] + sh[6] + sh[7];
    }
    __syncthreads();
    const float mu  = sh[0] * (1.0f / DOUT);
    const float var = sh[4] * (1.0f / DOUT) - mu * mu;
    const float inv = rsqrtf(var + 1e-5f);
#pragma unroll
    for (int i = 0; i < 4; ++i) {
        const int c = tid + i * 128;
        outp[(size_t)b * DOUT + c] = (a[i] - mu) * inv * gamma[c] + lbeta[c];
    }
}

// ---------------- W_fast update + stats output -------------------------------
__global__ void wfast_kernel(const float* __restrict__ Wf,
                             float* __restrict__ out_wf,
                             float* __restrict__ out_st)
{
    const int o = blockIdx.x;
    const float rate = g_stats[0] * (0.1f / (float)BATCH);
    const float m2 = g_m2[o] * (1.0f / (float)BATCH);
    for (int d = threadIdx.x; d < DIN; d += blockDim.x) {
        const float wf = Wf[o * DIN + d];
        const float hebb = g_hebb[o * DIN + d] * (1.0f / (float)BATCH);
        out_wf[o * DIN + d] = wf + tanhf(hebb - m2 * wf) * rate;
    }
    if (o == 0 && threadIdx.x < 3)
        out_st[threadIdx.x] = g_stats[threadIdx.x] * (1.0f / (float)BATCH);
}

// ---------------- launch -----------------------------------------------------
extern "C" void kernel_launch(void* const* d_in, const int* in_sizes, int n_in,
                              void* d_out, int out_size)
{
    (void)in_sizes; (void)n_in; (void)out_size;

    const float* x      = (const float*)d_in[0];
    const int*   step   = (const int*)  d_in[1];
    const float* cms_w1 = (const float*)d_in[2];
    const float* cms_b1 = (const float*)d_in[3];
    const float* cms_w2 = (const float*)d_in[4];
    const float* cms_b2 = (const float*)d_in[5];
    const float* gmw    = (const float*)d_in[6];
    const float* gmb    = (const float*)d_in[7];
    const float* gsw    = (const float*)d_in[8];
    const float* gsb    = (const float*)d_in[9];
    const float* ggw    = (const float*)d_in[10];
    const float* ggb    = (const float*)d_in[11];
    const float* gow    = (const float*)d_in[12];
    const float* gob    = (const float*)d_in[13];
    const float* Wslow  = (const float*)d_in[14];
    const float* Wfast  = (const float*)d_in[15];
    const float* gamma  = (const float*)d_in[16];
    const float* lbeta  = (const float*)d_in[17];

    float* out    = (float*)d_out;
    float* out_ln = out;
    float* out_wf = out + (size_t)BATCH * DOUT;
    float* out_st = out_wf + DOUT * DIN;

    void* p;
    cudaGetSymbolAddress(&p, g_buf);  float* buf  = (float*)p;
    cudaGetSymbolAddress(&p, g_h);    float* hbuf = (float*)p;
    cudaGetSymbolAddress(&p, g_h3);   float* h3   = (float*)p;
    cudaGetSymbolAddress(&p, g_sf);   float* sf   = (float*)p;
    cudaGetSymbolAddress(&p, g_xr);   float* xr   = (float*)p;
    cudaGetSymbolAddress(&p, g_gb3);  float* gb3  = (float*)p;
    cudaGetSymbolAddress(&p, g_w1r);  float* w1r  = (float*)p;
    cudaGetSymbolAddress(&p, g_w2r);  float* w2r  = (float*)p;
    cudaGetSymbolAddress(&p, g_gwr);  float* gwr  = (float*)p;
    cudaGetSymbolAddress(&p, g_sfr);  float* sfr  = (float*)p;

    static bool attr_done = false;
    if (!attr_done) {
        cudaFuncSetAttribute(mma_gemm<EPI_RELU , true >, cudaFuncAttributeMaxDynamicSharedMemorySize, GEMM_SMEM);
        cudaFuncSetAttribute(mma_gemm<EPI_RESID, true >, cudaFuncAttributeMaxDynamicSharedMemorySize, GEMM_SMEM);
        cudaFuncSetAttribute(mma_gemm<EPI_SIGW , false>, cudaFuncAttributeMaxDynamicSharedMemorySize, GEMM_SMEM);
        cudaFuncSetAttribute(mma_gemm<EPI_NONE , false>, cudaFuncAttributeMaxDynamicSharedMemorySize, GEMM_SMEM);
        cudaFuncSetAttribute(hebb_mma_kernel,            cudaFuncAttributeMaxDynamicSharedMemorySize, HEBB_SMEM);
        attr_done = true;
    }

    const dim3 blk(256);
    const dim3 gh(HIDN / 128, BATCH / 128);        // N=1024
    const dim3 gd(DIN  / 128, BATCH / 128);        // N=512
    const dim3 gg3(3 * HIDN / 128, BATCH / 128);   // N=3072
    const dim3 gsf(1024 / 128, BATCH / 128);       // N=1024 (slow|fast)

    prep_kernel<<<2048, 256>>>(x, cms_w1, cms_w2, gmw, gsw, ggw, Wslow, Wfast,
                               gmb, gsb, ggb);

    // CMS level 0 (freq 1)
    mma_gemm<EPI_RELU , true ><<<gh, blk, GEMM_SMEM>>>(xr,   w1r, cms_b1, nullptr, hbuf, HIDN, DIN,  step, 1);
    mma_gemm<EPI_RESID, true ><<<gd, blk, GEMM_SMEM>>>(hbuf, w2r, cms_b2, x,       buf,  DIN,  HIDN, step, 1);
    // CMS level 1 (freq 4)
    mma_gemm<EPI_RELU , true ><<<gh, blk, GEMM_SMEM>>>(buf,  w1r + NGW,     cms_b1 + HIDN,     nullptr, hbuf, HIDN, DIN,  step, 4);
    mma_gemm<EPI_RESID, true ><<<gd, blk, GEMM_SMEM>>>(hbuf, w2r + NGW,     cms_b2 + DIN,      buf,     buf,  DIN,  HIDN, step, 4);
    // CMS level 2 (freq 16)
    mma_gemm<EPI_RELU , true ><<<gh, blk, GEMM_SMEM>>>(buf,  w1r + 2 * NGW, cms_b1 + 2 * HIDN, nullptr, hbuf, HIDN, DIN,  step, 16);
    mma_gemm<EPI_RESID, true ><<<gd, blk, GEMM_SMEM>>>(hbuf, w2r + 2 * NGW, cms_b2 + 2 * DIN,  buf,     buf,  DIN,  HIDN, step, 16);

    // fused gate hidden GEMM: N=3072, sigmoid epilogue into 3 segments
    mma_gemm<EPI_SIGW, false><<<gg3, blk, GEMM_SMEM>>>(buf, gwr, gb3, nullptr, h3, 3 * HIDN, DIN, step, 1);

    gateout_kernel<<<BATCH / 8, 256>>>(h3, gow, gob);

    // fused slow|fast projection: N=1024
    mma_gemm<EPI_NONE, false><<<gsf, blk, GEMM_SMEM>>>(buf, sfr, nullptr, nullptr, sf, 1024, DIN, step, 1);

    hebb_mma_kernel<<<dim3(4, 4, 32), dim3(256), HEBB_SMEM>>>();
    m2_kernel<<<BATCH / 256, 256>>>();

    finalize_kernel<<<BATCH, 128>>>(gamma, lbeta, out_ln);
    wfast_kernel<<<DOUT, 256>>>(Wfast, out_wf, out_st);
}

// round 11
// speedup vs baseline: 1.2193x; 1.0202x over previous
#include <cuda_runtime.h>
#include <math.h>
#include <stdint.h>

#define BATCH 65536
#define DIN   512
#define DOUT  512
#define HIDN  1024

// ---------------- scratch (static device globals; no allocation) -------------
__device__ float g_buf [(size_t)BATCH * DIN];
__device__ float g_h   [(size_t)BATCH * HIDN];     // cms hidden
__device__ float g_h3  [(size_t)BATCH * 3 * HIDN]; // 3 gate sigmoids (segments)
__device__ float g_sf  [(size_t)BATCH * 1024];     // [slow | fast] per row
__device__ float g_gates[(size_t)BATCH * 3];
__device__ float g_hebb[DOUT * DIN];
__device__ float g_m2  [DOUT];
__device__ float g_stats[4];
__device__ float g_xr  [(size_t)BATCH * DIN];
__device__ float g_gb3 [3 * HIDN];                 // concat gate biases

// tf32-rounded weight copies
__device__ float g_w1r[3 * HIDN * DIN];
__device__ float g_w2r[3 * DIN * HIDN];
__device__ float g_gwr[3 * HIDN * DIN];
__device__ float g_sfr[2 * DOUT * DIN];

__device__ __forceinline__ float sigf(float x) { return 1.0f / (1.0f + expf(-x)); }

__device__ __forceinline__ uint32_t f2tf32(float x) {
    uint32_t r;
    asm("cvt.rna.tf32.f32 %0, %1;" : "=r"(r) : "f"(x));
    return r;
}
__device__ __forceinline__ float roundtf(float x) { return __uint_as_float(f2tf32(x)); }

__device__ __forceinline__ void mma_tf32(float* c, const uint32_t* a, const uint32_t* b) {
    asm volatile(
        "mma.sync.aligned.m16n8k8.row.col.f32.tf32.tf32.f32 "
        "{%0,%1,%2,%3}, {%4,%5,%6,%7}, {%8,%9}, {%0,%1,%2,%3};\n"
        : "+f"(c[0]), "+f"(c[1]), "+f"(c[2]), "+f"(c[3])
        : "r"(a[0]), "r"(a[1]), "r"(a[2]), "r"(a[3]), "r"(b[0]), "r"(b[1]));
}

__device__ __forceinline__ void cp16(void* smem, const void* g) {
    uint32_t s = (uint32_t)__cvta_generic_to_shared(smem);
    asm volatile("cp.async.cg.shared.global [%0], [%1], 16;\n" :: "r"(s), "l"(g));
}
__device__ __forceinline__ void cp_commit() { asm volatile("cp.async.commit_group;\n"); }
template <int N>
__device__ __forceinline__ void cp_wait() { asm volatile("cp.async.wait_group %0;\n" :: "n"(N)); }

// ---------------- prepass ----------------------------------------------------
#define NW1 (3 * HIDN * DIN)
#define NW2 (3 * DIN * HIDN)
#define NGW (HIDN * DIN)
#define NSF (DOUT * DIN)
#define NX  ((size_t)BATCH * DIN)

__global__ void prep_kernel(const float* __restrict__ x,
                            const float* __restrict__ w1, const float* __restrict__ w2,
                            const float* __restrict__ gm, const float* __restrict__ gs,
                            const float* __restrict__ gg, const float* __restrict__ ws,
                            const float* __restrict__ wf,
                            const float* __restrict__ gmb, const float* __restrict__ gsb,
                            const float* __restrict__ ggb)
{
    const size_t idx = blockIdx.x * blockDim.x + threadIdx.x;
    const size_t stride = (size_t)gridDim.x * blockDim.x;
    for (size_t i = idx; i < NX; i += stride) g_xr[i] = roundtf(x[i]);
    for (size_t i = idx; i < NW1; i += stride) g_w1r[i] = roundtf(w1[i]);
    for (size_t i = idx; i < NW2; i += stride) g_w2r[i] = roundtf(w2[i]);
    for (size_t i = idx; i < NGW; i += stride) {
        g_gwr[i]           = roundtf(gm[i]);
        g_gwr[i + NGW]     = roundtf(gs[i]);
        g_gwr[i + 2 * NGW] = roundtf(gg[i]);
    }
    for (size_t i = idx; i < NSF; i += stride) {
        g_sfr[i]       = roundtf(ws[i]);
        g_sfr[i + NSF] = roundtf(wf[i]);
    }
    for (size_t i = idx; i < HIDN; i += stride) {
        g_gb3[i]            = gmb[i];
        g_gb3[i + HIDN]     = gsb[i];
        g_gb3[i + 2 * HIDN] = ggb[i];
    }
    for (size_t i = idx; i < DOUT * DIN; i += stride) g_hebb[i] = 0.0f;
    if (idx < DOUT) g_m2[idx] = 0.0f;
    if (idx < 4)    g_stats[idx] = 0.0f;
}

// ------ tf32 mma GEMM: 128x128 tile, 4 warps, warp tile 64x64, k-tile 32 -----
enum { EPI_RELU = 0, EPI_RESID = 1, EPI_SIGW = 2, EPI_NONE = 4 };

#define SPITCH 36       // 32 k-floats + 4 pad (36 mod 32 = 4 -> conflict-free)
#define GSTAGES 2
#define GEMM_SMEM (GSTAGES * 2 * 128 * SPITCH * 4)   // 73728 bytes

template <int EPI, bool ROUND_OUT>
__global__ __launch_bounds__(128, 2)
void mma_gemm(const float* __restrict__ A, const float* __restrict__ W,
              const float* __restrict__ bias, const float* __restrict__ R,
              float* __restrict__ C, int N, int K,
              const int* __restrict__ step, int freq)
{
    if (freq > 1) { if ((step[0] % freq) != 0) return; }

    extern __shared__ float dynsmem[];
    float (*As)[128][SPITCH] = (float(*)[128][SPITCH])dynsmem;
    float (*Bs)[128][SPITCH] = (float(*)[128][SPITCH])(dynsmem + GSTAGES * 128 * SPITCH);

    const int tid  = threadIdx.x;
    const int lane = tid & 31;
    const int warp = tid >> 5;     // 0..3
    const int wm   = warp >> 1;    // 0..1 -> 64 rows
    const int wn   = warp & 1;     // 0..1 -> 64 cols
    const int m0   = blockIdx.y * 128;
    const int n0   = blockIdx.x * 128;

    float acc[4][8][4];
#pragma unroll
    for (int mt = 0; mt < 4; ++mt)
#pragma unroll
        for (int nt = 0; nt < 8; ++nt)
#pragma unroll
            for (int i = 0; i < 4; ++i) acc[mt][nt][i] = 0.0f;

    // loader: 128 rows x 8 float4-chunks per operand; 8 rows per thread
    const int lr = tid >> 3;   // 0..15
    const int lc = tid & 7;    // chunk 0..7 (32 k-floats)

    const float* Ag = A + (size_t)(m0 + lr) * K + lc * 4;
    const float* Wg = W + (size_t)(n0 + lr) * K + lc * 4;

    const int KT = K >> 5;     // 32-deep k-tiles

    // prologue: tile 0 -> stage 0
#pragma unroll
    for (int rr = 0; rr < 8; ++rr) {
        cp16(&As[0][lr + rr * 16][lc * 4], Ag + (size_t)rr * 16 * K);
        cp16(&Bs[0][lr + rr * 16][lc * 4], Wg + (size_t)rr * 16 * K);
    }
    cp_commit();

    int cur = 0;
    for (int kt = 0; kt < KT; ++kt) {
        cp_wait<0>();
        __syncthreads();       // stage cur ready; other slot free (read at kt-1)

        if (kt + 1 < KT) {
            const int nxt = cur ^ 1;
            const size_t ko = (size_t)(kt + 1) * 32;
#pragma unroll
            for (int rr = 0; rr < 8; ++rr) {
                cp16(&As[nxt][lr + rr * 16][lc * 4], Ag + (size_t)rr * 16 * K + ko);
                cp16(&Bs[nxt][lr + rr * 16][lc * 4], Wg + (size_t)rr * 16 * K + ko);
            }
        }
        cp_commit();

#pragma unroll
        for (int ks = 0; ks < 4; ++ks) {
            const int kk = ks * 8 + (lane & 3);
            uint32_t af[4][4];
#pragma unroll
            for (int mt = 0; mt < 4; ++mt) {
                const int mr = wm * 64 + mt * 16 + (lane >> 2);
                af[mt][0] = __float_as_uint(As[cur][mr][kk]);
                af[mt][1] = __float_as_uint(As[cur][mr + 8][kk]);
                af[mt][2] = __float_as_uint(As[cur][mr][kk + 4]);
                af[mt][3] = __float_as_uint(As[cur][mr + 8][kk + 4]);
            }
            uint32_t bf[8][2];
#pragma unroll
            for (int nt = 0; nt < 8; ++nt) {
                const int nc = wn * 64 + nt * 8 + (lane >> 2);
                bf[nt][0] = __float_as_uint(Bs[cur][nc][kk]);
                bf[nt][1] = __float_as_uint(Bs[cur][nc][kk + 4]);
            }
#pragma unroll
            for (int mt = 0; mt < 4; ++mt)
#pragma unroll
                for (int nt = 0; nt < 8; ++nt)
                    mma_tf32(acc[mt][nt], af[mt], bf[nt]);
        }

        cur ^= 1;
    }

    // epilogue
#pragma unroll
    for (int mt = 0; mt < 4; ++mt) {
#pragma unroll
        for (int nt = 0; nt < 8; ++nt) {
            const int col = n0 + wn * 64 + nt * 8 + (lane & 3) * 2;
            float bv0 = 0.f, bv1 = 0.f;
            if (EPI != EPI_NONE) { bv0 = bias[col]; bv1 = bias[col + 1]; }
#pragma unroll
            for (int h = 0; h < 2; ++h) {
                const int row = m0 + wm * 64 + mt * 16 + (lane >> 2) + h * 8;
                const size_t idx = (size_t)row * N + col;
                float v0 = acc[mt][nt][h * 2 + 0] + bv0;
                float v1 = acc[mt][nt][h * 2 + 1] + bv1;
                if (EPI == EPI_RELU) {
                    v0 = v0 > 0.f ? v0 : 0.f;
                    v1 = v1 > 0.f ? v1 : 0.f;
                } else if (EPI == EPI_RESID) {
                    v0 += R[idx]; v1 += R[idx + 1];
                } else if (EPI == EPI_SIGW) {
                    v0 = sigf(v0); v1 = sigf(v1);
                }
                if (ROUND_OUT) { v0 = roundtf(v0); v1 = roundtf(v1); }
                *(float2*)&C[idx] = make_float2(v0, v1);
            }
        }
    }
}

// ---------------- hebb: split-K tf32 GEMM, 4-stage pipeline ------------------
#define HPITCH 136
#define HSTAGES 4
#define HEBB_SMEM (HSTAGES * 2 * 16 * HPITCH * 4)

__global__ __launch_bounds__(256, 2)
void hebb_mma_kernel()
{
    extern __shared__ float dynsmem[];
    float (*Fs)[16][HPITCH] = (float(*)[16][HPITCH])dynsmem;
    float (*Xs)[16][HPITCH] = (float(*)[16][HPITCH])(dynsmem + HSTAGES * 16 * HPITCH);

    const int tid  = threadIdx.x;
    const int lane = tid & 31;
    const int warp = tid >> 5;
    const int wm   = warp >> 2;
    const int wn   = warp & 3;
    const int o0   = blockIdx.x * 128;
    const int d0   = blockIdx.y * 128;
    const int b0   = blockIdx.z * 2048;

    float acc[4][4][4];
#pragma unroll
    for (int mt = 0; mt < 4; ++mt)
#pragma unroll
        for (int nt = 0; nt < 4; ++nt)
#pragma unroll
            for (int i = 0; i < 4; ++i) acc[mt][nt][i] = 0.0f;

    const int r0 = tid >> 5,         c0 = tid & 31;
    const int r1 = (tid + 256) >> 5, c1 = tid & 31;

    const int KT = 2048 / 16;

#pragma unroll
    for (int s = 0; s < HSTAGES - 1; ++s) {
        const int bb = b0 + s * 16;
        cp16(&Fs[s][r0][c0 * 4], &g_sf[(size_t)(bb + r0) * 1024 + 512 + o0 + c0 * 4]);
        cp16(&Fs[s][r1][c1 * 4], &g_sf[(size_t)(bb + r1) * 1024 + 512 + o0 + c1 * 4]);
        cp16(&Xs[s][r0][c0 * 4], &g_buf[(size_t)(bb + r0) * DIN + d0 + c0 * 4]);
        cp16(&Xs[s][r1][c1 * 4], &g_buf[(size_t)(bb + r1) * DIN + d0 + c1 * 4]);
        cp_commit();
    }

    for (int kt = 0; kt < KT; ++kt) {
        cp_wait<HSTAGES - 2>();
        __syncthreads();

        if (kt + HSTAGES - 1 < KT) {
            const int st = (kt + HSTAGES - 1) & (HSTAGES - 1);
            const int bb = b0 + (kt + HSTAGES - 1) * 16;
            cp16(&Fs[st][r0][c0 * 4], &g_sf[(size_t)(bb + r0) * 1024 + 512 + o0 + c0 * 4]);
            cp16(&Fs[st][r1][c1 * 4], &g_sf[(size_t)(bb + r1) * 1024 + 512 + o0 + c1 * 4]);
            cp16(&Xs[st][r0][c0 * 4], &g_buf[(size_t)(bb + r0) * DIN + d0 + c0 * 4]);
            cp16(&Xs[st][r1][c1 * 4], &g_buf[(size_t)(bb + r1) * DIN + d0 + c1 * 4]);
        }
        cp_commit();

        const int cur = kt & (HSTAGES - 1);
#pragma unroll
        for (int ks = 0; ks < 2; ++ks) {
            const int kk = ks * 8 + (lane & 3);
            uint32_t af[4][4];
#pragma unroll
            for (int mt = 0; mt < 4; ++mt) {
                const int mr = wm * 64 + mt * 16 + (lane >> 2);
                af[mt][0] = f2tf32(Fs[cur][kk][mr]);
                af[mt][1] = f2tf32(Fs[cur][kk][mr + 8]);
                af[mt][2] = f2tf32(Fs[cur][kk + 4][mr]);
                af[mt][3] = f2tf32(Fs[cur][kk + 4][mr + 8]);
            }
            uint32_t bf[4][2];
#pragma unroll
            for (int nt = 0; nt < 4; ++nt) {
                const int nc = wn * 32 + nt * 8 + (lane >> 2);
                bf[nt][0] = __float_as_uint(Xs[cur][kk][nc]);
                bf[nt][1] = __float_as_uint(Xs[cur][kk + 4][nc]);
            }
#pragma unroll
            for (int mt = 0; mt < 4; ++mt)
#pragma unroll
                for (int nt = 0; nt < 4; ++nt)
                    mma_tf32(acc[mt][nt], af[mt], bf[nt]);
        }
    }

#pragma unroll
    for (int mt = 0; mt < 4; ++mt)
#pragma unroll
        for (int nt = 0; nt < 4; ++nt) {
            const int col = d0 + wn * 32 + nt * 8 + (lane & 3) * 2;
#pragma unroll
            for (int h = 0; h < 2; ++h) {
                const int row = o0 + wm * 64 + mt * 16 + (lane >> 2) + h * 8;
                atomicAdd(&g_hebb[row * DIN + col],     acc[mt][nt][h * 2 + 0]);
                atomicAdd(&g_hebb[row * DIN + col + 1], acc[mt][nt][h * 2 + 1]);
            }
        }
}

// ---------------- gates head: sum 3 sigmoid segments, project to 3 -----------
__global__ __launch_bounds__(256)
void gateout_kernel(const float* __restrict__ h3,
                    const float* __restrict__ w,
                    const float* __restrict__ b3)
{
    __shared__ float sw[3 * HIDN];
    __shared__ float sacc[3];
    const int tid = threadIdx.x;
    for (int i = tid; i < 3 * HIDN; i += 256) sw[i] = w[i];
    if (tid < 3) sacc[tid] = 0.0f;
    __syncthreads();

    const int lane = tid & 31, warp = tid >> 5;
    const int b = blockIdx.x * 8 + warp;
    const float* row = h3 + (size_t)b * (3 * HIDN);
    float a0 = 0.f, a1 = 0.f, a2 = 0.f;
    for (int h = lane; h < HIDN; h += 32) {
        float v = (row[h] + row[HIDN + h]) + row[2 * HIDN + h];
        a0 = fmaf(v, sw[h],            a0);
        a1 = fmaf(v, sw[HIDN + h],     a1);
        a2 = fmaf(v, sw[2 * HIDN + h], a2);
    }
#pragma unroll
    for (int o = 16; o > 0; o >>= 1) {
        a0 += __shfl_down_sync(0xffffffffu, a0, o);
        a1 += __shfl_down_sync(0xffffffffu, a1, o);
        a2 += __shfl_down_sync(0xffffffffu, a2, o);
    }
    if (lane == 0) {
        float s0 = sigf(a0 + b3[0]);
        float s1 = sigf(a1 + b3[1]);
        float s2 = sigf(a2 + b3[2]);
        g_gates[(size_t)b * 3 + 0] = s0;
        g_gates[(size_t)b * 3 + 1] = s1;
        g_gates[(size_t)b * 3 + 2] = s2;
        atomicAdd(&sacc[0], s0);
        atomicAdd(&sacc[1], s1);
        atomicAdd(&sacc[2], s2);
    }
    __syncthreads();
    if (tid < 3) atomicAdd(&g_stats[tid], sacc[tid]);
}

// ---------------- m2 -----------------------------------------------------------
__global__ __launch_bounds__(256)
void m2_kernel()
{
    const int c = threadIdx.x;
    const int r0 = blockIdx.x * 256;
    float s0 = 0.f, s1 = 0.f;
    for (int r = r0; r < r0 + 256; ++r) {
        float f0 = g_sf[(size_t)r * 1024 + 512 + c];
        float f1 = g_sf[(size_t)r * 1024 + 512 + c + 256];
        s0 = fmaf(f0, f0, s0);
        s1 = fmaf(f1, f1, s1);
    }
    atomicAdd(&g_m2[c], s0);
    atomicAdd(&g_m2[c + 256], s1);
}

// ---------------- combine + swish-beta + layernorm ---------------------------
__global__ __launch_bounds__(128)
void finalize_kernel(const float* __restrict__ gamma,
                     const float* __restrict__ lbeta,
                     float* __restrict__ outp)
{
    const int b = blockIdx.x;
    const int tid = threadIdx.x;
    const float sens = g_gates[(size_t)b * 3 + 1];
    const float gate = g_gates[(size_t)b * 3 + 2];
    const float be = 0.5f + 2.0f * sens;

    const float* row = &g_sf[(size_t)b * 1024];

    float a[4];
    float s = 0.f, sq = 0.f;
#pragma unroll
    for (int i = 0; i < 4; ++i) {
        const int c = tid + i * 128;
        float cmb = row[c] + row[512 + c] * gate;
        float act = cmb * sigf(be * cmb);
        a[i] = act;
        s += act;
        sq = fmaf(act, act, sq);
    }

    __shared__ float sh[8];
#pragma unroll
    for (int o = 16; o > 0; o >>= 1) {
        s  += __shfl_down_sync(0xffffffffu, s,  o);
        sq += __shfl_down_sync(0xffffffffu, sq, o);
    }
    const int lane = tid & 31, warp = tid >> 5;
    if (lane == 0) { sh[warp] = s; sh[4 + warp] = sq; }
    __syncthreads();
    if (tid == 0) {
        sh[0] = sh[0] + sh[1] + sh[2] + sh[3];
        sh[4] = sh[4] + sh[5] + sh[6] + sh[7];
    }
    __syncthreads();
    const float mu  = sh[0] * (1.0f / DOUT);
    const float var = sh[4] * (1.0f / DOUT) - mu * mu;
    const float inv = rsqrtf(var + 1e-5f);
#pragma unroll
    for (int i = 0; i < 4; ++i) {
        const int c = tid + i * 128;
        outp[(size_t)b * DOUT + c] = (a[i] - mu) * inv * gamma[c] + lbeta[c];
    }
}

// ---------------- W_fast update + stats output -------------------------------
__global__ void wfast_kernel(const float* __restrict__ Wf,
                             float* __restrict__ out_wf,
                             float* __restrict__ out_st)
{
    const int o = blockIdx.x;
    const float rate = g_stats[0] * (0.1f / (float)BATCH);
    const float m2 = g_m2[o] * (1.0f / (float)BATCH);
    for (int d = threadIdx.x; d < DIN; d += blockDim.x) {
        const float wf = Wf[o * DIN + d];
        const float hebb = g_hebb[o * DIN + d] * (1.0f / (float)BATCH);
        out_wf[o * DIN + d] = wf + tanhf(hebb - m2 * wf) * rate;
    }
    if (o == 0 && threadIdx.x < 3)
        out_st[threadIdx.x] = g_stats[threadIdx.x] * (1.0f / (float)BATCH);
}

// ---------------- launch -----------------------------------------------------
extern "C" void kernel_launch(void* const* d_in, const int* in_sizes, int n_in,
                              void* d_out, int out_size)
{
    (void)in_sizes; (void)n_in; (void)out_size;

    const float* x      = (const float*)d_in[0];
    const int*   step   = (const int*)  d_in[1];
    const float* cms_w1 = (const float*)d_in[2];
    const float* cms_b1 = (const float*)d_in[3];
    const float* cms_w2 = (const float*)d_in[4];
    const float* cms_b2 = (const float*)d_in[5];
    const float* gmw    = (const float*)d_in[6];
    const float* gmb    = (const float*)d_in[7];
    const float* gsw    = (const float*)d_in[8];
    const float* gsb    = (const float*)d_in[9];
    const float* ggw    = (const float*)d_in[10];
    const float* ggb    = (const float*)d_in[11];
    const float* gow    = (const float*)d_in[12];
    const float* gob    = (const float*)d_in[13];
    const float* Wslow  = (const float*)d_in[14];
    const float* Wfast  = (const float*)d_in[15];
    const float* gamma  = (const float*)d_in[16];
    const float* lbeta  = (const float*)d_in[17];

    float* out    = (float*)d_out;
    float* out_ln = out;
    float* out_wf = out + (size_t)BATCH * DOUT;
    float* out_st = out_wf + DOUT * DIN;

    void* p;
    cudaGetSymbolAddress(&p, g_buf);  float* buf  = (float*)p;
    cudaGetSymbolAddress(&p, g_h);    float* hbuf = (float*)p;
    cudaGetSymbolAddress(&p, g_h3);   float* h3   = (float*)p;
    cudaGetSymbolAddress(&p, g_sf);   float* sf   = (float*)p;
    cudaGetSymbolAddress(&p, g_xr);   float* xr   = (float*)p;
    cudaGetSymbolAddress(&p, g_gb3);  float* gb3  = (float*)p;
    cudaGetSymbolAddress(&p, g_w1r);  float* w1r  = (float*)p;
    cudaGetSymbolAddress(&p, g_w2r);  float* w2r  = (float*)p;
    cudaGetSymbolAddress(&p, g_gwr);  float* gwr  = (float*)p;
    cudaGetSymbolAddress(&p, g_sfr);  float* sfr  = (float*)p;

    static bool attr_done = false;
    if (!attr_done) {
        cudaFuncSetAttribute(mma_gemm<EPI_RELU , true >, cudaFuncAttributeMaxDynamicSharedMemorySize, GEMM_SMEM);
        cudaFuncSetAttribute(mma_gemm<EPI_RESID, true >, cudaFuncAttributeMaxDynamicSharedMemorySize, GEMM_SMEM);
        cudaFuncSetAttribute(mma_gemm<EPI_SIGW , false>, cudaFuncAttributeMaxDynamicSharedMemorySize, GEMM_SMEM);
        cudaFuncSetAttribute(mma_gemm<EPI_NONE , false>, cudaFuncAttributeMaxDynamicSharedMemorySize, GEMM_SMEM);
        cudaFuncSetAttribute(hebb_mma_kernel,            cudaFuncAttributeMaxDynamicSharedMemorySize, HEBB_SMEM);
        attr_done = true;
    }

    const dim3 blk(128);
    const dim3 gh(HIDN / 128, BATCH / 128);        // N=1024
    const dim3 gd(DIN  / 128, BATCH / 128);        // N=512
    const dim3 gg3(3 * HIDN / 128, BATCH / 128);   // N=3072
    const dim3 gsf(1024 / 128, BATCH / 128);       // N=1024 (slow|fast)

    prep_kernel<<<2048, 256>>>(x, cms_w1, cms_w2, gmw, gsw, ggw, Wslow, Wfast,
                               gmb, gsb, ggb);

    // CMS level 0 (freq 1)
    mma_gemm<EPI_RELU , true ><<<gh, blk, GEMM_SMEM>>>(xr,   w1r, cms_b1, nullptr, hbuf, HIDN, DIN,  step, 1);
    mma_gemm<EPI_RESID, true ><<<gd, blk, GEMM_SMEM>>>(hbuf, w2r, cms_b2, x,       buf,  DIN,  HIDN, step, 1);
    // CMS level 1 (freq 4)
    mma_gemm<EPI_RELU , true ><<<gh, blk, GEMM_SMEM>>>(buf,  w1r + NGW,     cms_b1 + HIDN,     nullptr, hbuf, HIDN, DIN,  step, 4);
    mma_gemm<EPI_RESID, true ><<<gd, blk, GEMM_SMEM>>>(hbuf, w2r + NGW,     cms_b2 + DIN,      buf,     buf,  DIN,  HIDN, step, 4);
    // CMS level 2 (freq 16)
    mma_gemm<EPI_RELU , true ><<<gh, blk, GEMM_SMEM>>>(buf,  w1r + 2 * NGW, cms_b1 + 2 * HIDN, nullptr, hbuf, HIDN, DIN,  step, 16);
    mma_gemm<EPI_RESID, true ><<<gd, blk, GEMM_SMEM>>>(hbuf, w2r + 2 * NGW, cms_b2 + 2 * DIN,  buf,     buf,  DIN,  HIDN, step, 16);

    // fused gate hidden GEMM: N=3072, sigmoid epilogue into 3 segments
    mma_gemm<EPI_SIGW, false><<<gg3, blk, GEMM_SMEM>>>(buf, gwr, gb3, nullptr, h3, 3 * HIDN, DIN, step, 1);

    gateout_kernel<<<BATCH / 8, 256>>>(h3, gow, gob);

    // fused slow|fast projection: N=1024
    mma_gemm<EPI_NONE, false><<<gsf, blk, GEMM_SMEM>>>(buf, sfr, nullptr, nullptr, sf, 1024, DIN, step, 1);

    hebb_mma_kernel<<<dim3(4, 4, 32), dim3(256), HEBB_SMEM>>>();
    m2_kernel<<<BATCH / 256, 256>>>();

    finalize_kernel<<<BATCH, 128>>>(gamma, lbeta, out_ln);
    wfast_kernel<<<DOUT, 256>>>(Wfast, out_wf, out_st);
}

// round 12
// speedup vs baseline: 1.2611x; 1.0342x over previous
#include <cuda_runtime.h>
#include <math.h>
#include <stdint.h>

#define BATCH 65536
#define DIN   512
#define DOUT  512
#define HIDN  1024

// ---------------- scratch (static device globals; no allocation) -------------
__device__ float g_buf [(size_t)BATCH * DIN];
__device__ float g_h   [(size_t)BATCH * HIDN];     // cms hidden
__device__ float g_sf  [(size_t)BATCH * 1024];     // [slow | fast] per row
__device__ float g_gates[(size_t)BATCH * 3];
__device__ float g_pre [(size_t)BATCH * 3];        // gate pre-activations (atomic acc)
__device__ float g_hebb[DOUT * DIN];
__device__ float g_m2  [DOUT];
__device__ float g_stats[4];
__device__ float g_xr  [(size_t)BATCH * DIN];
__device__ float g_gb3 [3 * HIDN];                 // concat gate biases

// tf32-rounded weight copies
__device__ float g_w1r[3 * HIDN * DIN];
__device__ float g_w2r[3 * DIN * HIDN];
__device__ float g_gwr[3 * HIDN * DIN];
__device__ float g_sfr[2 * DOUT * DIN];

__device__ __forceinline__ float sigf(float x) { return 1.0f / (1.0f + expf(-x)); }

__device__ __forceinline__ uint32_t f2tf32(float x) {
    uint32_t r;
    asm("cvt.rna.tf32.f32 %0, %1;" : "=r"(r) : "f"(x));
    return r;
}
__device__ __forceinline__ float roundtf(float x) { return __uint_as_float(f2tf32(x)); }

__device__ __forceinline__ void mma_tf32(float* c, const uint32_t* a, const uint32_t* b) {
    asm volatile(
        "mma.sync.aligned.m16n8k8.row.col.f32.tf32.tf32.f32 "
        "{%0,%1,%2,%3}, {%4,%5,%6,%7}, {%8,%9}, {%0,%1,%2,%3};\n"
        : "+f"(c[0]), "+f"(c[1]), "+f"(c[2]), "+f"(c[3])
        : "r"(a[0]), "r"(a[1]), "r"(a[2]), "r"(a[3]), "r"(b[0]), "r"(b[1]));
}

__device__ __forceinline__ void cp16(void* smem, const void* g) {
    uint32_t s = (uint32_t)__cvta_generic_to_shared(smem);
    asm volatile("cp.async.cg.shared.global [%0], [%1], 16;\n" :: "r"(s), "l"(g));
}
__device__ __forceinline__ void cp_commit() { asm volatile("cp.async.commit_group;\n"); }
template <int N>
__device__ __forceinline__ void cp_wait() { asm volatile("cp.async.wait_group %0;\n" :: "n"(N)); }

// ---------------- prepass ----------------------------------------------------
#define NW1 (3 * HIDN * DIN)
#define NW2 (3 * DIN * HIDN)
#define NGW (HIDN * DIN)
#define NSF (DOUT * DIN)
#define NX  ((size_t)BATCH * DIN)

__global__ void prep_kernel(const float* __restrict__ x,
                            const float* __restrict__ w1, const float* __restrict__ w2,
                            const float* __restrict__ gm, const float* __restrict__ gs,
                            const float* __restrict__ gg, const float* __restrict__ ws,
                            const float* __restrict__ wf,
                            const float* __restrict__ gmb, const float* __restrict__ gsb,
                            const float* __restrict__ ggb)
{
    const size_t idx = blockIdx.x * blockDim.x + threadIdx.x;
    const size_t stride = (size_t)gridDim.x * blockDim.x;
    for (size_t i = idx; i < NX; i += stride) g_xr[i] = roundtf(x[i]);
    for (size_t i = idx; i < NW1; i += stride) g_w1r[i] = roundtf(w1[i]);
    for (size_t i = idx; i < NW2; i += stride) g_w2r[i] = roundtf(w2[i]);
    for (size_t i = idx; i < NGW; i += stride) {
        g_gwr[i]           = roundtf(gm[i]);
        g_gwr[i + NGW]     = roundtf(gs[i]);
        g_gwr[i + 2 * NGW] = roundtf(gg[i]);
    }
    for (size_t i = idx; i < NSF; i += stride) {
        g_sfr[i]       = roundtf(ws[i]);
        g_sfr[i + NSF] = roundtf(wf[i]);
    }
    for (size_t i = idx; i < HIDN; i += stride) {
        g_gb3[i]            = gmb[i];
        g_gb3[i + HIDN]     = gsb[i];
        g_gb3[i + 2 * HIDN] = ggb[i];
    }
    for (size_t i = idx; i < DOUT * DIN; i += stride) g_hebb[i] = 0.0f;
    for (size_t i = idx; i < (size_t)BATCH * 3; i += stride) g_pre[i] = 0.0f;
    if (idx < DOUT) g_m2[idx] = 0.0f;
    if (idx < 4)    g_stats[idx] = 0.0f;
}

// ------ tf32 mma GEMM: 128x128 tile, 4 warps, warp tile 64x64, k-tile 32 -----
enum { EPI_RELU = 0, EPI_RESID = 1, EPI_GPROJ = 2, EPI_NONE = 4 };

#define SPITCH 36       // 32 k-floats + 4 pad (36 mod 32 = 4 -> conflict-free)
#define GSTAGES 2
#define GEMM_SMEM (GSTAGES * 2 * 128 * SPITCH * 4)   // 73728 bytes

template <int EPI, bool ROUND_OUT>
__global__ __launch_bounds__(128, 2)
void mma_gemm(const float* __restrict__ A, const float* __restrict__ W,
              const float* __restrict__ bias, const float* __restrict__ R,
              float* __restrict__ C, int N, int K,
              const int* __restrict__ step, int freq,
              const float* __restrict__ gw, float* __restrict__ gpre)
{
    if (freq > 1) { if ((step[0] % freq) != 0) return; }

    extern __shared__ float dynsmem[];
    float (*As)[128][SPITCH] = (float(*)[128][SPITCH])dynsmem;
    float (*Bs)[128][SPITCH] = (float(*)[128][SPITCH])(dynsmem + GSTAGES * 128 * SPITCH);

    const int tid  = threadIdx.x;
    const int lane = tid & 31;
    const int warp = tid >> 5;     // 0..3
    const int wm   = warp >> 1;    // 0..1 -> 64 rows
    const int wn   = warp & 1;     // 0..1 -> 64 cols
    const int m0   = blockIdx.y * 128;
    const int n0   = blockIdx.x * 128;

    float acc[4][8][4];
#pragma unroll
    for (int mt = 0; mt < 4; ++mt)
#pragma unroll
        for (int nt = 0; nt < 8; ++nt)
#pragma unroll
            for (int i = 0; i < 4; ++i) acc[mt][nt][i] = 0.0f;

    // loader: 128 rows x 8 float4-chunks per operand; 8 rows per thread
    const int lr = tid >> 3;   // 0..15
    const int lc = tid & 7;    // chunk 0..7 (32 k-floats)

    const float* Ag = A + (size_t)(m0 + lr) * K + lc * 4;
    const float* Wg = W + (size_t)(n0 + lr) * K + lc * 4;

    const int KT = K >> 5;     // 32-deep k-tiles

    // prologue: tile 0 -> stage 0
#pragma unroll
    for (int rr = 0; rr < 8; ++rr) {
        cp16(&As[0][lr + rr * 16][lc * 4], Ag + (size_t)rr * 16 * K);
        cp16(&Bs[0][lr + rr * 16][lc * 4], Wg + (size_t)rr * 16 * K);
    }
    cp_commit();

    int cur = 0;
    for (int kt = 0; kt < KT; ++kt) {
        cp_wait<0>();
        __syncthreads();       // stage cur ready; other slot free (read at kt-1)

        if (kt + 1 < KT) {
            const int nxt = cur ^ 1;
            const size_t ko = (size_t)(kt + 1) * 32;
#pragma unroll
            for (int rr = 0; rr < 8; ++rr) {
                cp16(&As[nxt][lr + rr * 16][lc * 4], Ag + (size_t)rr * 16 * K + ko);
                cp16(&Bs[nxt][lr + rr * 16][lc * 4], Wg + (size_t)rr * 16 * K + ko);
            }
        }
        cp_commit();

#pragma unroll
        for (int ks = 0; ks < 4; ++ks) {
            const int kk = ks * 8 + (lane & 3);
            uint32_t af[4][4];
#pragma unroll
            for (int mt = 0; mt < 4; ++mt) {
                const int mr = wm * 64 + mt * 16 + (lane >> 2);
                af[mt][0] = __float_as_uint(As[cur][mr][kk]);
                af[mt][1] = __float_as_uint(As[cur][mr + 8][kk]);
                af[mt][2] = __float_as_uint(As[cur][mr][kk + 4]);
                af[mt][3] = __float_as_uint(As[cur][mr + 8][kk + 4]);
            }
            uint32_t bf[8][2];
#pragma unroll
            for (int nt = 0; nt < 8; ++nt) {
                const int nc = wn * 64 + nt * 8 + (lane >> 2);
                bf[nt][0] = __float_as_uint(Bs[cur][nc][kk]);
                bf[nt][1] = __float_as_uint(Bs[cur][nc][kk + 4]);
            }
#pragma unroll
            for (int mt = 0; mt < 4; ++mt)
#pragma unroll
                for (int nt = 0; nt < 8; ++nt)
                    mma_tf32(acc[mt][nt], af[mt], bf[nt]);
        }

        cur ^= 1;
    }

    // ---------------- epilogues ----------------
    if (EPI == EPI_GPROJ) {
        // partial projection: pr[mt][h][j] = sum over this thread's cols of
        // sig(v) * w_o[j][col&1023]; quad-reduce; atomicAdd into gpre[row*3+j].
        float pr[4][2][3];
#pragma unroll
        for (int mt = 0; mt < 4; ++mt)
#pragma unroll
            for (int h = 0; h < 2; ++h)
#pragma unroll
                for (int j = 0; j < 3; ++j) pr[mt][h][j] = 0.0f;

#pragma unroll
        for (int nt = 0; nt < 8; ++nt) {
            const int col = n0 + wn * 64 + nt * 8 + (lane & 3) * 2;
            const int hh  = col & (HIDN - 1);
            const float bv0 = bias[col], bv1 = bias[col + 1];
            const float w0a = gw[hh],            w0b = gw[hh + 1];
            const float w1a = gw[HIDN + hh],     w1b = gw[HIDN + hh + 1];
            const float w2a = gw[2 * HIDN + hh], w2b = gw[2 * HIDN + hh + 1];
#pragma unroll
            for (int mt = 0; mt < 4; ++mt)
#pragma unroll
                for (int h = 0; h < 2; ++h) {
                    const float v0 = sigf(acc[mt][nt][h * 2 + 0] + bv0);
                    const float v1 = sigf(acc[mt][nt][h * 2 + 1] + bv1);
                    pr[mt][h][0] += v0 * w0a + v1 * w0b;
                    pr[mt][h][1] += v0 * w1a + v1 * w1b;
                    pr[mt][h][2] += v0 * w2a + v1 * w2b;
                }
        }
#pragma unroll
        for (int mt = 0; mt < 4; ++mt)
#pragma unroll
            for (int h = 0; h < 2; ++h)
#pragma unroll
                for (int j = 0; j < 3; ++j) {
                    float v = pr[mt][h][j];
                    v += __shfl_xor_sync(0xffffffffu, v, 1);
                    v += __shfl_xor_sync(0xffffffffu, v, 2);
                    pr[mt][h][j] = v;
                }
        if ((lane & 3) == 0) {
#pragma unroll
            for (int mt = 0; mt < 4; ++mt)
#pragma unroll
                for (int h = 0; h < 2; ++h) {
                    const int row = m0 + wm * 64 + mt * 16 + (lane >> 2) + h * 8;
#pragma unroll
                    for (int j = 0; j < 3; ++j)
                        atomicAdd(&gpre[(size_t)row * 3 + j], pr[mt][h][j]);
                }
        }
        return;
    }

#pragma unroll
    for (int mt = 0; mt < 4; ++mt) {
#pragma unroll
        for (int nt = 0; nt < 8; ++nt) {
            const int col = n0 + wn * 64 + nt * 8 + (lane & 3) * 2;
            float bv0 = 0.f, bv1 = 0.f;
            if (EPI != EPI_NONE) { bv0 = bias[col]; bv1 = bias[col + 1]; }
#pragma unroll
            for (int h = 0; h < 2; ++h) {
                const int row = m0 + wm * 64 + mt * 16 + (lane >> 2) + h * 8;
                const size_t idx = (size_t)row * N + col;
                float v0 = acc[mt][nt][h * 2 + 0] + bv0;
                float v1 = acc[mt][nt][h * 2 + 1] + bv1;
                if (EPI == EPI_RELU) {
                    v0 = v0 > 0.f ? v0 : 0.f;
                    v1 = v1 > 0.f ? v1 : 0.f;
                } else if (EPI == EPI_RESID) {
                    v0 += R[idx]; v1 += R[idx + 1];
                }
                if (ROUND_OUT) { v0 = roundtf(v0); v1 = roundtf(v1); }
                *(float2*)&C[idx] = make_float2(v0, v1);
            }
        }
    }
}

// ---------------- gate_final: bias + sigmoid + stats -------------------------
__global__ __launch_bounds__(256)
void gate_final_kernel(const float* __restrict__ gob)
{
    __shared__ float sacc[3];
    const int tid = threadIdx.x;
    if (tid < 3) sacc[tid] = 0.0f;
    __syncthreads();

    const size_t b = (size_t)blockIdx.x * 256 + tid;
    float s0 = sigf(g_pre[b * 3 + 0] + gob[0]);
    float s1 = sigf(g_pre[b * 3 + 1] + gob[1]);
    float s2 = sigf(g_pre[b * 3 + 2] + gob[2]);
    g_gates[b * 3 + 0] = s0;
    g_gates[b * 3 + 1] = s1;
    g_gates[b * 3 + 2] = s2;

#pragma unroll
    for (int o = 16; o > 0; o >>= 1) {
        s0 += __shfl_down_sync(0xffffffffu, s0, o);
        s1 += __shfl_down_sync(0xffffffffu, s1, o);
        s2 += __shfl_down_sync(0xffffffffu, s2, o);
    }
    if ((tid & 31) == 0) {
        atomicAdd(&sacc[0], s0);
        atomicAdd(&sacc[1], s1);
        atomicAdd(&sacc[2], s2);
    }
    __syncthreads();
    if (tid < 3) atomicAdd(&g_stats[tid], sacc[tid]);
}

// ---------------- hebb: split-K tf32 GEMM, 4-stage pipeline ------------------
#define HPITCH 136
#define HSTAGES 4
#define HEBB_SMEM (HSTAGES * 2 * 16 * HPITCH * 4)

__global__ __launch_bounds__(256, 2)
void hebb_mma_kernel()
{
    extern __shared__ float dynsmem[];
    float (*Fs)[16][HPITCH] = (float(*)[16][HPITCH])dynsmem;
    float (*Xs)[16][HPITCH] = (float(*)[16][HPITCH])(dynsmem + HSTAGES * 16 * HPITCH);

    const int tid  = threadIdx.x;
    const int lane = tid & 31;
    const int warp = tid >> 5;
    const int wm   = warp >> 2;
    const int wn   = warp & 3;
    const int o0   = blockIdx.x * 128;
    const int d0   = blockIdx.y * 128;
    const int b0   = blockIdx.z * 2048;

    float acc[4][4][4];
#pragma unroll
    for (int mt = 0; mt < 4; ++mt)
#pragma unroll
        for (int nt = 0; nt < 4; ++nt)
#pragma unroll
            for (int i = 0; i < 4; ++i) acc[mt][nt][i] = 0.0f;

    const int r0 = tid >> 5,         c0 = tid & 31;
    const int r1 = (tid + 256) >> 5, c1 = tid & 31;

    const int KT = 2048 / 16;

#pragma unroll
    for (int s = 0; s < HSTAGES - 1; ++s) {
        const int bb = b0 + s * 16;
        cp16(&Fs[s][r0][c0 * 4], &g_sf[(size_t)(bb + r0) * 1024 + 512 + o0 + c0 * 4]);
        cp16(&Fs[s][r1][c1 * 4], &g_sf[(size_t)(bb + r1) * 1024 + 512 + o0 + c1 * 4]);
        cp16(&Xs[s][r0][c0 * 4], &g_buf[(size_t)(bb + r0) * DIN + d0 + c0 * 4]);
        cp16(&Xs[s][r1][c1 * 4], &g_buf[(size_t)(bb + r1) * DIN + d0 + c1 * 4]);
        cp_commit();
    }

    for (int kt = 0; kt < KT; ++kt) {
        cp_wait<HSTAGES - 2>();
        __syncthreads();

        if (kt + HSTAGES - 1 < KT) {
            const int st = (kt + HSTAGES - 1) & (HSTAGES - 1);
            const int bb = b0 + (kt + HSTAGES - 1) * 16;
            cp16(&Fs[st][r0][c0 * 4], &g_sf[(size_t)(bb + r0) * 1024 + 512 + o0 + c0 * 4]);
            cp16(&Fs[st][r1][c1 * 4], &g_sf[(size_t)(bb + r1) * 1024 + 512 + o0 + c1 * 4]);
            cp16(&Xs[st][r0][c0 * 4], &g_buf[(size_t)(bb + r0) * DIN + d0 + c0 * 4]);
            cp16(&Xs[st][r1][c1 * 4], &g_buf[(size_t)(bb + r1) * DIN + d0 + c1 * 4]);
        }
        cp_commit();

        const int cur = kt & (HSTAGES - 1);
#pragma unroll
        for (int ks = 0; ks < 2; ++ks) {
            const int kk = ks * 8 + (lane & 3);
            uint32_t af[4][4];
#pragma unroll
            for (int mt = 0; mt < 4; ++mt) {
                const int mr = wm * 64 + mt * 16 + (lane >> 2);
                af[mt][0] = f2tf32(Fs[cur][kk][mr]);
                af[mt][1] = f2tf32(Fs[cur][kk][mr + 8]);
                af[mt][2] = f2tf32(Fs[cur][kk + 4][mr]);
                af[mt][3] = f2tf32(Fs[cur][kk + 4][mr + 8]);
            }
            uint32_t bf[4][2];
#pragma unroll
            for (int nt = 0; nt < 4; ++nt) {
                const int nc = wn * 32 + nt * 8 + (lane >> 2);
                bf[nt][0] = __float_as_uint(Xs[cur][kk][nc]);
                bf[nt][1] = __float_as_uint(Xs[cur][kk + 4][nc]);
            }
#pragma unroll
            for (int mt = 0; mt < 4; ++mt)
#pragma unroll
                for (int nt = 0; nt < 4; ++nt)
                    mma_tf32(acc[mt][nt], af[mt], bf[nt]);
        }
    }

#pragma unroll
    for (int mt = 0; mt < 4; ++mt)
#pragma unroll
        for (int nt = 0; nt < 4; ++nt) {
            const int col = d0 + wn * 32 + nt * 8 + (lane & 3) * 2;
#pragma unroll
            for (int h = 0; h < 2; ++h) {
                const int row = o0 + wm * 64 + mt * 16 + (lane >> 2) + h * 8;
                atomicAdd(&g_hebb[row * DIN + col],     acc[mt][nt][h * 2 + 0]);
                atomicAdd(&g_hebb[row * DIN + col + 1], acc[mt][nt][h * 2 + 1]);
            }
        }
}

// ---------------- m2 -----------------------------------------------------------
__global__ __launch_bounds__(256)
void m2_kernel()
{
    const int c = threadIdx.x;
    const int r0 = blockIdx.x * 256;
    float s0 = 0.f, s1 = 0.f;
    for (int r = r0; r < r0 + 256; ++r) {
        float f0 = g_sf[(size_t)r * 1024 + 512 + c];
        float f1 = g_sf[(size_t)r * 1024 + 512 + c + 256];
        s0 = fmaf(f0, f0, s0);
        s1 = fmaf(f1, f1, s1);
    }
    atomicAdd(&g_m2[c], s0);
    atomicAdd(&g_m2[c + 256], s1);
}

// ---------------- combine + swish-beta + layernorm ---------------------------
__global__ __launch_bounds__(128)
void finalize_kernel(const float* __restrict__ gamma,
                     const float* __restrict__ lbeta,
                     float* __restrict__ outp)
{
    const int b = blockIdx.x;
    const int tid = threadIdx.x;
    const float sens = g_gates[(size_t)b * 3 + 1];
    const float gate = g_gates[(size_t)b * 3 + 2];
    const float be = 0.5f + 2.0f * sens;

    const float* row = &g_sf[(size_t)b * 1024];

    float a[4];
    float s = 0.f, sq = 0.f;
#pragma unroll
    for (int i = 0; i < 4; ++i) {
        const int c = tid + i * 128;
        float cmb = row[c] + row[512 + c] * gate;
        float act = cmb * sigf(be * cmb);
        a[i] = act;
        s += act;
        sq = fmaf(act, act, sq);
    }

    __shared__ float sh[8];
#pragma unroll
    for (int o = 16; o > 0; o >>= 1) {
        s  += __shfl_down_sync(0xffffffffu, s,  o);
        sq += __shfl_down_sync(0xffffffffu, sq, o);
    }
    const int lane = tid & 31, warp = tid >> 5;
    if (lane == 0) { sh[warp] = s; sh[4 + warp] = sq; }
    __syncthreads();
    if (tid == 0) {
        sh[0] = sh[0] + sh[1] + sh[2] + sh[3];
        sh[4] = sh[4] + sh[5] + sh[6] + sh[7];
    }
    __syncthreads();
    const float mu  = sh[0] * (1.0f / DOUT);
    const float var = sh[4] * (1.0f / DOUT) - mu * mu;
    const float inv = rsqrtf(var + 1e-5f);
#pragma unroll
    for (int i = 0; i < 4; ++i) {
        const int c = tid + i * 128;
        outp[(size_t)b * DOUT + c] = (a[i] - mu) * inv * gamma[c] + lbeta[c];
    }
}

// ---------------- W_fast update + stats output -------------------------------
__global__ void wfast_kernel(const float* __restrict__ Wf,
                             float* __restrict__ out_wf,
                             float* __restrict__ out_st)
{
    const int o = blockIdx.x;
    const float rate = g_stats[0] * (0.1f / (float)BATCH);
    const float m2 = g_m2[o] * (1.0f / (float)BATCH);
    for (int d = threadIdx.x; d < DIN; d += blockDim.x) {
        const float wf = Wf[o * DIN + d];
        const float hebb = g_hebb[o * DIN + d] * (1.0f / (float)BATCH);
        out_wf[o * DIN + d] = wf + tanhf(hebb - m2 * wf) * rate;
    }
    if (o == 0 && threadIdx.x < 3)
        out_st[threadIdx.x] = g_stats[threadIdx.x] * (1.0f / (float)BATCH);
}

// ---------------- launch -----------------------------------------------------
extern "C" void kernel_launch(void* const* d_in, const int* in_sizes, int n_in,
                              void* d_out, int out_size)
{
    (void)in_sizes; (void)n_in; (void)out_size;

    const float* x      = (const float*)d_in[0];
    const int*   step   = (const int*)  d_in[1];
    const float* cms_w1 = (const float*)d_in[2];
    const float* cms_b1 = (const float*)d_in[3];
    const float* cms_w2 = (const float*)d_in[4];
    const float* cms_b2 = (const float*)d_in[5];
    const float* gmw    = (const float*)d_in[6];
    const float* gmb    = (const float*)d_in[7];
    const float* gsw    = (const float*)d_in[8];
    const float* gsb    = (const float*)d_in[9];
    const float* ggw    = (const float*)d_in[10];
    const float* ggb    = (const float*)d_in[11];
    const float* gow    = (const float*)d_in[12];
    const float* gob    = (const float*)d_in[13];
    const float* Wslow  = (const float*)d_in[14];
    const float* Wfast  = (const float*)d_in[15];
    const float* gamma  = (const float*)d_in[16];
    const float* lbeta  = (const float*)d_in[17];

    float* out    = (float*)d_out;
    float* out_ln = out;
    float* out_wf = out + (size_t)BATCH * DOUT;
    float* out_st = out_wf + DOUT * DIN;

    void* p;
    cudaGetSymbolAddress(&p, g_buf);  float* buf  = (float*)p;
    cudaGetSymbolAddress(&p, g_h);    float* hbuf = (float*)p;
    cudaGetSymbolAddress(&p, g_sf);   float* sf   = (float*)p;
    cudaGetSymbolAddress(&p, g_xr);   float* xr   = (float*)p;
    cudaGetSymbolAddress(&p, g_gb3);  float* gb3  = (float*)p;
    cudaGetSymbolAddress(&p, g_pre);  float* pre  = (float*)p;
    cudaGetSymbolAddress(&p, g_w1r);  float* w1r  = (float*)p;
    cudaGetSymbolAddress(&p, g_w2r);  float* w2r  = (float*)p;
    cudaGetSymbolAddress(&p, g_gwr);  float* gwr  = (float*)p;
    cudaGetSymbolAddress(&p, g_sfr);  float* sfr  = (float*)p;

    static bool attr_done = false;
    if (!attr_done) {
        cudaFuncSetAttribute(mma_gemm<EPI_RELU , true >, cudaFuncAttributeMaxDynamicSharedMemorySize, GEMM_SMEM);
        cudaFuncSetAttribute(mma_gemm<EPI_RESID, true >, cudaFuncAttributeMaxDynamicSharedMemorySize, GEMM_SMEM);
        cudaFuncSetAttribute(mma_gemm<EPI_GPROJ, false>, cudaFuncAttributeMaxDynamicSharedMemorySize, GEMM_SMEM);
        cudaFuncSetAttribute(mma_gemm<EPI_NONE , false>, cudaFuncAttributeMaxDynamicSharedMemorySize, GEMM_SMEM);
        cudaFuncSetAttribute(hebb_mma_kernel,            cudaFuncAttributeMaxDynamicSharedMemorySize, HEBB_SMEM);
        attr_done = true;
    }

    const dim3 blk(128);
    const dim3 gh(HIDN / 128, BATCH / 128);        // N=1024
    const dim3 gd(DIN  / 128, BATCH / 128);        // N=512
    const dim3 gg3(3 * HIDN / 128, BATCH / 128);   // N=3072
    const dim3 gsf(1024 / 128, BATCH / 128);       // N=1024 (slow|fast)

    prep_kernel<<<2048, 256>>>(x, cms_w1, cms_w2, gmw, gsw, ggw, Wslow, Wfast,
                               gmb, gsb, ggb);

    // CMS level 0 (freq 1)
    mma_gemm<EPI_RELU , true ><<<gh, blk, GEMM_SMEM>>>(xr,   w1r, cms_b1, nullptr, hbuf, HIDN, DIN,  step, 1, nullptr, nullptr);
    mma_gemm<EPI_RESID, true ><<<gd, blk, GEMM_SMEM>>>(hbuf, w2r, cms_b2, x,       buf,  DIN,  HIDN, step, 1, nullptr, nullptr);
    // CMS level 1 (freq 4)
    mma_gemm<EPI_RELU , true ><<<gh, blk, GEMM_SMEM>>>(buf,  w1r + NGW,     cms_b1 + HIDN,     nullptr, hbuf, HIDN, DIN,  step, 4, nullptr, nullptr);
    mma_gemm<EPI_RESID, true ><<<gd, blk, GEMM_SMEM>>>(hbuf, w2r + NGW,     cms_b2 + DIN,      buf,     buf,  DIN,  HIDN, step, 4, nullptr, nullptr);
    // CMS level 2 (freq 16)
    mma_gemm<EPI_RELU , true ><<<gh, blk, GEMM_SMEM>>>(buf,  w1r + 2 * NGW, cms_b1 + 2 * HIDN, nullptr, hbuf, HIDN, DIN,  step, 16, nullptr, nullptr);
    mma_gemm<EPI_RESID, true ><<<gd, blk, GEMM_SMEM>>>(hbuf, w2r + 2 * NGW, cms_b2 + 2 * DIN,  buf,     buf,  DIN,  HIDN, step, 16, nullptr, nullptr);

    // fused gate GEMM + sigmoid + projection-to-3 (no C write)
    mma_gemm<EPI_GPROJ, false><<<gg3, blk, GEMM_SMEM>>>(buf, gwr, gb3, nullptr, nullptr, 3 * HIDN, DIN, step, 1, gow, pre);

    gate_final_kernel<<<BATCH / 256, 256>>>(gob);

    // fused slow|fast projection: N=1024
    mma_gemm<EPI_NONE, false><<<gsf, blk, GEMM_SMEM>>>(buf, sfr, nullptr, nullptr, sf, 1024, DIN, step, 1, nullptr, nullptr);

    hebb_mma_kernel<<<dim3(4, 4, 32), dim3(256), HEBB_SMEM>>>();
    m2_kernel<<<BATCH / 256, 256>>>();

    finalize_kernel<<<BATCH, 128>>>(gamma, lbeta, out_ln);
    wfast_kernel<<<DOUT, 256>>>(Wfast, out_wf, out_st);
}

// round 13
// speedup vs baseline: 1.2621x; 1.0008x over previous
#include <cuda_runtime.h>
#include <math.h>
#include <stdint.h>

#define BATCH 65536
#define DIN   512
#define DOUT  512
#define HIDN  1024

// ---------------- scratch (static device globals; no allocation) -------------
__device__ float g_buf [(size_t)BATCH * DIN];
__device__ float g_h   [(size_t)BATCH * HIDN];     // cms hidden
__device__ float g_sf  [(size_t)BATCH * 1024];     // [slow | fast] per row
__device__ float g_gates[(size_t)BATCH * 3];
__device__ float g_pre [(size_t)BATCH * 3];        // gate pre-activations (atomic acc)
__device__ float g_hebb[DOUT * DIN];
__device__ float g_m2  [DOUT];
__device__ float g_stats[4];
__device__ float g_xr  [(size_t)BATCH * DIN];
__device__ float g_gb3 [3 * HIDN];                 // concat gate biases

// tf32-rounded weight copies
__device__ float g_w1r [3 * HIDN * DIN];
__device__ float g_w2r [3 * DIN * HIDN];
__device__ float g_gsfw[4096 * DIN];               // [gates 3072 | slow 512 | fast 512]

__device__ __forceinline__ float sigf(float x) { return 1.0f / (1.0f + expf(-x)); }

__device__ __forceinline__ uint32_t f2tf32(float x) {
    uint32_t r;
    asm("cvt.rna.tf32.f32 %0, %1;" : "=r"(r) : "f"(x));
    return r;
}
__device__ __forceinline__ float roundtf(float x) { return __uint_as_float(f2tf32(x)); }

__device__ __forceinline__ void mma_tf32(float* c, const uint32_t* a, const uint32_t* b) {
    asm volatile(
        "mma.sync.aligned.m16n8k8.row.col.f32.tf32.tf32.f32 "
        "{%0,%1,%2,%3}, {%4,%5,%6,%7}, {%8,%9}, {%0,%1,%2,%3};\n"
        : "+f"(c[0]), "+f"(c[1]), "+f"(c[2]), "+f"(c[3])
        : "r"(a[0]), "r"(a[1]), "r"(a[2]), "r"(a[3]), "r"(b[0]), "r"(b[1]));
}

__device__ __forceinline__ void cp16(void* smem, const void* g) {
    uint32_t s = (uint32_t)__cvta_generic_to_shared(smem);
    asm volatile("cp.async.cg.shared.global [%0], [%1], 16;\n" :: "r"(s), "l"(g));
}
__device__ __forceinline__ void cp_commit() { asm volatile("cp.async.commit_group;\n"); }
template <int N>
__device__ __forceinline__ void cp_wait() { asm volatile("cp.async.wait_group %0;\n" :: "n"(N)); }

// ---------------- prepass ----------------------------------------------------
#define NW1 (3 * HIDN * DIN)
#define NW2 (3 * DIN * HIDN)
#define NGW (HIDN * DIN)
#define NSF (DOUT * DIN)
#define NX  ((size_t)BATCH * DIN)

__global__ void prep_kernel(const float* __restrict__ x,
                            const float* __restrict__ w1, const float* __restrict__ w2,
                            const float* __restrict__ gm, const float* __restrict__ gs,
                            const float* __restrict__ gg, const float* __restrict__ ws,
                            const float* __restrict__ wf,
                            const float* __restrict__ gmb, const float* __restrict__ gsb,
                            const float* __restrict__ ggb)
{
    const size_t idx = blockIdx.x * blockDim.x + threadIdx.x;
    const size_t stride = (size_t)gridDim.x * blockDim.x;
    for (size_t i = idx; i < NX; i += stride) g_xr[i] = roundtf(x[i]);
    for (size_t i = idx; i < NW1; i += stride) g_w1r[i] = roundtf(w1[i]);
    for (size_t i = idx; i < NW2; i += stride) g_w2r[i] = roundtf(w2[i]);
    for (size_t i = idx; i < NGW; i += stride) {
        g_gsfw[i]           = roundtf(gm[i]);
        g_gsfw[i + NGW]     = roundtf(gs[i]);
        g_gsfw[i + 2 * NGW] = roundtf(gg[i]);
    }
    for (size_t i = idx; i < NSF; i += stride) {
        g_gsfw[3 * NGW + i]       = roundtf(ws[i]);
        g_gsfw[3 * NGW + NSF + i] = roundtf(wf[i]);
    }
    for (size_t i = idx; i < HIDN; i += stride) {
        g_gb3[i]            = gmb[i];
        g_gb3[i + HIDN]     = gsb[i];
        g_gb3[i + 2 * HIDN] = ggb[i];
    }
    for (size_t i = idx; i < DOUT * DIN; i += stride) g_hebb[i] = 0.0f;
    for (size_t i = idx; i < (size_t)BATCH * 3; i += stride) g_pre[i] = 0.0f;
    if (idx < DOUT) g_m2[idx] = 0.0f;
    if (idx < 4)    g_stats[idx] = 0.0f;
}

// ------ tf32 mma GEMM: 128x128 tile, 4 warps, warp tile 64x64, k-tile 32 -----
enum { EPI_RELU = 0, EPI_RESID = 1, EPI_GSF = 2, EPI_NONE = 4 };

#define SPITCH 36       // 32 k-floats + 4 pad (36 mod 32 = 4 -> conflict-free)
#define GSTAGES 2
#define GEMM_SMEM (GSTAGES * 2 * 128 * SPITCH * 4)   // 73728 bytes

template <int EPI, bool ROUND_OUT>
__global__ __launch_bounds__(128, 2)
void mma_gemm(const float* __restrict__ A, const float* __restrict__ W,
              const float* __restrict__ bias, const float* __restrict__ R,
              float* __restrict__ C, int N, int K,
              const int* __restrict__ step, int freq,
              const float* __restrict__ gw, float* __restrict__ gpre)
{
    if (freq > 1) { if ((step[0] % freq) != 0) return; }

    extern __shared__ float dynsmem[];
    float (*As)[128][SPITCH] = (float(*)[128][SPITCH])dynsmem;
    float (*Bs)[128][SPITCH] = (float(*)[128][SPITCH])(dynsmem + GSTAGES * 128 * SPITCH);

    const int tid  = threadIdx.x;
    const int lane = tid & 31;
    const int warp = tid >> 5;     // 0..3
    const int wm   = warp >> 1;    // 0..1 -> 64 rows
    const int wn   = warp & 1;     // 0..1 -> 64 cols
    const int m0   = blockIdx.y * 128;
    const int n0   = blockIdx.x * 128;

    float acc[4][8][4];
#pragma unroll
    for (int mt = 0; mt < 4; ++mt)
#pragma unroll
        for (int nt = 0; nt < 8; ++nt)
#pragma unroll
            for (int i = 0; i < 4; ++i) acc[mt][nt][i] = 0.0f;

    // loader: 128 rows x 8 float4-chunks per operand; 8 rows per thread
    const int lr = tid >> 3;   // 0..15
    const int lc = tid & 7;    // chunk 0..7 (32 k-floats)

    const float* Ag = A + (size_t)(m0 + lr) * K + lc * 4;
    const float* Wg = W + (size_t)(n0 + lr) * K + lc * 4;

    const int KT = K >> 5;     // 32-deep k-tiles

    // prologue: tile 0 -> stage 0
#pragma unroll
    for (int rr = 0; rr < 8; ++rr) {
        cp16(&As[0][lr + rr * 16][lc * 4], Ag + (size_t)rr * 16 * K);
        cp16(&Bs[0][lr + rr * 16][lc * 4], Wg + (size_t)rr * 16 * K);
    }
    cp_commit();

    int cur = 0;
    for (int kt = 0; kt < KT; ++kt) {
        cp_wait<0>();
        __syncthreads();       // stage cur ready; other slot free (read at kt-1)

        if (kt + 1 < KT) {
            const int nxt = cur ^ 1;
            const size_t ko = (size_t)(kt + 1) * 32;
#pragma unroll
            for (int rr = 0; rr < 8; ++rr) {
                cp16(&As[nxt][lr + rr * 16][lc * 4], Ag + (size_t)rr * 16 * K + ko);
                cp16(&Bs[nxt][lr + rr * 16][lc * 4], Wg + (size_t)rr * 16 * K + ko);
            }
        }
        cp_commit();

#pragma unroll
        for (int ks = 0; ks < 4; ++ks) {
            const int kk = ks * 8 + (lane & 3);
            uint32_t af[4][4];
#pragma unroll
            for (int mt = 0; mt < 4; ++mt) {
                const int mr = wm * 64 + mt * 16 + (lane >> 2);
                af[mt][0] = __float_as_uint(As[cur][mr][kk]);
                af[mt][1] = __float_as_uint(As[cur][mr + 8][kk]);
                af[mt][2] = __float_as_uint(As[cur][mr][kk + 4]);
                af[mt][3] = __float_as_uint(As[cur][mr + 8][kk + 4]);
            }
            uint32_t bf[8][2];
#pragma unroll
            for (int nt = 0; nt < 8; ++nt) {
                const int nc = wn * 64 + nt * 8 + (lane >> 2);
                bf[nt][0] = __float_as_uint(Bs[cur][nc][kk]);
                bf[nt][1] = __float_as_uint(Bs[cur][nc][kk + 4]);
            }
#pragma unroll
            for (int mt = 0; mt < 4; ++mt)
#pragma unroll
                for (int nt = 0; nt < 8; ++nt)
                    mma_tf32(acc[mt][nt], af[mt], bf[nt]);
        }

        cur ^= 1;
    }

    // ---------------- epilogues ----------------
    if (EPI == EPI_GSF) {
        if (n0 < 3 * HIDN) {
            // gates: sigmoid + rank-3 projection, atomic into gpre
            float pr[4][2][3];
#pragma unroll
            for (int mt = 0; mt < 4; ++mt)
#pragma unroll
                for (int h = 0; h < 2; ++h)
#pragma unroll
                    for (int j = 0; j < 3; ++j) pr[mt][h][j] = 0.0f;

#pragma unroll
            for (int nt = 0; nt < 8; ++nt) {
                const int col = n0 + wn * 64 + nt * 8 + (lane & 3) * 2;
                const int hh  = col & (HIDN - 1);
                const float bv0 = bias[col], bv1 = bias[col + 1];
                const float w0a = gw[hh],            w0b = gw[hh + 1];
                const float w1a = gw[HIDN + hh],     w1b = gw[HIDN + hh + 1];
                const float w2a = gw[2 * HIDN + hh], w2b = gw[2 * HIDN + hh + 1];
#pragma unroll
                for (int mt = 0; mt < 4; ++mt)
#pragma unroll
                    for (int h = 0; h < 2; ++h) {
                        const float v0 = sigf(acc[mt][nt][h * 2 + 0] + bv0);
                        const float v1 = sigf(acc[mt][nt][h * 2 + 1] + bv1);
                        pr[mt][h][0] += v0 * w0a + v1 * w0b;
                        pr[mt][h][1] += v0 * w1a + v1 * w1b;
                        pr[mt][h][2] += v0 * w2a + v1 * w2b;
                    }
            }
#pragma unroll
            for (int mt = 0; mt < 4; ++mt)
#pragma unroll
                for (int h = 0; h < 2; ++h)
#pragma unroll
                    for (int j = 0; j < 3; ++j) {
                        float v = pr[mt][h][j];
                        v += __shfl_xor_sync(0xffffffffu, v, 1);
                        v += __shfl_xor_sync(0xffffffffu, v, 2);
                        pr[mt][h][j] = v;
                    }
            if ((lane & 3) == 0) {
#pragma unroll
                for (int mt = 0; mt < 4; ++mt)
#pragma unroll
                    for (int h = 0; h < 2; ++h) {
                        const int row = m0 + wm * 64 + mt * 16 + (lane >> 2) + h * 8;
#pragma unroll
                        for (int j = 0; j < 3; ++j)
                            atomicAdd(&gpre[(size_t)row * 3 + j], pr[mt][h][j]);
                    }
            }
        } else {
            // slow|fast: write to g_sf; fast half also accumulates m2
            const bool isfast = (n0 >= 3 * HIDN + 512);
#pragma unroll
            for (int nt = 0; nt < 8; ++nt) {
                const int col = n0 + wn * 64 + nt * 8 + (lane & 3) * 2;
                const int csf = col - 3 * HIDN;      // 0..1023
                float s0 = 0.f, s1 = 0.f;
#pragma unroll
                for (int mt = 0; mt < 4; ++mt)
#pragma unroll
                    for (int h = 0; h < 2; ++h) {
                        const int row = m0 + wm * 64 + mt * 16 + (lane >> 2) + h * 8;
                        const float v0 = acc[mt][nt][h * 2 + 0];
                        const float v1 = acc[mt][nt][h * 2 + 1];
                        *(float2*)&C[(size_t)row * 1024 + csf] = make_float2(v0, v1);
                        s0 = fmaf(v0, v0, s0);
                        s1 = fmaf(v1, v1, s1);
                    }
                if (isfast) {
                    s0 += __shfl_xor_sync(0xffffffffu, s0, 4);
                    s0 += __shfl_xor_sync(0xffffffffu, s0, 8);
                    s0 += __shfl_xor_sync(0xffffffffu, s0, 16);
                    s1 += __shfl_xor_sync(0xffffffffu, s1, 4);
                    s1 += __shfl_xor_sync(0xffffffffu, s1, 8);
                    s1 += __shfl_xor_sync(0xffffffffu, s1, 16);
                    if ((lane >> 2) == 0) {
                        atomicAdd(&g_m2[csf - 512],     s0);
                        atomicAdd(&g_m2[csf - 512 + 1], s1);
                    }
                }
            }
        }
        return;
    }

#pragma unroll
    for (int mt = 0; mt < 4; ++mt) {
#pragma unroll
        for (int nt = 0; nt < 8; ++nt) {
            const int col = n0 + wn * 64 + nt * 8 + (lane & 3) * 2;
            float bv0 = 0.f, bv1 = 0.f;
            if (EPI != EPI_NONE) { bv0 = bias[col]; bv1 = bias[col + 1]; }
#pragma unroll
            for (int h = 0; h < 2; ++h) {
                const int row = m0 + wm * 64 + mt * 16 + (lane >> 2) + h * 8;
                const size_t idx = (size_t)row * N + col;
                float v0 = acc[mt][nt][h * 2 + 0] + bv0;
                float v1 = acc[mt][nt][h * 2 + 1] + bv1;
                if (EPI == EPI_RELU) {
                    v0 = v0 > 0.f ? v0 : 0.f;
                    v1 = v1 > 0.f ? v1 : 0.f;
                } else if (EPI == EPI_RESID) {
                    v0 += R[idx]; v1 += R[idx + 1];
                }
                if (ROUND_OUT) { v0 = roundtf(v0); v1 = roundtf(v1); }
                *(float2*)&C[idx] = make_float2(v0, v1);
            }
        }
    }
}

// ---------------- gate_final: bias + sigmoid + stats -------------------------
__global__ __launch_bounds__(256)
void gate_final_kernel(const float* __restrict__ gob)
{
    __shared__ float sacc[3];
    const int tid = threadIdx.x;
    if (tid < 3) sacc[tid] = 0.0f;
    __syncthreads();

    const size_t b = (size_t)blockIdx.x * 256 + tid;
    float s0 = sigf(g_pre[b * 3 + 0] + gob[0]);
    float s1 = sigf(g_pre[b * 3 + 1] + gob[1]);
    float s2 = sigf(g_pre[b * 3 + 2] + gob[2]);
    g_gates[b * 3 + 0] = s0;
    g_gates[b * 3 + 1] = s1;
    g_gates[b * 3 + 2] = s2;

#pragma unroll
    for (int o = 16; o > 0; o >>= 1) {
        s0 += __shfl_down_sync(0xffffffffu, s0, o);
        s1 += __shfl_down_sync(0xffffffffu, s1, o);
        s2 += __shfl_down_sync(0xffffffffu, s2, o);
    }
    if ((tid & 31) == 0) {
        atomicAdd(&sacc[0], s0);
        atomicAdd(&sacc[1], s1);
        atomicAdd(&sacc[2], s2);
    }
    __syncthreads();
    if (tid < 3) atomicAdd(&g_stats[tid], sacc[tid]);
}

// ---------------- hebb: split-K tf32 GEMM, 4-stage pipeline ------------------
#define HPITCH 136
#define HSTAGES 4
#define HEBB_SMEM (HSTAGES * 2 * 16 * HPITCH * 4)

__global__ __launch_bounds__(256, 2)
void hebb_mma_kernel()
{
    extern __shared__ float dynsmem[];
    float (*Fs)[16][HPITCH] = (float(*)[16][HPITCH])dynsmem;
    float (*Xs)[16][HPITCH] = (float(*)[16][HPITCH])(dynsmem + HSTAGES * 16 * HPITCH);

    const int tid  = threadIdx.x;
    const int lane = tid & 31;
    const int warp = tid >> 5;
    const int wm   = warp >> 2;
    const int wn   = warp & 3;
    const int o0   = blockIdx.x * 128;
    const int d0   = blockIdx.y * 128;
    const int b0   = blockIdx.z * 2048;

    float acc[4][4][4];
#pragma unroll
    for (int mt = 0; mt < 4; ++mt)
#pragma unroll
        for (int nt = 0; nt < 4; ++nt)
#pragma unroll
            for (int i = 0; i < 4; ++i) acc[mt][nt][i] = 0.0f;

    const int r0 = tid >> 5,         c0 = tid & 31;
    const int r1 = (tid + 256) >> 5, c1 = tid & 31;

    const int KT = 2048 / 16;

#pragma unroll
    for (int s = 0; s < HSTAGES - 1; ++s) {
        const int bb = b0 + s * 16;
        cp16(&Fs[s][r0][c0 * 4], &g_sf[(size_t)(bb + r0) * 1024 + 512 + o0 + c0 * 4]);
        cp16(&Fs[s][r1][c1 * 4], &g_sf[(size_t)(bb + r1) * 1024 + 512 + o0 + c1 * 4]);
        cp16(&Xs[s][r0][c0 * 4], &g_buf[(size_t)(bb + r0) * DIN + d0 + c0 * 4]);
        cp16(&Xs[s][r1][c1 * 4], &g_buf[(size_t)(bb + r1) * DIN + d0 + c1 * 4]);
        cp_commit();
    }

    for (int kt = 0; kt < KT; ++kt) {
        cp_wait<HSTAGES - 2>();
        __syncthreads();

        if (kt + HSTAGES - 1 < KT) {
            const int st = (kt + HSTAGES - 1) & (HSTAGES - 1);
            const int bb = b0 + (kt + HSTAGES - 1) * 16;
            cp16(&Fs[st][r0][c0 * 4], &g_sf[(size_t)(bb + r0) * 1024 + 512 + o0 + c0 * 4]);
            cp16(&Fs[st][r1][c1 * 4], &g_sf[(size_t)(bb + r1) * 1024 + 512 + o0 + c1 * 4]);
            cp16(&Xs[st][r0][c0 * 4], &g_buf[(size_t)(bb + r0) * DIN + d0 + c0 * 4]);
            cp16(&Xs[st][r1][c1 * 4], &g_buf[(size_t)(bb + r1) * DIN + d0 + c1 * 4]);
        }
        cp_commit();

        const int cur = kt & (HSTAGES - 1);
#pragma unroll
        for (int ks = 0; ks < 2; ++ks) {
            const int kk = ks * 8 + (lane & 3);
            uint32_t af[4][4];
#pragma unroll
            for (int mt = 0; mt < 4; ++mt) {
                const int mr = wm * 64 + mt * 16 + (lane >> 2);
                af[mt][0] = f2tf32(Fs[cur][kk][mr]);
                af[mt][1] = f2tf32(Fs[cur][kk][mr + 8]);
                af[mt][2] = f2tf32(Fs[cur][kk + 4][mr]);
                af[mt][3] = f2tf32(Fs[cur][kk + 4][mr + 8]);
            }
            uint32_t bf[4][2];
#pragma unroll
            for (int nt = 0; nt < 4; ++nt) {
                const int nc = wn * 32 + nt * 8 + (lane >> 2);
                bf[nt][0] = __float_as_uint(Xs[cur][kk][nc]);
                bf[nt][1] = __float_as_uint(Xs[cur][kk + 4][nc]);
            }
#pragma unroll
            for (int mt = 0; mt < 4; ++mt)
#pragma unroll
                for (int nt = 0; nt < 4; ++nt)
                    mma_tf32(acc[mt][nt], af[mt], bf[nt]);
        }
    }

#pragma unroll
    for (int mt = 0; mt < 4; ++mt)
#pragma unroll
        for (int nt = 0; nt < 4; ++nt) {
            const int col = d0 + wn * 32 + nt * 8 + (lane & 3) * 2;
#pragma unroll
            for (int h = 0; h < 2; ++h) {
                const int row = o0 + wm * 64 + mt * 16 + (lane >> 2) + h * 8;
                atomicAdd(&g_hebb[row * DIN + col],     acc[mt][nt][h * 2 + 0]);
                atomicAdd(&g_hebb[row * DIN + col + 1], acc[mt][nt][h * 2 + 1]);
            }
        }
}

// ---------------- combine + swish-beta + layernorm ---------------------------
__global__ __launch_bounds__(128)
void finalize_kernel(const float* __restrict__ gamma,
                     const float* __restrict__ lbeta,
                     float* __restrict__ outp)
{
    const int b = blockIdx.x;
    const int tid = threadIdx.x;
    const float sens = g_gates[(size_t)b * 3 + 1];
    const float gate = g_gates[(size_t)b * 3 + 2];
    const float be = 0.5f + 2.0f * sens;

    const float* row = &g_sf[(size_t)b * 1024];

    float a[4];
    float s = 0.f, sq = 0.f;
#pragma unroll
    for (int i = 0; i < 4; ++i) {
        const int c = tid + i * 128;
        float cmb = row[c] + row[512 + c] * gate;
        float act = cmb * sigf(be * cmb);
        a[i] = act;
        s += act;
        sq = fmaf(act, act, sq);
    }

    __shared__ float sh[8];
#pragma unroll
    for (int o = 16; o > 0; o >>= 1) {
        s  += __shfl_down_sync(0xffffffffu, s,  o);
        sq += __shfl_down_sync(0xffffffffu, sq, o);
    }
    const int lane = tid & 31, warp = tid >> 5;
    if (lane == 0) { sh[warp] = s; sh[4 + warp] = sq; }
    __syncthreads();
    if (tid == 0) {
        sh[0] = sh[0] + sh[1] + sh[2] + sh[3];
        sh[4] = sh[4] + sh[5] + sh[6] + sh[7];
    }
    __syncthreads();
    const float mu  = sh[0] * (1.0f / DOUT);
    const float var = sh[4] * (1.0f / DOUT) - mu * mu;
    const float inv = rsqrtf(var + 1e-5f);
#pragma unroll
    for (int i = 0; i < 4; ++i) {
        const int c = tid + i * 128;
        outp[(size_t)b * DOUT + c] = (a[i] - mu) * inv * gamma[c] + lbeta[c];
    }
}

// ---------------- W_fast update + stats output -------------------------------
__global__ void wfast_kernel(const float* __restrict__ Wf,
                             float* __restrict__ out_wf,
                             float* __restrict__ out_st)
{
    const int o = blockIdx.x;
    const float rate = g_stats[0] * (0.1f / (float)BATCH);
    const float m2 = g_m2[o] * (1.0f / (float)BATCH);
    for (int d = threadIdx.x; d < DIN; d += blockDim.x) {
        const float wf = Wf[o * DIN + d];
        const float hebb = g_hebb[o * DIN + d] * (1.0f / (float)BATCH);
        out_wf[o * DIN + d] = wf + tanhf(hebb - m2 * wf) * rate;
    }
    if (o == 0 && threadIdx.x < 3)
        out_st[threadIdx.x] = g_stats[threadIdx.x] * (1.0f / (float)BATCH);
}

// ---------------- launch -----------------------------------------------------
extern "C" void kernel_launch(void* const* d_in, const int* in_sizes, int n_in,
                              void* d_out, int out_size)
{
    (void)in_sizes; (void)n_in; (void)out_size;

    const float* x      = (const float*)d_in[0];
    const int*   step   = (const int*)  d_in[1];
    const float* cms_w1 = (const float*)d_in[2];
    const float* cms_b1 = (const float*)d_in[3];
    const float* cms_w2 = (const float*)d_in[4];
    const float* cms_b2 = (const float*)d_in[5];
    const float* gmw    = (const float*)d_in[6];
    const float* gmb    = (const float*)d_in[7];
    const float* gsw    = (const float*)d_in[8];
    const float* gsb    = (const float*)d_in[9];
    const float* ggw    = (const float*)d_in[10];
    const float* ggb    = (const float*)d_in[11];
    const float* gow    = (const float*)d_in[12];
    const float* gob    = (const float*)d_in[13];
    const float* Wslow  = (const float*)d_in[14];
    const float* Wfast  = (const float*)d_in[15];
    const float* gamma  = (const float*)d_in[16];
    const float* lbeta  = (const float*)d_in[17];

    float* out    = (float*)d_out;
    float* out_ln = out;
    float* out_wf = out + (size_t)BATCH * DOUT;
    float* out_st = out_wf + DOUT * DIN;

    void* p;
    cudaGetSymbolAddress(&p, g_buf);   float* buf  = (float*)p;
    cudaGetSymbolAddress(&p, g_h);     float* hbuf = (float*)p;
    cudaGetSymbolAddress(&p, g_sf);    float* sf   = (float*)p;
    cudaGetSymbolAddress(&p, g_xr);    float* xr   = (float*)p;
    cudaGetSymbolAddress(&p, g_gb3);   float* gb3  = (float*)p;
    cudaGetSymbolAddress(&p, g_pre);   float* pre  = (float*)p;
    cudaGetSymbolAddress(&p, g_w1r);   float* w1r  = (float*)p;
    cudaGetSymbolAddress(&p, g_w2r);   float* w2r  = (float*)p;
    cudaGetSymbolAddress(&p, g_gsfw);  float* gsfw = (float*)p;

    static bool attr_done = false;
    if (!attr_done) {
        cudaFuncSetAttribute(mma_gemm<EPI_RELU , true >, cudaFuncAttributeMaxDynamicSharedMemorySize, GEMM_SMEM);
        cudaFuncSetAttribute(mma_gemm<EPI_RESID, true >, cudaFuncAttributeMaxDynamicSharedMemorySize, GEMM_SMEM);
        cudaFuncSetAttribute(mma_gemm<EPI_GSF  , false>, cudaFuncAttributeMaxDynamicSharedMemorySize, GEMM_SMEM);
        cudaFuncSetAttribute(hebb_mma_kernel,            cudaFuncAttributeMaxDynamicSharedMemorySize, HEBB_SMEM);
        attr_done = true;
    }

    const dim3 blk(128);
    const dim3 gh(HIDN / 128, BATCH / 128);        // N=1024
    const dim3 gd(DIN  / 128, BATCH / 128);        // N=512
    const dim3 ggsf(4096 / 128, BATCH / 128);      // N=4096 merged gates+slow+fast

    prep_kernel<<<2048, 256>>>(x, cms_w1, cms_w2, gmw, gsw, ggw, Wslow, Wfast,
                               gmb, gsb, ggb);

    // CMS level 0 (freq 1)
    mma_gemm<EPI_RELU , true ><<<gh, blk, GEMM_SMEM>>>(xr,   w1r, cms_b1, nullptr, hbuf, HIDN, DIN,  step, 1, nullptr, nullptr);
    mma_gemm<EPI_RESID, true ><<<gd, blk, GEMM_SMEM>>>(hbuf, w2r, cms_b2, x,       buf,  DIN,  HIDN, step, 1, nullptr, nullptr);
    // CMS level 1 (freq 4)
    mma_gemm<EPI_RELU , true ><<<gh, blk, GEMM_SMEM>>>(buf,  w1r + NGW,     cms_b1 + HIDN,     nullptr, hbuf, HIDN, DIN,  step, 4, nullptr, nullptr);
    mma_gemm<EPI_RESID, true ><<<gd, blk, GEMM_SMEM>>>(hbuf, w2r + NGW,     cms_b2 + DIN,      buf,     buf,  DIN,  HIDN, step, 4, nullptr, nullptr);
    // CMS level 2 (freq 16)
    mma_gemm<EPI_RELU , true ><<<gh, blk, GEMM_SMEM>>>(buf,  w1r + 2 * NGW, cms_b1 + 2 * HIDN, nullptr, hbuf, HIDN, DIN,  step, 16, nullptr, nullptr);
    mma_gemm<EPI_RESID, true ><<<gd, blk, GEMM_SMEM>>>(hbuf, w2r + 2 * NGW, cms_b2 + 2 * DIN,  buf,     buf,  DIN,  HIDN, step, 16, nullptr, nullptr);

    // merged GEMM: gates (sigmoid+proj->g_pre, +m2 fold) and slow|fast -> g_sf
    mma_gemm<EPI_GSF, false><<<ggsf, blk, GEMM_SMEM>>>(buf, gsfw, gb3, nullptr, sf, 1024, DIN, step, 1, gow, pre);

    gate_final_kernel<<<BATCH / 256, 256>>>(gob);

    hebb_mma_kernel<<<dim3(4, 4, 32), dim3(256), HEBB_SMEM>>>();

    finalize_kernel<<<BATCH, 128>>>(gamma, lbeta, out_ln);
    wfast_kernel<<<DOUT, 256>>>(Wfast, out_wf, out_st);
}

// round 14
// speedup vs baseline: 1.2767x; 1.0116x over previous
#include <cuda_runtime.h>
#include <math.h>
#include <stdint.h>

#define BATCH 65536
#define DIN   512
#define DOUT  512
#define HIDN  1024

// ---------------- scratch (static device globals; no allocation) -------------
__device__ float g_buf [(size_t)BATCH * DIN];
__device__ float g_h   [(size_t)BATCH * HIDN];     // cms hidden
__device__ float g_sf  [(size_t)BATCH * 1024];     // [slow | fast] per row
__device__ float g_gates[(size_t)BATCH * 3];
__device__ float g_pre [(size_t)BATCH * 3];        // gate pre-activations (atomic acc)
__device__ float g_hebb[DOUT * DIN];
__device__ float g_m2  [DOUT];
__device__ float g_stats[4];
__device__ float g_xr  [(size_t)BATCH * DIN];
__device__ float g_gb3 [3 * HIDN];                 // concat gate biases

// tf32-rounded weight copies
__device__ float g_w1r [3 * HIDN * DIN];
__device__ float g_w2r [3 * DIN * HIDN];
__device__ float g_gsfw[4096 * DIN];               // [gates 3072 | slow 512 | fast 512]

__device__ __forceinline__ float sigf(float x) { return 1.0f / (1.0f + expf(-x)); }

__device__ __forceinline__ uint32_t f2tf32(float x) {
    uint32_t r;
    asm("cvt.rna.tf32.f32 %0, %1;" : "=r"(r) : "f"(x));
    return r;
}
__device__ __forceinline__ float roundtf(float x) { return __uint_as_float(f2tf32(x)); }

__device__ __forceinline__ void mma_tf32(float* c, const uint32_t* a, const uint32_t* b) {
    asm volatile(
        "mma.sync.aligned.m16n8k8.row.col.f32.tf32.tf32.f32 "
        "{%0,%1,%2,%3}, {%4,%5,%6,%7}, {%8,%9}, {%0,%1,%2,%3};\n"
        : "+f"(c[0]), "+f"(c[1]), "+f"(c[2]), "+f"(c[3])
        : "r"(a[0]), "r"(a[1]), "r"(a[2]), "r"(a[3]), "r"(b[0]), "r"(b[1]));
}

__device__ __forceinline__ void cp16(void* smem, const void* g) {
    uint32_t s = (uint32_t)__cvta_generic_to_shared(smem);
    asm volatile("cp.async.cg.shared.global [%0], [%1], 16;\n" :: "r"(s), "l"(g));
}
__device__ __forceinline__ void cp_commit() { asm volatile("cp.async.commit_group;\n"); }
template <int N>
__device__ __forceinline__ void cp_wait() { asm volatile("cp.async.wait_group %0;\n" :: "n"(N)); }

// ---------------- prepass ----------------------------------------------------
#define NW1 (3 * HIDN * DIN)
#define NW2 (3 * DIN * HIDN)
#define NGW (HIDN * DIN)
#define NSF (DOUT * DIN)
#define NX  ((size_t)BATCH * DIN)

__global__ void prep_kernel(const float* __restrict__ x,
                            const float* __restrict__ w1, const float* __restrict__ w2,
                            const float* __restrict__ gm, const float* __restrict__ gs,
                            const float* __restrict__ gg, const float* __restrict__ ws,
                            const float* __restrict__ wf,
                            const float* __restrict__ gmb, const float* __restrict__ gsb,
                            const float* __restrict__ ggb)
{
    const size_t idx = blockIdx.x * blockDim.x + threadIdx.x;
    const size_t stride = (size_t)gridDim.x * blockDim.x;
    for (size_t i = idx; i < NX; i += stride) g_xr[i] = roundtf(x[i]);
    for (size_t i = idx; i < NW1; i += stride) g_w1r[i] = roundtf(w1[i]);
    for (size_t i = idx; i < NW2; i += stride) g_w2r[i] = roundtf(w2[i]);
    for (size_t i = idx; i < NGW; i += stride) {
        g_gsfw[i]           = roundtf(gm[i]);
        g_gsfw[i + NGW]     = roundtf(gs[i]);
        g_gsfw[i + 2 * NGW] = roundtf(gg[i]);
    }
    for (size_t i = idx; i < NSF; i += stride) {
        g_gsfw[3 * NGW + i]       = roundtf(ws[i]);
        g_gsfw[3 * NGW + NSF + i] = roundtf(wf[i]);
    }
    for (size_t i = idx; i < HIDN; i += stride) {
        g_gb3[i]            = gmb[i];
        g_gb3[i + HIDN]     = gsb[i];
        g_gb3[i + 2 * HIDN] = ggb[i];
    }
    for (size_t i = idx; i < DOUT * DIN; i += stride) g_hebb[i] = 0.0f;
    for (size_t i = idx; i < (size_t)BATCH * 3; i += stride) g_pre[i] = 0.0f;
    if (idx < DOUT) g_m2[idx] = 0.0f;
    if (idx < 4)    g_stats[idx] = 0.0f;
}

// ------ tf32 mma GEMM: 128x128 tile, 4 warps, warp tile 64x64, k-tile 32 -----
enum { EPI_RELU = 0, EPI_RESID = 1, EPI_GSF = 2, EPI_NONE = 4 };

#define SPITCH 36       // 32 k-floats + 4 pad (36 mod 32 = 4 -> conflict-free)
#define GSTAGES 2
#define GEMM_SMEM (GSTAGES * 2 * 128 * SPITCH * 4)   // 73728 bytes

template <int EPI, bool ROUND_OUT>
__global__ __launch_bounds__(128, 2)
void mma_gemm(const float* __restrict__ A, const float* __restrict__ W,
              const float* __restrict__ bias, const float* __restrict__ R,
              float* __restrict__ C, int N, int K,
              const int* __restrict__ step, int freq,
              const float* __restrict__ gw, float* __restrict__ gpre)
{
    if (freq > 1) { if ((step[0] % freq) != 0) return; }

    extern __shared__ float dynsmem[];
    float (*As)[128][SPITCH] = (float(*)[128][SPITCH])dynsmem;
    float (*Bs)[128][SPITCH] = (float(*)[128][SPITCH])(dynsmem + GSTAGES * 128 * SPITCH);

    const int tid  = threadIdx.x;
    const int lane = tid & 31;
    const int warp = tid >> 5;     // 0..3
    const int wm   = warp >> 1;    // 0..1 -> 64 rows
    const int wn   = warp & 1;     // 0..1 -> 64 cols
    const int m0   = blockIdx.y * 128;
    const int n0   = blockIdx.x * 128;

    float acc[4][8][4];
#pragma unroll
    for (int mt = 0; mt < 4; ++mt)
#pragma unroll
        for (int nt = 0; nt < 8; ++nt)
#pragma unroll
            for (int i = 0; i < 4; ++i) acc[mt][nt][i] = 0.0f;

    const int lr = tid >> 3;   // 0..15
    const int lc = tid & 7;    // chunk 0..7 (32 k-floats)

    const float* Ag = A + (size_t)(m0 + lr) * K + lc * 4;
    const float* Wg = W + (size_t)(n0 + lr) * K + lc * 4;

    const int KT = K >> 5;     // 32-deep k-tiles

    // prologue: tile 0 -> stage 0
#pragma unroll
    for (int rr = 0; rr < 8; ++rr) {
        cp16(&As[0][lr + rr * 16][lc * 4], Ag + (size_t)rr * 16 * K);
        cp16(&Bs[0][lr + rr * 16][lc * 4], Wg + (size_t)rr * 16 * K);
    }
    cp_commit();

    int cur = 0;
    for (int kt = 0; kt < KT; ++kt) {
        cp_wait<0>();
        __syncthreads();       // stage cur ready; other slot free (read at kt-1)

        if (kt + 1 < KT) {
            const int nxt = cur ^ 1;
            const size_t ko = (size_t)(kt + 1) * 32;
#pragma unroll
            for (int rr = 0; rr < 8; ++rr) {
                cp16(&As[nxt][lr + rr * 16][lc * 4], Ag + (size_t)rr * 16 * K + ko);
                cp16(&Bs[nxt][lr + rr * 16][lc * 4], Wg + (size_t)rr * 16 * K + ko);
            }
        }
        cp_commit();

#pragma unroll
        for (int ks = 0; ks < 4; ++ks) {
            const int kk = ks * 8 + (lane & 3);
            uint32_t af[4][4];
#pragma unroll
            for (int mt = 0; mt < 4; ++mt) {
                const int mr = wm * 64 + mt * 16 + (lane >> 2);
                af[mt][0] = __float_as_uint(As[cur][mr][kk]);
                af[mt][1] = __float_as_uint(As[cur][mr + 8][kk]);
                af[mt][2] = __float_as_uint(As[cur][mr][kk + 4]);
                af[mt][3] = __float_as_uint(As[cur][mr + 8][kk + 4]);
            }
            uint32_t bf[8][2];
#pragma unroll
            for (int nt = 0; nt < 8; ++nt) {
                const int nc = wn * 64 + nt * 8 + (lane >> 2);
                bf[nt][0] = __float_as_uint(Bs[cur][nc][kk]);
                bf[nt][1] = __float_as_uint(Bs[cur][nc][kk + 4]);
            }
#pragma unroll
            for (int mt = 0; mt < 4; ++mt)
#pragma unroll
                for (int nt = 0; nt < 8; ++nt)
                    mma_tf32(acc[mt][nt], af[mt], bf[nt]);
        }

        cur ^= 1;
    }

    // ---------------- epilogues ----------------
    if (EPI == EPI_GSF) {
        if (n0 < 3 * HIDN) {
            float pr[4][2][3];
#pragma unroll
            for (int mt = 0; mt < 4; ++mt)
#pragma unroll
                for (int h = 0; h < 2; ++h)
#pragma unroll
                    for (int j = 0; j < 3; ++j) pr[mt][h][j] = 0.0f;

#pragma unroll
            for (int nt = 0; nt < 8; ++nt) {
                const int col = n0 + wn * 64 + nt * 8 + (lane & 3) * 2;
                const int hh  = col & (HIDN - 1);
                const float bv0 = bias[col], bv1 = bias[col + 1];
                const float w0a = gw[hh],            w0b = gw[hh + 1];
                const float w1a = gw[HIDN + hh],     w1b = gw[HIDN + hh + 1];
                const float w2a = gw[2 * HIDN + hh], w2b = gw[2 * HIDN + hh + 1];
#pragma unroll
                for (int mt = 0; mt < 4; ++mt)
#pragma unroll
                    for (int h = 0; h < 2; ++h) {
                        const float v0 = sigf(acc[mt][nt][h * 2 + 0] + bv0);
                        const float v1 = sigf(acc[mt][nt][h * 2 + 1] + bv1);
                        pr[mt][h][0] += v0 * w0a + v1 * w0b;
                        pr[mt][h][1] += v0 * w1a + v1 * w1b;
                        pr[mt][h][2] += v0 * w2a + v1 * w2b;
                    }
            }
#pragma unroll
            for (int mt = 0; mt < 4; ++mt)
#pragma unroll
                for (int h = 0; h < 2; ++h)
#pragma unroll
                    for (int j = 0; j < 3; ++j) {
                        float v = pr[mt][h][j];
                        v += __shfl_xor_sync(0xffffffffu, v, 1);
                        v += __shfl_xor_sync(0xffffffffu, v, 2);
                        pr[mt][h][j] = v;
                    }
            if ((lane & 3) == 0) {
#pragma unroll
                for (int mt = 0; mt < 4; ++mt)
#pragma unroll
                    for (int h = 0; h < 2; ++h) {
                        const int row = m0 + wm * 64 + mt * 16 + (lane >> 2) + h * 8;
#pragma unroll
                        for (int j = 0; j < 3; ++j)
                            atomicAdd(&gpre[(size_t)row * 3 + j], pr[mt][h][j]);
                    }
            }
        } else {
            const bool isfast = (n0 >= 3 * HIDN + 512);
#pragma unroll
            for (int nt = 0; nt < 8; ++nt) {
                const int col = n0 + wn * 64 + nt * 8 + (lane & 3) * 2;
                const int csf = col - 3 * HIDN;      // 0..1023
                float s0 = 0.f, s1 = 0.f;
#pragma unroll
                for (int mt = 0; mt < 4; ++mt)
#pragma unroll
                    for (int h = 0; h < 2; ++h) {
                        const int row = m0 + wm * 64 + mt * 16 + (lane >> 2) + h * 8;
                        const float v0 = acc[mt][nt][h * 2 + 0];
                        const float v1 = acc[mt][nt][h * 2 + 1];
                        *(float2*)&C[(size_t)row * 1024 + csf] = make_float2(v0, v1);
                        s0 = fmaf(v0, v0, s0);
                        s1 = fmaf(v1, v1, s1);
                    }
                if (isfast) {
                    s0 += __shfl_xor_sync(0xffffffffu, s0, 4);
                    s0 += __shfl_xor_sync(0xffffffffu, s0, 8);
                    s0 += __shfl_xor_sync(0xffffffffu, s0, 16);
                    s1 += __shfl_xor_sync(0xffffffffu, s1, 4);
                    s1 += __shfl_xor_sync(0xffffffffu, s1, 8);
                    s1 += __shfl_xor_sync(0xffffffffu, s1, 16);
                    if ((lane >> 2) == 0) {
                        atomicAdd(&g_m2[csf - 512],     s0);
                        atomicAdd(&g_m2[csf - 512 + 1], s1);
                    }
                }
            }
        }
        return;
    }

#pragma unroll
    for (int mt = 0; mt < 4; ++mt) {
#pragma unroll
        for (int nt = 0; nt < 8; ++nt) {
            const int col = n0 + wn * 64 + nt * 8 + (lane & 3) * 2;
            float bv0 = 0.f, bv1 = 0.f;
            if (EPI != EPI_NONE) { bv0 = bias[col]; bv1 = bias[col + 1]; }
#pragma unroll
            for (int h = 0; h < 2; ++h) {
                const int row = m0 + wm * 64 + mt * 16 + (lane >> 2) + h * 8;
                const size_t idx = (size_t)row * N + col;
                float v0 = acc[mt][nt][h * 2 + 0] + bv0;
                float v1 = acc[mt][nt][h * 2 + 1] + bv1;
                if (EPI == EPI_RELU) {
                    v0 = v0 > 0.f ? v0 : 0.f;
                    v1 = v1 > 0.f ? v1 : 0.f;
                } else if (EPI == EPI_RESID) {
                    v0 += R[idx]; v1 += R[idx + 1];
                }
                if (ROUND_OUT) { v0 = roundtf(v0); v1 = roundtf(v1); }
                *(float2*)&C[idx] = make_float2(v0, v1);
            }
        }
    }
}

// ---------------- gate_final: bias + sigmoid + stats -------------------------
__global__ __launch_bounds__(256)
void gate_final_kernel(const float* __restrict__ gob)
{
    __shared__ float sacc[3];
    const int tid = threadIdx.x;
    if (tid < 3) sacc[tid] = 0.0f;
    __syncthreads();

    const size_t b = (size_t)blockIdx.x * 256 + tid;
    float s0 = sigf(g_pre[b * 3 + 0] + gob[0]);
    float s1 = sigf(g_pre[b * 3 + 1] + gob[1]);
    float s2 = sigf(g_pre[b * 3 + 2] + gob[2]);
    g_gates[b * 3 + 0] = s0;
    g_gates[b * 3 + 1] = s1;
    g_gates[b * 3 + 2] = s2;

#pragma unroll
    for (int o = 16; o > 0; o >>= 1) {
        s0 += __shfl_down_sync(0xffffffffu, s0, o);
        s1 += __shfl_down_sync(0xffffffffu, s1, o);
        s2 += __shfl_down_sync(0xffffffffu, s2, o);
    }
    if ((tid & 31) == 0) {
        atomicAdd(&sacc[0], s0);
        atomicAdd(&sacc[1], s1);
        atomicAdd(&sacc[2], s2);
    }
    __syncthreads();
    if (tid < 3) atomicAdd(&g_stats[tid], sacc[tid]);
}

// ---------- hebb: split-K tf32 GEMM, k-tile 32 rows, 2-stage pipeline --------
#define HPITCH 136
#define HEBB_SMEM (2 * 2 * 32 * HPITCH * 4)   // 69632 bytes

__global__ __launch_bounds__(256, 2)
void hebb_mma_kernel()
{
    extern __shared__ float dynsmem[];
    float (*Fs)[32][HPITCH] = (float(*)[32][HPITCH])dynsmem;
    float (*Xs)[32][HPITCH] = (float(*)[32][HPITCH])(dynsmem + 2 * 32 * HPITCH);

    const int tid  = threadIdx.x;
    const int lane = tid & 31;
    const int warp = tid >> 5;
    const int wm   = warp >> 2;
    const int wn   = warp & 3;
    const int o0   = blockIdx.x * 128;
    const int d0   = blockIdx.y * 128;
    const int b0   = blockIdx.z * 2048;

    float acc[4][4][4];
#pragma unroll
    for (int mt = 0; mt < 4; ++mt)
#pragma unroll
        for (int nt = 0; nt < 4; ++nt)
#pragma unroll
            for (int i = 0; i < 4; ++i) acc[mt][nt][i] = 0.0f;

    const int KT = 2048 / 32;

    // loader: 32 rows x 32 float4 per operand; thread handles 4 chunks each
    auto load_tile = [&](int kt, int st) {
#pragma unroll
        for (int j = 0; j < 4; ++j) {
            const int id = tid + j * 256;
            const int r = id >> 5, c = id & 31;
            const int bb = b0 + kt * 32 + r;
            cp16(&Fs[st][r][c * 4], &g_sf[(size_t)bb * 1024 + 512 + o0 + c * 4]);
            cp16(&Xs[st][r][c * 4], &g_buf[(size_t)bb * DIN + d0 + c * 4]);
        }
    };

    load_tile(0, 0);
    cp_commit();

    int cur = 0;
    for (int kt = 0; kt < KT; ++kt) {
        cp_wait<0>();
        __syncthreads();

        if (kt + 1 < KT) load_tile(kt + 1, cur ^ 1);
        cp_commit();

#pragma unroll
        for (int ks = 0; ks < 4; ++ks) {
            const int kk = ks * 8 + (lane & 3);
            uint32_t af[4][4];
#pragma unroll
            for (int mt = 0; mt < 4; ++mt) {
                const int mr = wm * 64 + mt * 16 + (lane >> 2);
                af[mt][0] = f2tf32(Fs[cur][kk][mr]);
                af[mt][1] = f2tf32(Fs[cur][kk][mr + 8]);
                af[mt][2] = f2tf32(Fs[cur][kk + 4][mr]);
                af[mt][3] = f2tf32(Fs[cur][kk + 4][mr + 8]);
            }
            uint32_t bf[4][2];
#pragma unroll
            for (int nt = 0; nt < 4; ++nt) {
                const int nc = wn * 32 + nt * 8 + (lane >> 2);
                bf[nt][0] = __float_as_uint(Xs[cur][kk][nc]);
                bf[nt][1] = __float_as_uint(Xs[cur][kk + 4][nc]);
            }
#pragma unroll
            for (int mt = 0; mt < 4; ++mt)
#pragma unroll
                for (int nt = 0; nt < 4; ++nt)
                    mma_tf32(acc[mt][nt], af[mt], bf[nt]);
        }

        cur ^= 1;
    }

#pragma unroll
    for (int mt = 0; mt < 4; ++mt)
#pragma unroll
        for (int nt = 0; nt < 4; ++nt) {
            const int col = d0 + wn * 32 + nt * 8 + (lane & 3) * 2;
#pragma unroll
            for (int h = 0; h < 2; ++h) {
                const int row = o0 + wm * 64 + mt * 16 + (lane >> 2) + h * 8;
                atomicAdd(&g_hebb[row * DIN + col],     acc[mt][nt][h * 2 + 0]);
                atomicAdd(&g_hebb[row * DIN + col + 1], acc[mt][nt][h * 2 + 1]);
            }
        }
}

// ---------------- combine + swish-beta + layernorm ---------------------------
__global__ __launch_bounds__(128)
void finalize_kernel(const float* __restrict__ gamma,
                     const float* __restrict__ lbeta,
                     float* __restrict__ outp)
{
    const int b = blockIdx.x;
    const int tid = threadIdx.x;
    const float sens = g_gates[(size_t)b * 3 + 1];
    const float gate = g_gates[(size_t)b * 3 + 2];
    const float be = 0.5f + 2.0f * sens;

    const float* row = &g_sf[(size_t)b * 1024];

    float a[4];
    float s = 0.f, sq = 0.f;
#pragma unroll
    for (int i = 0; i < 4; ++i) {
        const int c = tid + i * 128;
        float cmb = row[c] + row[512 + c] * gate;
        float act = cmb * sigf(be * cmb);
        a[i] = act;
        s += act;
        sq = fmaf(act, act, sq);
    }

    __shared__ float sh[8];
#pragma unroll
    for (int o = 16; o > 0; o >>= 1) {
        s  += __shfl_down_sync(0xffffffffu, s,  o);
        sq += __shfl_down_sync(0xffffffffu, sq, o);
    }
    const int lane = tid & 31, warp = tid >> 5;
    if (lane == 0) { sh[warp] = s; sh[4 + warp] = sq; }
    __syncthreads();
    if (tid == 0) {
        sh[0] = sh[0] + sh[1] + sh[2] + sh[3];
        sh[4] = sh[4] + sh[5] + sh[6] + sh[7];
    }
    __syncthreads();
    const float mu  = sh[0] * (1.0f / DOUT);
    const float var = sh[4] * (1.0f / DOUT) - mu * mu;
    const float inv = rsqrtf(var + 1e-5f);
#pragma unroll
    for (int i = 0; i < 4; ++i) {
        const int c = tid + i * 128;
        outp[(size_t)b * DOUT + c] = (a[i] - mu) * inv * gamma[c] + lbeta[c];
    }
}

// ---------------- W_fast update + stats output -------------------------------
__global__ void wfast_kernel(const float* __restrict__ Wf,
                             float* __restrict__ out_wf,
                             float* __restrict__ out_st)
{
    const int o = blockIdx.x;
    const float rate = g_stats[0] * (0.1f / (float)BATCH);
    const float m2 = g_m2[o] * (1.0f / (float)BATCH);
    for (int d = threadIdx.x; d < DIN; d += blockDim.x) {
        const float wf = Wf[o * DIN + d];
        const float hebb = g_hebb[o * DIN + d] * (1.0f / (float)BATCH);
        out_wf[o * DIN + d] = wf + tanhf(hebb - m2 * wf) * rate;
    }
    if (o == 0 && threadIdx.x < 3)
        out_st[threadIdx.x] = g_stats[threadIdx.x] * (1.0f / (float)BATCH);
}

// ---------------- launch -----------------------------------------------------
extern "C" void kernel_launch(void* const* d_in, const int* in_sizes, int n_in,
                              void* d_out, int out_size)
{
    (void)in_sizes; (void)n_in; (void)out_size;

    const float* x      = (const float*)d_in[0];
    const int*   step   = (const int*)  d_in[1];
    const float* cms_w1 = (const float*)d_in[2];
    const float* cms_b1 = (const float*)d_in[3];
    const float* cms_w2 = (const float*)d_in[4];
    const float* cms_b2 = (const float*)d_in[5];
    const float* gmw    = (const float*)d_in[6];
    const float* gmb    = (const float*)d_in[7];
    const float* gsw    = (const float*)d_in[8];
    const float* gsb    = (const float*)d_in[9];
    const float* ggw    = (const float*)d_in[10];
    const float* ggb    = (const float*)d_in[11];
    const float* gow    = (const float*)d_in[12];
    const float* gob    = (const float*)d_in[13];
    const float* Wslow  = (const float*)d_in[14];
    const float* Wfast  = (const float*)d_in[15];
    const float* gamma  = (const float*)d_in[16];
    const float* lbeta  = (const float*)d_in[17];

    float* out    = (float*)d_out;
    float* out_ln = out;
    float* out_wf = out + (size_t)BATCH * DOUT;
    float* out_st = out_wf + DOUT * DIN;

    void* p;
    cudaGetSymbolAddress(&p, g_buf);   float* buf  = (float*)p;
    cudaGetSymbolAddress(&p, g_h);     float* hbuf = (float*)p;
    cudaGetSymbolAddress(&p, g_sf);    float* sf   = (float*)p;
    cudaGetSymbolAddress(&p, g_xr);    float* xr   = (float*)p;
    cudaGetSymbolAddress(&p, g_gb3);   float* gb3  = (float*)p;
    cudaGetSymbolAddress(&p, g_pre);   float* pre  = (float*)p;
    cudaGetSymbolAddress(&p, g_w1r);   float* w1r  = (float*)p;
    cudaGetSymbolAddress(&p, g_w2r);   float* w2r  = (float*)p;
    cudaGetSymbolAddress(&p, g_gsfw);  float* gsfw = (float*)p;

    static cudaStream_t s2 = nullptr;
    static cudaEvent_t  e1 = nullptr, e2 = nullptr;
    static bool attr_done = false;
    if (!attr_done) {
        cudaFuncSetAttribute(mma_gemm<EPI_RELU , true >, cudaFuncAttributeMaxDynamicSharedMemorySize, GEMM_SMEM);
        cudaFuncSetAttribute(mma_gemm<EPI_RESID, true >, cudaFuncAttributeMaxDynamicSharedMemorySize, GEMM_SMEM);
        cudaFuncSetAttribute(mma_gemm<EPI_GSF  , false>, cudaFuncAttributeMaxDynamicSharedMemorySize, GEMM_SMEM);
        cudaFuncSetAttribute(hebb_mma_kernel,            cudaFuncAttributeMaxDynamicSharedMemorySize, HEBB_SMEM);
        cudaStreamCreateWithFlags(&s2, cudaStreamNonBlocking);
        cudaEventCreateWithFlags(&e1, cudaEventDisableTiming);
        cudaEventCreateWithFlags(&e2, cudaEventDisableTiming);
        attr_done = true;
    }

    const dim3 blk(128);
    const dim3 gh(HIDN / 128, BATCH / 128);        // N=1024
    const dim3 gd(DIN  / 128, BATCH / 128);        // N=512
    const dim3 ggsf(4096 / 128, BATCH / 128);      // N=4096 merged gates+slow+fast

    prep_kernel<<<2048, 256>>>(x, cms_w1, cms_w2, gmw, gsw, ggw, Wslow, Wfast,
                               gmb, gsb, ggb);

    // CMS level 0 (freq 1)
    mma_gemm<EPI_RELU , true ><<<gh, blk, GEMM_SMEM>>>(xr,   w1r, cms_b1, nullptr, hbuf, HIDN, DIN,  step, 1, nullptr, nullptr);
    mma_gemm<EPI_RESID, true ><<<gd, blk, GEMM_SMEM>>>(hbuf, w2r, cms_b2, x,       buf,  DIN,  HIDN, step, 1, nullptr, nullptr);
    // CMS level 1 (freq 4)
    mma_gemm<EPI_RELU , true ><<<gh, blk, GEMM_SMEM>>>(buf,  w1r + NGW,     cms_b1 + HIDN,     nullptr, hbuf, HIDN, DIN,  step, 4, nullptr, nullptr);
    mma_gemm<EPI_RESID, true ><<<gd, blk, GEMM_SMEM>>>(hbuf, w2r + NGW,     cms_b2 + DIN,      buf,     buf,  DIN,  HIDN, step, 4, nullptr, nullptr);
    // CMS level 2 (freq 16)
    mma_gemm<EPI_RELU , true ><<<gh, blk, GEMM_SMEM>>>(buf,  w1r + 2 * NGW, cms_b1 + 2 * HIDN, nullptr, hbuf, HIDN, DIN,  step, 16, nullptr, nullptr);
    mma_gemm<EPI_RESID, true ><<<gd, blk, GEMM_SMEM>>>(hbuf, w2r + 2 * NGW, cms_b2 + 2 * DIN,  buf,     buf,  DIN,  HIDN, step, 16, nullptr, nullptr);

    // merged GEMM: gates (sigmoid+proj->g_pre, +m2 fold) and slow|fast -> g_sf
    mma_gemm<EPI_GSF, false><<<ggsf, blk, GEMM_SMEM>>>(buf, gsfw, gb3, nullptr, sf, 1024, DIN, step, 1, gow, pre);

    // fork: hebb on s2 runs concurrently with gate_final + finalize on main
    cudaEventRecord(e1, 0);
    cudaStreamWaitEvent(s2, e1, 0);
    hebb_mma_kernel<<<dim3(4, 4, 32), dim3(256), HEBB_SMEM, s2>>>();
    cudaEventRecord(e2, s2);

    gate_final_kernel<<<BATCH / 256, 256>>>(gob);
    finalize_kernel<<<BATCH, 128>>>(gamma, lbeta, out_ln);

    // join: wfast needs hebb + m2 + stats
    cudaStreamWaitEvent(0, e2, 0);
    wfast_kernel<<<DOUT, 256>>>(Wfast, out_wf, out_st);
}

// round 15
// speedup vs baseline: 1.3520x; 1.0590x over previous
#include <cuda_runtime.h>
#include <math.h>
#include <stdint.h>

#define BATCH 65536
#define DIN   512
#define DOUT  512
#define HIDN  1024

// ---------------- scratch (static device globals; no allocation) -------------
__device__ float g_buf [(size_t)BATCH * DIN];
__device__ float g_h   [(size_t)BATCH * HIDN];     // cms hidden
__device__ float g_sf  [(size_t)BATCH * 1024];     // [slow | fast] per row
__device__ float g_gates[(size_t)BATCH * 3];
__device__ float g_pre [(size_t)BATCH * 3];        // gate pre-activations (atomic acc)
__device__ float g_hebb[DOUT * DIN];
__device__ float g_m2  [DOUT];
__device__ float g_stats[4];
__device__ float g_xr  [(size_t)BATCH * DIN];
__device__ float g_gb3 [3 * HIDN];                 // concat gate biases

// tf32-rounded weight copies
__device__ float g_w1r [3 * HIDN * DIN];
__device__ float g_w2r [3 * DIN * HIDN];
__device__ float g_gsfw[4096 * DIN];               // [gates 3072 | slow 512 | fast 512]

__device__ __forceinline__ float sigf(float x) { return 1.0f / (1.0f + expf(-x)); }

__device__ __forceinline__ uint32_t f2tf32(float x) {
    uint32_t r;
    asm("cvt.rna.tf32.f32 %0, %1;" : "=r"(r) : "f"(x));
    return r;
}
__device__ __forceinline__ float roundtf(float x) { return __uint_as_float(f2tf32(x)); }

__device__ __forceinline__ void mma_tf32(float* c, const uint32_t* a, const uint32_t* b) {
    asm volatile(
        "mma.sync.aligned.m16n8k8.row.col.f32.tf32.tf32.f32 "
        "{%0,%1,%2,%3}, {%4,%5,%6,%7}, {%8,%9}, {%0,%1,%2,%3};\n"
        : "+f"(c[0]), "+f"(c[1]), "+f"(c[2]), "+f"(c[3])
        : "r"(a[0]), "r"(a[1]), "r"(a[2]), "r"(a[3]), "r"(b[0]), "r"(b[1]));
}

__device__ __forceinline__ void ldsm_x4(uint32_t& r0, uint32_t& r1, uint32_t& r2,
                                        uint32_t& r3, const void* p) {
    uint32_t a = (uint32_t)__cvta_generic_to_shared(p);
    asm volatile("ldmatrix.sync.aligned.m8n8.x4.shared.b16 {%0,%1,%2,%3}, [%4];"
        : "=r"(r0), "=r"(r1), "=r"(r2), "=r"(r3) : "r"(a));
}

__device__ __forceinline__ void cp16(void* smem, const void* g) {
    uint32_t s = (uint32_t)__cvta_generic_to_shared(smem);
    asm volatile("cp.async.cg.shared.global [%0], [%1], 16;\n" :: "r"(s), "l"(g));
}
__device__ __forceinline__ void cp_commit() { asm volatile("cp.async.commit_group;\n"); }
template <int N>
__device__ __forceinline__ void cp_wait() { asm volatile("cp.async.wait_group %0;\n" :: "n"(N)); }

// ---------------- prepass ----------------------------------------------------
#define NW1 (3 * HIDN * DIN)
#define NW2 (3 * DIN * HIDN)
#define NGW (HIDN * DIN)
#define NSF (DOUT * DIN)
#define NX  ((size_t)BATCH * DIN)

__global__ void prep_kernel(const float* __restrict__ x,
                            const float* __restrict__ w1, const float* __restrict__ w2,
                            const float* __restrict__ gm, const float* __restrict__ gs,
                            const float* __restrict__ gg, const float* __restrict__ ws,
                            const float* __restrict__ wf,
                            const float* __restrict__ gmb, const float* __restrict__ gsb,
                            const float* __restrict__ ggb)
{
    const size_t idx = blockIdx.x * blockDim.x + threadIdx.x;
    const size_t stride = (size_t)gridDim.x * blockDim.x;
    for (size_t i = idx; i < NX; i += stride) g_xr[i] = roundtf(x[i]);
    for (size_t i = idx; i < NW1; i += stride) g_w1r[i] = roundtf(w1[i]);
    for (size_t i = idx; i < NW2; i += stride) g_w2r[i] = roundtf(w2[i]);
    for (size_t i = idx; i < NGW; i += stride) {
        g_gsfw[i]           = roundtf(gm[i]);
        g_gsfw[i + NGW]     = roundtf(gs[i]);
        g_gsfw[i + 2 * NGW] = roundtf(gg[i]);
    }
    for (size_t i = idx; i < NSF; i += stride) {
        g_gsfw[3 * NGW + i]       = roundtf(ws[i]);
        g_gsfw[3 * NGW + NSF + i] = roundtf(wf[i]);
    }
    for (size_t i = idx; i < HIDN; i += stride) {
        g_gb3[i]            = gmb[i];
        g_gb3[i + HIDN]     = gsb[i];
        g_gb3[i + 2 * HIDN] = ggb[i];
    }
    for (size_t i = idx; i < DOUT * DIN; i += stride) g_hebb[i] = 0.0f;
    for (size_t i = idx; i < (size_t)BATCH * 3; i += stride) g_pre[i] = 0.0f;
    if (idx < DOUT) g_m2[idx] = 0.0f;
    if (idx < 4)    g_stats[idx] = 0.0f;
}

// ------ tf32 mma GEMM: 128x128 tile, 4 warps, warp tile 64x64, k-tile 32 -----
enum { EPI_RELU = 0, EPI_RESID = 1, EPI_GSF = 2, EPI_NONE = 4 };

#define SPITCH 36       // 32 k-floats + 4 pad (36 mod 32 = 4 -> conflict-free)
#define GSTAGES 2
#define GEMM_SMEM (GSTAGES * 2 * 128 * SPITCH * 4)   // 73728 bytes

template <int EPI, bool ROUND_OUT>
__global__ __launch_bounds__(128, 2)
void mma_gemm(const float* __restrict__ A, const float* __restrict__ W,
              const float* __restrict__ bias, const float* __restrict__ R,
              float* __restrict__ C, int N, int K,
              const int* __restrict__ step, int freq,
              const float* __restrict__ gw, float* __restrict__ gpre)
{
    if (freq > 1) { if ((step[0] % freq) != 0) return; }

    extern __shared__ float dynsmem[];
    float (*As)[128][SPITCH] = (float(*)[128][SPITCH])dynsmem;
    float (*Bs)[128][SPITCH] = (float(*)[128][SPITCH])(dynsmem + GSTAGES * 128 * SPITCH);

    const int tid  = threadIdx.x;
    const int lane = tid & 31;
    const int warp = tid >> 5;     // 0..3
    const int wm   = warp >> 1;    // 0..1 -> 64 rows
    const int wn   = warp & 1;     // 0..1 -> 64 cols
    const int m0   = blockIdx.y * 128;
    const int n0   = blockIdx.x * 128;

    float acc[4][8][4];
#pragma unroll
    for (int mt = 0; mt < 4; ++mt)
#pragma unroll
        for (int nt = 0; nt < 8; ++nt)
#pragma unroll
            for (int i = 0; i < 4; ++i) acc[mt][nt][i] = 0.0f;

    const int lr = tid >> 3;   // 0..15
    const int lc = tid & 7;    // chunk 0..7 (32 k-floats)

    const float* Ag = A + (size_t)(m0 + lr) * K + lc * 4;
    const float* Wg = W + (size_t)(n0 + lr) * K + lc * 4;

    const int KT = K >> 5;     // 32-deep k-tiles

    // ldmatrix per-thread offsets (relative row/col within tile & k-slice):
    // A x4: matrices = quadrants (rows 0-7 / 8-15) x (cols 0-3 / 4-7)
    const int a_row = wm * 64 + (lane & 15);
    const int a_col = (lane >> 4) << 2;
    // B x4 over an nt-pair: q0=(rows 0-7,c0) q1=(rows0-7,c4) q2=(rows8-15,c0) q3=(rows8-15,c4)
    const int b_row = wn * 64 + ((lane >> 4) << 3) + (lane & 7);
    const int b_col = ((lane >> 3) & 1) << 2;

    // prologue: tile 0 -> stage 0
#pragma unroll
    for (int rr = 0; rr < 8; ++rr) {
        cp16(&As[0][lr + rr * 16][lc * 4], Ag + (size_t)rr * 16 * K);
        cp16(&Bs[0][lr + rr * 16][lc * 4], Wg + (size_t)rr * 16 * K);
    }
    cp_commit();

    int cur = 0;
    for (int kt = 0; kt < KT; ++kt) {
        cp_wait<0>();
        __syncthreads();       // stage cur ready; other slot free (read at kt-1)

        if (kt + 1 < KT) {
            const int nxt = cur ^ 1;
            const size_t ko = (size_t)(kt + 1) * 32;
#pragma unroll
            for (int rr = 0; rr < 8; ++rr) {
                cp16(&As[nxt][lr + rr * 16][lc * 4], Ag + (size_t)rr * 16 * K + ko);
                cp16(&Bs[nxt][lr + rr * 16][lc * 4], Wg + (size_t)rr * 16 * K + ko);
            }
        }
        cp_commit();

#pragma unroll
        for (int ks = 0; ks < 4; ++ks) {
            const int kkb = ks * 8;
            uint32_t af[4][4];
#pragma unroll
            for (int mt = 0; mt < 4; ++mt)
                ldsm_x4(af[mt][0], af[mt][1], af[mt][2], af[mt][3],
                        &As[cur][a_row + mt * 16][kkb + a_col]);
            uint32_t bf[8][2];
#pragma unroll
            for (int np = 0; np < 4; ++np)
                ldsm_x4(bf[np * 2][0], bf[np * 2][1], bf[np * 2 + 1][0], bf[np * 2 + 1][1],
                        &Bs[cur][b_row + np * 16][kkb + b_col]);
#pragma unroll
            for (int mt = 0; mt < 4; ++mt)
#pragma unroll
                for (int nt = 0; nt < 8; ++nt)
                    mma_tf32(acc[mt][nt], af[mt], bf[nt]);
        }

        cur ^= 1;
    }

    // ---------------- epilogues ----------------
    if (EPI == EPI_GSF) {
        if (n0 < 3 * HIDN) {
            float pr[4][2][3];
#pragma unroll
            for (int mt = 0; mt < 4; ++mt)
#pragma unroll
                for (int h = 0; h < 2; ++h)
#pragma unroll
                    for (int j = 0; j < 3; ++j) pr[mt][h][j] = 0.0f;

#pragma unroll
            for (int nt = 0; nt < 8; ++nt) {
                const int col = n0 + wn * 64 + nt * 8 + (lane & 3) * 2;
                const int hh  = col & (HIDN - 1);
                const float bv0 = bias[col], bv1 = bias[col + 1];
                const float w0a = gw[hh],            w0b = gw[hh + 1];
                const float w1a = gw[HIDN + hh],     w1b = gw[HIDN + hh + 1];
                const float w2a = gw[2 * HIDN + hh], w2b = gw[2 * HIDN + hh + 1];
#pragma unroll
                for (int mt = 0; mt < 4; ++mt)
#pragma unroll
                    for (int h = 0; h < 2; ++h) {
                        const float v0 = sigf(acc[mt][nt][h * 2 + 0] + bv0);
                        const float v1 = sigf(acc[mt][nt][h * 2 + 1] + bv1);
                        pr[mt][h][0] += v0 * w0a + v1 * w0b;
                        pr[mt][h][1] += v0 * w1a + v1 * w1b;
                        pr[mt][h][2] += v0 * w2a + v1 * w2b;
                    }
            }
#pragma unroll
            for (int mt = 0; mt < 4; ++mt)
#pragma unroll
                for (int h = 0; h < 2; ++h)
#pragma unroll
                    for (int j = 0; j < 3; ++j) {
                        float v = pr[mt][h][j];
                        v += __shfl_xor_sync(0xffffffffu, v, 1);
                        v += __shfl_xor_sync(0xffffffffu, v, 2);
                        pr[mt][h][j] = v;
                    }
            if ((lane & 3) == 0) {
#pragma unroll
                for (int mt = 0; mt < 4; ++mt)
#pragma unroll
                    for (int h = 0; h < 2; ++h) {
                        const int row = m0 + wm * 64 + mt * 16 + (lane >> 2) + h * 8;
#pragma unroll
                        for (int j = 0; j < 3; ++j)
                            atomicAdd(&gpre[(size_t)row * 3 + j], pr[mt][h][j]);
                    }
            }
        } else {
            const bool isfast = (n0 >= 3 * HIDN + 512);
#pragma unroll
            for (int nt = 0; nt < 8; ++nt) {
                const int col = n0 + wn * 64 + nt * 8 + (lane & 3) * 2;
                const int csf = col - 3 * HIDN;      // 0..1023
                float s0 = 0.f, s1 = 0.f;
#pragma unroll
                for (int mt = 0; mt < 4; ++mt)
#pragma unroll
                    for (int h = 0; h < 2; ++h) {
                        const int row = m0 + wm * 64 + mt * 16 + (lane >> 2) + h * 8;
                        const float v0 = acc[mt][nt][h * 2 + 0];
                        const float v1 = acc[mt][nt][h * 2 + 1];
                        *(float2*)&C[(size_t)row * 1024 + csf] = make_float2(v0, v1);
                        s0 = fmaf(v0, v0, s0);
                        s1 = fmaf(v1, v1, s1);
                    }
                if (isfast) {
                    s0 += __shfl_xor_sync(0xffffffffu, s0, 4);
                    s0 += __shfl_xor_sync(0xffffffffu, s0, 8);
                    s0 += __shfl_xor_sync(0xffffffffu, s0, 16);
                    s1 += __shfl_xor_sync(0xffffffffu, s1, 4);
                    s1 += __shfl_xor_sync(0xffffffffu, s1, 8);
                    s1 += __shfl_xor_sync(0xffffffffu, s1, 16);
                    if ((lane >> 2) == 0) {
                        atomicAdd(&g_m2[csf - 512],     s0);
                        atomicAdd(&g_m2[csf - 512 + 1], s1);
                    }
                }
            }
        }
        return;
    }

#pragma unroll
    for (int mt = 0; mt < 4; ++mt) {
#pragma unroll
        for (int nt = 0; nt < 8; ++nt) {
            const int col = n0 + wn * 64 + nt * 8 + (lane & 3) * 2;
            float bv0 = 0.f, bv1 = 0.f;
            if (EPI != EPI_NONE) { bv0 = bias[col]; bv1 = bias[col + 1]; }
#pragma unroll
            for (int h = 0; h < 2; ++h) {
                const int row = m0 + wm * 64 + mt * 16 + (lane >> 2) + h * 8;
                const size_t idx = (size_t)row * N + col;
                float v0 = acc[mt][nt][h * 2 + 0] + bv0;
                float v1 = acc[mt][nt][h * 2 + 1] + bv1;
                if (EPI == EPI_RELU) {
                    v0 = v0 > 0.f ? v0 : 0.f;
                    v1 = v1 > 0.f ? v1 : 0.f;
                } else if (EPI == EPI_RESID) {
                    v0 += R[idx]; v1 += R[idx + 1];
                }
                if (ROUND_OUT) { v0 = roundtf(v0); v1 = roundtf(v1); }
                *(float2*)&C[idx] = make_float2(v0, v1);
            }
        }
    }
}

// ---------------- gate_final: bias + sigmoid + stats -------------------------
__global__ __launch_bounds__(256)
void gate_final_kernel(const float* __restrict__ gob)
{
    __shared__ float sacc[3];
    const int tid = threadIdx.x;
    if (tid < 3) sacc[tid] = 0.0f;
    __syncthreads();

    const size_t b = (size_t)blockIdx.x * 256 + tid;
    float s0 = sigf(g_pre[b * 3 + 0] + gob[0]);
    float s1 = sigf(g_pre[b * 3 + 1] + gob[1]);
    float s2 = sigf(g_pre[b * 3 + 2] + gob[2]);
    g_gates[b * 3 + 0] = s0;
    g_gates[b * 3 + 1] = s1;
    g_gates[b * 3 + 2] = s2;

#pragma unroll
    for (int o = 16; o > 0; o >>= 1) {
        s0 += __shfl_down_sync(0xffffffffu, s0, o);
        s1 += __shfl_down_sync(0xffffffffu, s1, o);
        s2 += __shfl_down_sync(0xffffffffu, s2, o);
    }
    if ((tid & 31) == 0) {
        atomicAdd(&sacc[0], s0);
        atomicAdd(&sacc[1], s1);
        atomicAdd(&sacc[2], s2);
    }
    __syncthreads();
    if (tid < 3) atomicAdd(&g_stats[tid], sacc[tid]);
}

// ---------- hebb: split-K tf32 GEMM, k-tile 32 rows, 2-stage pipeline --------
#define HPITCH 136
#define HEBB_SMEM (2 * 2 * 32 * HPITCH * 4)   // 69632 bytes

__global__ __launch_bounds__(256, 2)
void hebb_mma_kernel()
{
    extern __shared__ float dynsmem[];
    float (*Fs)[32][HPITCH] = (float(*)[32][HPITCH])dynsmem;
    float (*Xs)[32][HPITCH] = (float(*)[32][HPITCH])(dynsmem + 2 * 32 * HPITCH);

    const int tid  = threadIdx.x;
    const int lane = tid & 31;
    const int warp = tid >> 5;
    const int wm   = warp >> 2;
    const int wn   = warp & 3;
    const int o0   = blockIdx.x * 128;
    const int d0   = blockIdx.y * 128;
    const int b0   = blockIdx.z * 2048;

    float acc[4][4][4];
#pragma unroll
    for (int mt = 0; mt < 4; ++mt)
#pragma unroll
        for (int nt = 0; nt < 4; ++nt)
#pragma unroll
            for (int i = 0; i < 4; ++i) acc[mt][nt][i] = 0.0f;

    const int KT = 2048 / 32;

    auto load_tile = [&](int kt, int st) {
#pragma unroll
        for (int j = 0; j < 4; ++j) {
            const int id = tid + j * 256;
            const int r = id >> 5, c = id & 31;
            const int bb = b0 + kt * 32 + r;
            cp16(&Fs[st][r][c * 4], &g_sf[(size_t)bb * 1024 + 512 + o0 + c * 4]);
            cp16(&Xs[st][r][c * 4], &g_buf[(size_t)bb * DIN + d0 + c * 4]);
        }
    };

    load_tile(0, 0);
    cp_commit();

    int cur = 0;
    for (int kt = 0; kt < KT; ++kt) {
        cp_wait<0>();
        __syncthreads();

        if (kt + 1 < KT) load_tile(kt + 1, cur ^ 1);
        cp_commit();

#pragma unroll
        for (int ks = 0; ks < 4; ++ks) {
            const int kk = ks * 8 + (lane & 3);
            uint32_t af[4][4];
#pragma unroll
            for (int mt = 0; mt < 4; ++mt) {
                const int mr = wm * 64 + mt * 16 + (lane >> 2);
                af[mt][0] = f2tf32(Fs[cur][kk][mr]);
                af[mt][1] = f2tf32(Fs[cur][kk][mr + 8]);
                af[mt][2] = f2tf32(Fs[cur][kk + 4][mr]);
                af[mt][3] = f2tf32(Fs[cur][kk + 4][mr + 8]);
            }
            uint32_t bf[4][2];
#pragma unroll
            for (int nt = 0; nt < 4; ++nt) {
                const int nc = wn * 32 + nt * 8 + (lane >> 2);
                bf[nt][0] = __float_as_uint(Xs[cur][kk][nc]);
                bf[nt][1] = __float_as_uint(Xs[cur][kk + 4][nc]);
            }
#pragma unroll
            for (int mt = 0; mt < 4; ++mt)
#pragma unroll
                for (int nt = 0; nt < 4; ++nt)
                    mma_tf32(acc[mt][nt], af[mt], bf[nt]);
        }

        cur ^= 1;
    }

#pragma unroll
    for (int mt = 0; mt < 4; ++mt)
#pragma unroll
        for (int nt = 0; nt < 4; ++nt) {
            const int col = d0 + wn * 32 + nt * 8 + (lane & 3) * 2;
#pragma unroll
            for (int h = 0; h < 2; ++h) {
                const int row = o0 + wm * 64 + mt * 16 + (lane >> 2) + h * 8;
                atomicAdd(&g_hebb[row * DIN + col],     acc[mt][nt][h * 2 + 0]);
                atomicAdd(&g_hebb[row * DIN + col + 1], acc[mt][nt][h * 2 + 1]);
            }
        }
}

// ---------------- combine + swish-beta + layernorm ---------------------------
__global__ __launch_bounds__(128)
void finalize_kernel(const float* __restrict__ gamma,
                     const float* __restrict__ lbeta,
                     float* __restrict__ outp)
{
    const int b = blockIdx.x;
    const int tid = threadIdx.x;
    const float sens = g_gates[(size_t)b * 3 + 1];
    const float gate = g_gates[(size_t)b * 3 + 2];
    const float be = 0.5f + 2.0f * sens;

    const float* row = &g_sf[(size_t)b * 1024];

    float a[4];
    float s = 0.f, sq = 0.f;
#pragma unroll
    for (int i = 0; i < 4; ++i) {
        const int c = tid + i * 128;
        float cmb = row[c] + row[512 + c] * gate;
        float act = cmb * sigf(be * cmb);
        a[i] = act;
        s += act;
        sq = fmaf(act, act, sq);
    }

    __shared__ float sh[8];
#pragma unroll
    for (int o = 16; o > 0; o >>= 1) {
        s  += __shfl_down_sync(0xffffffffu, s,  o);
        sq += __shfl_down_sync(0xffffffffu, sq, o);
    }
    const int lane = tid & 31, warp = tid >> 5;
    if (lane == 0) { sh[warp] = s; sh[4 + warp] = sq; }
    __syncthreads();
    if (tid == 0) {
        sh[0] = sh[0] + sh[1] + sh[2] + sh[3];
        sh[4] = sh[4] + sh[5] + sh[6] + sh[7];
    }
    __syncthreads();
    const float mu  = sh[0] * (1.0f / DOUT);
    const float var = sh[4] * (1.0f / DOUT) - mu * mu;
    const float inv = rsqrtf(var + 1e-5f);
#pragma unroll
    for (int i = 0; i < 4; ++i) {
        const int c = tid + i * 128;
        outp[(size_t)b * DOUT + c] = (a[i] - mu) * inv * gamma[c] + lbeta[c];
    }
}

// ---------------- W_fast update + stats output -------------------------------
__global__ void wfast_kernel(const float* __restrict__ Wf,
                             float* __restrict__ out_wf,
                             float* __restrict__ out_st)
{
    const int o = blockIdx.x;
    const float rate = g_stats[0] * (0.1f / (float)BATCH);
    const float m2 = g_m2[o] * (1.0f / (float)BATCH);
    for (int d = threadIdx.x; d < DIN; d += blockDim.x) {
        const float wf = Wf[o * DIN + d];
        const float hebb = g_hebb[o * DIN + d] * (1.0f / (float)BATCH);
        out_wf[o * DIN + d] = wf + tanhf(hebb - m2 * wf) * rate;
    }
    if (o == 0 && threadIdx.x < 3)
        out_st[threadIdx.x] = g_stats[threadIdx.x] * (1.0f / (float)BATCH);
}

// ---------------- launch -----------------------------------------------------
extern "C" void kernel_launch(void* const* d_in, const int* in_sizes, int n_in,
                              void* d_out, int out_size)
{
    (void)in_sizes; (void)n_in; (void)out_size;

    const float* x      = (const float*)d_in[0];
    const int*   step   = (const int*)  d_in[1];
    const float* cms_w1 = (const float*)d_in[2];
    const float* cms_b1 = (const float*)d_in[3];
    const float* cms_w2 = (const float*)d_in[4];
    const float* cms_b2 = (const float*)d_in[5];
    const float* gmw    = (const float*)d_in[6];
    const float* gmb    = (const float*)d_in[7];
    const float* gsw    = (const float*)d_in[8];
    const float* gsb    = (const float*)d_in[9];
    const float* ggw    = (const float*)d_in[10];
    const float* ggb    = (const float*)d_in[11];
    const float* gow    = (const float*)d_in[12];
    const float* gob    = (const float*)d_in[13];
    const float* Wslow  = (const float*)d_in[14];
    const float* Wfast  = (const float*)d_in[15];
    const float* gamma  = (const float*)d_in[16];
    const float* lbeta  = (const float*)d_in[17];

    float* out    = (float*)d_out;
    float* out_ln = out;
    float* out_wf = out + (size_t)BATCH * DOUT;
    float* out_st = out_wf + DOUT * DIN;

    void* p;
    cudaGetSymbolAddress(&p, g_buf);   float* buf  = (float*)p;
    cudaGetSymbolAddress(&p, g_h);     float* hbuf = (float*)p;
    cudaGetSymbolAddress(&p, g_sf);    float* sf   = (float*)p;
    cudaGetSymbolAddress(&p, g_xr);    float* xr   = (float*)p;
    cudaGetSymbolAddress(&p, g_gb3);   float* gb3  = (float*)p;
    cudaGetSymbolAddress(&p, g_pre);   float* pre  = (float*)p;
    cudaGetSymbolAddress(&p, g_w1r);   float* w1r  = (float*)p;
    cudaGetSymbolAddress(&p, g_w2r);   float* w2r  = (float*)p;
    cudaGetSymbolAddress(&p, g_gsfw);  float* gsfw = (float*)p;

    static cudaStream_t s2 = nullptr;
    static cudaEvent_t  e1 = nullptr, e2 = nullptr;
    static bool attr_done = false;
    if (!attr_done) {
        cudaFuncSetAttribute(mma_gemm<EPI_RELU , true >, cudaFuncAttributeMaxDynamicSharedMemorySize, GEMM_SMEM);
        cudaFuncSetAttribute(mma_gemm<EPI_RESID, true >, cudaFuncAttributeMaxDynamicSharedMemorySize, GEMM_SMEM);
        cudaFuncSetAttribute(mma_gemm<EPI_GSF  , false>, cudaFuncAttributeMaxDynamicSharedMemorySize, GEMM_SMEM);
        cudaFuncSetAttribute(hebb_mma_kernel,            cudaFuncAttributeMaxDynamicSharedMemorySize, HEBB_SMEM);
        cudaStreamCreateWithFlags(&s2, cudaStreamNonBlocking);
        cudaEventCreateWithFlags(&e1, cudaEventDisableTiming);
        cudaEventCreateWithFlags(&e2, cudaEventDisableTiming);
        attr_done = true;
    }

    const dim3 blk(128);
    const dim3 gh(HIDN / 128, BATCH / 128);        // N=1024
    const dim3 gd(DIN  / 128, BATCH / 128);        // N=512
    const dim3 ggsf(4096 / 128, BATCH / 128);      // N=4096 merged gates+slow+fast

    prep_kernel<<<2048, 256>>>(x, cms_w1, cms_w2, gmw, gsw, ggw, Wslow, Wfast,
                               gmb, gsb, ggb);

    // CMS level 0 (freq 1)
    mma_gemm<EPI_RELU , true ><<<gh, blk, GEMM_SMEM>>>(xr,   w1r, cms_b1, nullptr, hbuf, HIDN, DIN,  step, 1, nullptr, nullptr);
    mma_gemm<EPI_RESID, true ><<<gd, blk, GEMM_SMEM>>>(hbuf, w2r, cms_b2, x,       buf,  DIN,  HIDN, step, 1, nullptr, nullptr);
    // CMS level 1 (freq 4)
    mma_gemm<EPI_RELU , true ><<<gh, blk, GEMM_SMEM>>>(buf,  w1r + NGW,     cms_b1 + HIDN,     nullptr, hbuf, HIDN, DIN,  step, 4, nullptr, nullptr);
    mma_gemm<EPI_RESID, true ><<<gd, blk, GEMM_SMEM>>>(hbuf, w2r + NGW,     cms_b2 + DIN,      buf,     buf,  DIN,  HIDN, step, 4, nullptr, nullptr);
    // CMS level 2 (freq 16)
    mma_gemm<EPI_RELU , true ><<<gh, blk, GEMM_SMEM>>>(buf,  w1r + 2 * NGW, cms_b1 + 2 * HIDN, nullptr, hbuf, HIDN, DIN,  step, 16, nullptr, nullptr);
    mma_gemm<EPI_RESID, true ><<<gd, blk, GEMM_SMEM>>>(hbuf, w2r + 2 * NGW, cms_b2 + 2 * DIN,  buf,     buf,  DIN,  HIDN, step, 16, nullptr, nullptr);

    // merged GEMM: gates (sigmoid+proj->g_pre, +m2 fold) and slow|fast -> g_sf
    mma_gemm<EPI_GSF, false><<<ggsf, blk, GEMM_SMEM>>>(buf, gsfw, gb3, nullptr, sf, 1024, DIN, step, 1, gow, pre);

    // fork: hebb on s2 runs concurrently with gate_final + finalize on main
    cudaEventRecord(e1, 0);
    cudaStreamWaitEvent(s2, e1, 0);
    hebb_mma_kernel<<<dim3(4, 4, 32), dim3(256), HEBB_SMEM, s2>>>();
    cudaEventRecord(e2, s2);

    gate_final_kernel<<<BATCH / 256, 256>>>(gob);
    finalize_kernel<<<BATCH, 128>>>(gamma, lbeta, out_ln);

    // join: wfast needs hebb + m2 + stats
    cudaStreamWaitEvent(0, e2, 0);
    wfast_kernel<<<DOUT, 256>>>(Wfast, out_wf, out_st);
}